// round 2
// baseline (speedup 1.0000x reference)
#include <cuda_runtime.h>
#include <cuda_bf16.h>
#include <math.h>

// ---------------------------------------------------------------------------
// Problem constants
// ---------------------------------------------------------------------------
#define BB      4096
#define KOBJ    5
#define EMB     128
#define HID     512
#define ADIM    4
#define FEAT    25
#define EPS_F   1e-5f

#define M_CONV  (BB * 25)          // 102400 rows (b*25 + spatial)
#define K_CONV  300                // 3*10*10
#define M_OBJ   (BB * KOBJ)        // 20480
#define M_EDGE  (BB * 20)          // 81920
#define NODE_IN (EMB + ADIM + HID) // 644

// ---------------------------------------------------------------------------
// Scratch (device globals: the sanctioned no-alloc workaround)
// ---------------------------------------------------------------------------
static __device__ float g_acol[(size_t)M_CONV * K_CONV];     // 30.72M  im2col
static __device__ float g_y[(size_t)M_CONV * HID];           // 52.43M  conv1 out
static __device__ float g_w1t[K_CONV * HID];                 // conv1_w transposed
static __device__ float g_part[400 * 1024];                  // BN partial sums (s, ss)
static __device__ float g_scale[HID];
static __device__ float g_shift[HID];
static __device__ float g_x[(size_t)BB * KOBJ * FEAT];       // 512000
static __device__ float g_state[(size_t)M_OBJ * EMB];        // 2.62M
static __device__ float g_ein[(size_t)M_EDGE * 2 * EMB];     // 20.97M
static __device__ float g_bufA[(size_t)M_EDGE * HID];        // 41.94M
static __device__ float g_bufB[(size_t)M_EDGE * HID];        // 41.94M
static __device__ float g_agg[(size_t)M_OBJ * HID];          // 10.49M
static __device__ float g_nin[(size_t)M_OBJ * NODE_IN];      // 13.19M

// ---------------------------------------------------------------------------
// im2col: stride==kernel==10 -> pure permutation of obs
// ---------------------------------------------------------------------------
__global__ void im2col_kernel(const float* __restrict__ obs) {
    size_t idx = (size_t)blockIdx.x * 256 + threadIdx.x;
    if (idx >= (size_t)M_CONV * K_CONV) return;
    int m  = (int)(idx / K_CONV);
    int kk = (int)(idx % K_CONV);
    int b = m / 25, p = m % 25;
    int py = p / 5, px = p % 5;
    int c = kk / 100, rr = kk % 100;
    int ky = rr / 10, kx = rr % 10;
    g_acol[idx] = obs[((size_t)(b * 3 + c) * 50 + py * 10 + ky) * 50 + px * 10 + kx];
}

// conv1_w (512,3,10,10) -> w1t (300, 512)
__global__ void transpose_w1_kernel(const float* __restrict__ w) {
    int idx = blockIdx.x * 256 + threadIdx.x;
    if (idx >= 512 * K_CONV) return;
    int o = idx / K_CONV, kk = idx % K_CONV;
    g_w1t[kk * 512 + o] = w[idx];
}

// ---------------------------------------------------------------------------
// Generic fused SGEMM: C[M,N] = A[M,K] @ B[K,N] + bias (+resid) (+relu)
// M % 128 == 0, N % 128 == 0 guaranteed by the problem shapes.
// 128x128 block tile, 8x8 per thread, 256 threads, BK=8.
// ---------------------------------------------------------------------------
__global__ void __launch_bounds__(256, 2)
sgemm_kernel(const float* __restrict__ A, const float* __restrict__ Bm,
             const float* __restrict__ bias, const float* __restrict__ resid,
             float* __restrict__ C, int M, int N, int K, int doRelu)
{
    __shared__ __align__(16) float As[8][128];
    __shared__ __align__(16) float Bs[8][128];

    const int tid = threadIdx.x;
    const int bm = blockIdx.y * 128;
    const int bn = blockIdx.x * 128;

    const int warp = tid >> 5, lane = tid & 31;
    const int row0 = (warp & 3) * 32 + (lane & 3) * 8;   // 0..127 (step 8)
    const int col0 = (warp >> 2) * 64 + (lane >> 2) * 8; // 0..127 (step 8)

    float acc[8][8];
#pragma unroll
    for (int i = 0; i < 8; ++i)
#pragma unroll
        for (int j = 0; j < 8; ++j) acc[i][j] = 0.f;

    const int lam = tid >> 1;          // A tile row loaded by this thread
    const int lak = (tid & 1) * 4;     // A tile k offset
    const int lbk = tid >> 5;          // B tile k row
    const int lbn = (tid & 31) * 4;    // B tile col

    const float* Aptr = A + (size_t)(bm + lam) * K;
    const bool kvec = ((K & 3) == 0);

    for (int k0 = 0; k0 < K; k0 += 8) {
        float a0 = 0.f, a1 = 0.f, a2 = 0.f, a3 = 0.f;
        int ka = k0 + lak;
        if (kvec) {
            if (ka < K) {  // K%4==0 => whole float4 is in range
                float4 v = *(const float4*)(Aptr + ka);
                a0 = v.x; a1 = v.y; a2 = v.z; a3 = v.w;
            }
        } else {
            if (ka     < K) a0 = Aptr[ka];
            if (ka + 1 < K) a1 = Aptr[ka + 1];
            if (ka + 2 < K) a2 = Aptr[ka + 2];
            if (ka + 3 < K) a3 = Aptr[ka + 3];
        }
        As[lak + 0][lam] = a0;
        As[lak + 1][lam] = a1;
        As[lak + 2][lam] = a2;
        As[lak + 3][lam] = a3;

        float4 bv = make_float4(0.f, 0.f, 0.f, 0.f);
        int kb = k0 + lbk;
        if (kb < K) bv = *(const float4*)(Bm + (size_t)kb * N + bn + lbn);
        *(float4*)&Bs[lbk][lbn] = bv;

        __syncthreads();

#pragma unroll
        for (int kk = 0; kk < 8; ++kk) {
            float4 aA = *(const float4*)&As[kk][row0];
            float4 aB = *(const float4*)&As[kk][row0 + 4];
            float4 bA = *(const float4*)&Bs[kk][col0];
            float4 bB = *(const float4*)&Bs[kk][col0 + 4];
            float af[8] = {aA.x, aA.y, aA.z, aA.w, aB.x, aB.y, aB.z, aB.w};
            float bf[8] = {bA.x, bA.y, bA.z, bA.w, bB.x, bB.y, bB.z, bB.w};
#pragma unroll
            for (int i = 0; i < 8; ++i)
#pragma unroll
                for (int j = 0; j < 8; ++j)
                    acc[i][j] = fmaf(af[i], bf[j], acc[i][j]);
        }
        __syncthreads();
    }

    float bv[8];
    const float* bp = bias + bn + col0;
#pragma unroll
    for (int j = 0; j < 8; ++j) bv[j] = bp[j];

#pragma unroll
    for (int i = 0; i < 8; ++i) {
        size_t r = (size_t)(bm + row0 + i);
        float* crow = C + r * N + bn + col0;
        float o[8];
#pragma unroll
        for (int j = 0; j < 8; ++j) {
            float v = acc[i][j] + bv[j];
            if (doRelu) v = fmaxf(v, 0.f);
            o[j] = v;
        }
        if (resid) {
            const float* rr = resid + r * N + bn + col0;
#pragma unroll
            for (int j = 0; j < 8; ++j) o[j] += rr[j];
        }
        *(float4*)(crow)     = make_float4(o[0], o[1], o[2], o[3]);
        *(float4*)(crow + 4) = make_float4(o[4], o[5], o[6], o[7]);
    }
}

// ---------------------------------------------------------------------------
// BatchNorm stats: deterministic 2-stage column reduction over g_y (102400x512)
// ---------------------------------------------------------------------------
__global__ void bn_stats1_kernel() {
    int c = threadIdx.x;                       // 512 threads = channel
    size_t r0 = (size_t)blockIdx.x * 256;      // 400 blocks
    float s = 0.f, ss = 0.f;
    for (int i = 0; i < 256; ++i) {
        float v = g_y[(r0 + i) * HID + c];
        s += v; ss += v * v;
    }
    g_part[(size_t)blockIdx.x * 1024 + c]       = s;
    g_part[(size_t)blockIdx.x * 1024 + 512 + c] = ss;
}

__global__ void bn_stats2_kernel(const float* __restrict__ gamma,
                                 const float* __restrict__ beta) {
    int c = threadIdx.x;  // 512
    float s = 0.f, ss = 0.f;
    for (int b = 0; b < 400; ++b) {
        s  += g_part[(size_t)b * 1024 + c];
        ss += g_part[(size_t)b * 1024 + 512 + c];
    }
    const float inv_n = 1.f / (float)M_CONV;
    float mu  = s * inv_n;
    float var = ss * inv_n - mu * mu;
    float sc = gamma[c] * rsqrtf(var + EPS_F);
    g_scale[c] = sc;
    g_shift[c] = beta[c] - mu * sc;
}

// ---------------------------------------------------------------------------
// conv2 (1x1, 512 -> 5) + sigmoid, fused with BN-normalize + relu on the fly
// One warp per (b, spatial) row.
// ---------------------------------------------------------------------------
__global__ void conv2_sigmoid_kernel(const float* __restrict__ w2,
                                     const float* __restrict__ b2) {
    __shared__ float ws[5 * HID];
    __shared__ float bs[5];
    int tid = threadIdx.x;
    for (int i = tid; i < 5 * HID; i += 256) ws[i] = w2[i];
    if (tid < 5) bs[tid] = b2[tid];
    __syncthreads();

    int warp = tid >> 5, lane = tid & 31;
    size_t m = (size_t)blockIdx.x * 8 + warp;       // < 102400
    const float* y = g_y + m * HID;
    float a0 = 0.f, a1 = 0.f, a2 = 0.f, a3 = 0.f, a4 = 0.f;
#pragma unroll
    for (int i = 0; i < 16; ++i) {
        int c = lane + 32 * i;
        float h = fmaxf(fmaf(y[c], g_scale[c], g_shift[c]), 0.f);
        a0 = fmaf(h, ws[c],            a0);
        a1 = fmaf(h, ws[HID + c],      a1);
        a2 = fmaf(h, ws[2 * HID + c],  a2);
        a3 = fmaf(h, ws[3 * HID + c],  a3);
        a4 = fmaf(h, ws[4 * HID + c],  a4);
    }
#pragma unroll
    for (int o = 16; o > 0; o >>= 1) {
        a0 += __shfl_down_sync(0xffffffffu, a0, o);
        a1 += __shfl_down_sync(0xffffffffu, a1, o);
        a2 += __shfl_down_sync(0xffffffffu, a2, o);
        a3 += __shfl_down_sync(0xffffffffu, a3, o);
        a4 += __shfl_down_sync(0xffffffffu, a4, o);
    }
    if (lane == 0) {
        int b = (int)(m / 25), f = (int)(m % 25);
        float* xb = g_x + (size_t)b * (KOBJ * FEAT) + f;
        xb[0 * FEAT] = 1.f / (1.f + expf(-(a0 + bs[0])));
        xb[1 * FEAT] = 1.f / (1.f + expf(-(a1 + bs[1])));
        xb[2 * FEAT] = 1.f / (1.f + expf(-(a2 + bs[2])));
        xb[3 * FEAT] = 1.f / (1.f + expf(-(a3 + bs[3])));
        xb[4 * FEAT] = 1.f / (1.f + expf(-(a4 + bs[4])));
    }
}

// ---------------------------------------------------------------------------
// LayerNorm (width 512) + ReLU, in place. One block of 256 threads per row.
// ---------------------------------------------------------------------------
__global__ void ln_relu_kernel(float* __restrict__ H,
                               const float* __restrict__ g,
                               const float* __restrict__ b) {
    __shared__ float sh[8];
    float* h = H + (size_t)blockIdx.x * HID;
    int tid = threadIdx.x, lane = tid & 31, w = tid >> 5;

    float x0 = h[tid], x1 = h[tid + 256];
    float s = x0 + x1;
#pragma unroll
    for (int o = 16; o > 0; o >>= 1) s += __shfl_down_sync(0xffffffffu, s, o);
    if (lane == 0) sh[w] = s;
    __syncthreads();
    if (tid == 0) {
        float t = 0.f;
#pragma unroll
        for (int i = 0; i < 8; ++i) t += sh[i];
        sh[0] = t;
    }
    __syncthreads();
    float mean = sh[0] * (1.f / (float)HID);
    __syncthreads();

    float d0 = x0 - mean, d1 = x1 - mean;
    float ss = d0 * d0 + d1 * d1;
#pragma unroll
    for (int o = 16; o > 0; o >>= 1) ss += __shfl_down_sync(0xffffffffu, ss, o);
    if (lane == 0) sh[w] = ss;
    __syncthreads();
    if (tid == 0) {
        float t = 0.f;
#pragma unroll
        for (int i = 0; i < 8; ++i) t += sh[i];
        sh[0] = t;
    }
    __syncthreads();
    float inv = rsqrtf(sh[0] * (1.f / (float)HID) + EPS_F);

    h[tid]       = fmaxf(fmaf(d0 * inv, g[tid],       b[tid]),       0.f);
    h[tid + 256] = fmaxf(fmaf(d1 * inv, g[tid + 256], b[tid + 256]), 0.f);
}

// ---------------------------------------------------------------------------
// Edge-input gather: e_in[b, p, :] = concat(state[b, row[p]], state[b, col[p]])
// row[p] = p/4 ; col[p] = t + (t >= p/4) with t = p%4
// ---------------------------------------------------------------------------
__global__ void gather_ein_kernel() {
    size_t idx = (size_t)blockIdx.x * 256 + threadIdx.x;
    if (idx >= (size_t)M_EDGE * 256) return;
    int r = (int)(idx >> 8);
    int j = (int)(idx & 255);
    int b = r / 20, p = r % 20;
    int i = p >> 2, t = p & 3;
    int tgt = t + (t >= i ? 1 : 0);
    int obj = (j < 128) ? i : tgt;
    g_ein[idx] = g_state[((size_t)b * KOBJ + obj) * EMB + (j & 127)];
}

// agg[b,k] = sum over 4 consecutive edge rows (row[p]==k for p in [4k,4k+4))
__global__ void agg_kernel() {
    size_t idx = (size_t)blockIdx.x * 256 + threadIdx.x;
    if (idx >= (size_t)M_OBJ * HID) return;
    int r = (int)(idx >> 9);     // b*5 + k
    int j = (int)(idx & 511);
    int b = r / KOBJ, k = r % KOBJ;
    size_t base = ((size_t)b * 20 + k * 4) * HID + j;
    g_agg[idx] = g_bufA[base] + g_bufA[base + HID] +
                 g_bufA[base + 2 * HID] + g_bufA[base + 3 * HID];
}

// node_in = concat(state[128], one_hot(action)[4], agg[512])  (644 cols)
__global__ void node_in_kernel(const int* __restrict__ action) {
    size_t idx = (size_t)blockIdx.x * 256 + threadIdx.x;
    if (idx >= (size_t)M_OBJ * NODE_IN) return;
    int r = (int)(idx / NODE_IN);
    int j = (int)(idx % NODE_IN);
    int b = r / KOBJ, k = r % KOBJ;
    float v;
    if (j < EMB) {
        v = g_state[(size_t)r * EMB + j];
    } else if (j < EMB + ADIM) {
        v = (action[b] == k * ADIM + (j - EMB)) ? 1.f : 0.f;
    } else {
        v = g_agg[(size_t)r * HID + (j - EMB - ADIM)];
    }
    g_nin[idx] = v;
}

// ---------------------------------------------------------------------------
// Launch
// ---------------------------------------------------------------------------
extern "C" void kernel_launch(void* const* d_in, const int* in_sizes, int n_in,
                              void* d_out, int out_size) {
    const float* obs     = (const float*)d_in[0];
    const int*   action  = (const int*)d_in[1];
    const float* conv1_w = (const float*)d_in[2];
    const float* conv1_b = (const float*)d_in[3];
    const float* bn1_g   = (const float*)d_in[4];
    const float* bn1_b   = (const float*)d_in[5];
    const float* conv2_w = (const float*)d_in[6];
    const float* conv2_b = (const float*)d_in[7];
    const float* enc_w1  = (const float*)d_in[8];
    const float* enc_b1  = (const float*)d_in[9];
    const float* enc_w2  = (const float*)d_in[10];
    const float* enc_b2  = (const float*)d_in[11];
    const float* enc_lng = (const float*)d_in[12];
    const float* enc_lnb = (const float*)d_in[13];
    const float* enc_w3  = (const float*)d_in[14];
    const float* enc_b3  = (const float*)d_in[15];
    const float* edge_w1 = (const float*)d_in[16];
    const float* edge_b1 = (const float*)d_in[17];
    const float* edge_w2 = (const float*)d_in[18];
    const float* edge_b2 = (const float*)d_in[19];
    const float* edge_lng= (const float*)d_in[20];
    const float* edge_lnb= (const float*)d_in[21];
    const float* edge_w3 = (const float*)d_in[22];
    const float* edge_b3 = (const float*)d_in[23];
    const float* node_w1 = (const float*)d_in[24];
    const float* node_b1 = (const float*)d_in[25];
    const float* node_w2 = (const float*)d_in[26];
    const float* node_b2 = (const float*)d_in[27];
    const float* node_lng= (const float*)d_in[28];
    const float* node_lnb= (const float*)d_in[29];
    const float* node_w3 = (const float*)d_in[30];
    const float* node_b3 = (const float*)d_in[31];
    float* out = (float*)d_out;

    // Resolve device-global addresses for passing as kernel args
    float *p_acol, *p_y, *p_w1t, *p_x, *p_state, *p_ein, *p_bufA, *p_bufB, *p_agg, *p_nin;
    cudaGetSymbolAddress((void**)&p_acol,  g_acol);
    cudaGetSymbolAddress((void**)&p_y,     g_y);
    cudaGetSymbolAddress((void**)&p_w1t,   g_w1t);
    cudaGetSymbolAddress((void**)&p_x,     g_x);
    cudaGetSymbolAddress((void**)&p_state, g_state);
    cudaGetSymbolAddress((void**)&p_ein,   g_ein);
    cudaGetSymbolAddress((void**)&p_bufA,  g_bufA);
    cudaGetSymbolAddress((void**)&p_bufB,  g_bufB);
    cudaGetSymbolAddress((void**)&p_agg,   g_agg);
    cudaGetSymbolAddress((void**)&p_nin,   g_nin);

    // --- conv1 as GEMM ---
    im2col_kernel<<<(unsigned)(((size_t)M_CONV * K_CONV + 255) / 256), 256>>>(obs);
    transpose_w1_kernel<<<(512 * K_CONV + 255) / 256, 256>>>(conv1_w);
    sgemm_kernel<<<dim3(HID / 128, M_CONV / 128), 256>>>(
        p_acol, p_w1t, conv1_b, nullptr, p_y, M_CONV, HID, K_CONV, 0);

    // --- batch norm (deterministic 2-stage) + conv2 + sigmoid ---
    bn_stats1_kernel<<<400, 512>>>();
    bn_stats2_kernel<<<1, 512>>>(bn1_g, bn1_b);
    conv2_sigmoid_kernel<<<M_CONV / 8, 256>>>(conv2_w, conv2_b);

    // --- encoder MLP: 25 -> 512 -> 512(LN) -> 128 ---
    sgemm_kernel<<<dim3(HID / 128, M_OBJ / 128), 256>>>(
        p_x, enc_w1, enc_b1, nullptr, p_bufA, M_OBJ, HID, FEAT, 1);
    sgemm_kernel<<<dim3(HID / 128, M_OBJ / 128), 256>>>(
        p_bufA, enc_w2, enc_b2, nullptr, p_bufB, M_OBJ, HID, HID, 0);
    ln_relu_kernel<<<M_OBJ, 256>>>(p_bufB, enc_lng, enc_lnb);
    sgemm_kernel<<<dim3(EMB / 128, M_OBJ / 128), 256>>>(
        p_bufB, enc_w3, enc_b3, nullptr, p_state, M_OBJ, EMB, HID, 0);

    // --- edge MLP: gather -> 256 -> 512 -> 512(LN) -> 512 ---
    gather_ein_kernel<<<(unsigned)(((size_t)M_EDGE * 256 + 255) / 256), 256>>>();
    sgemm_kernel<<<dim3(HID / 128, M_EDGE / 128), 256>>>(
        p_ein, edge_w1, edge_b1, nullptr, p_bufA, M_EDGE, HID, 2 * EMB, 1);
    sgemm_kernel<<<dim3(HID / 128, M_EDGE / 128), 256>>>(
        p_bufA, edge_w2, edge_b2, nullptr, p_bufB, M_EDGE, HID, HID, 0);
    ln_relu_kernel<<<M_EDGE, 256>>>(p_bufB, edge_lng, edge_lnb);
    sgemm_kernel<<<dim3(HID / 128, M_EDGE / 128), 256>>>(
        p_bufB, edge_w3, edge_b3, nullptr, p_bufA, M_EDGE, HID, HID, 0);

    // --- aggregate + node input assembly ---
    agg_kernel<<<(unsigned)(((size_t)M_OBJ * HID + 255) / 256), 256>>>();
    node_in_kernel<<<(unsigned)(((size_t)M_OBJ * NODE_IN + 255) / 256), 256>>>(action);

    // --- node MLP: 644 -> 512 -> 512(LN) -> 128, residual add state ---
    sgemm_kernel<<<dim3(HID / 128, M_OBJ / 128), 256>>>(
        p_nin, node_w1, node_b1, nullptr, p_bufB, M_OBJ, HID, NODE_IN, 1);
    sgemm_kernel<<<dim3(HID / 128, M_OBJ / 128), 256>>>(
        p_bufB, node_w2, node_b2, nullptr, p_bufA, M_OBJ, HID, HID, 0);
    ln_relu_kernel<<<M_OBJ, 256>>>(p_bufA, node_lng, node_lnb);
    sgemm_kernel<<<dim3(EMB / 128, M_OBJ / 128), 256>>>(
        p_bufA, node_w3, node_b3, p_state, out, M_OBJ, EMB, HID, 0);
}

// round 8
// speedup vs baseline: 2.5527x; 2.5527x over previous
#include <cuda_runtime.h>
#include <cuda_bf16.h>
#include <stdint.h>
#include <math.h>

// ---------------------------------------------------------------------------
// Problem constants
// ---------------------------------------------------------------------------
#define BB      4096
#define KOBJ    5
#define EMB     128
#define HID     512
#define ADIM    4
#define FEAT    25
#define EPS_F   1e-5f

#define M_CONV  (BB * 25)          // 102400
#define K_CONV  300
#define K_CONVP 320                // padded to %32
#define M_OBJ   (BB * KOBJ)        // 20480
#define M_EDGE  (BB * 20)          // 81920
#define NODE_IN 644
#define NODE_INP 672               // padded
#define FEATP   32                 // padded

// ---------------------------------------------------------------------------
// Scratch (device globals)
// ---------------------------------------------------------------------------
static __device__ float g_acol[(size_t)M_CONV * K_CONVP];
static __device__ float g_y[(size_t)M_CONV * HID];
static __device__ float g_part[400 * 1024];
static __device__ float g_scale[HID];
static __device__ float g_shift[HID];
static __device__ float g_x[(size_t)M_OBJ * FEATP];
static __device__ float g_state[(size_t)M_OBJ * EMB];
static __device__ float g_ein[(size_t)M_EDGE * 2 * EMB];
static __device__ float g_bufA[(size_t)M_EDGE * HID];
static __device__ float g_bufB[(size_t)M_EDGE * HID];
static __device__ float g_agg[(size_t)M_OBJ * HID];
static __device__ float g_nin[(size_t)M_OBJ * NODE_INP];
static __device__ float g_wts[1835008];   // transposed+padded weights

#define OFF_C1 0         // 512x320
#define OFF_E1 163840    // 512x32
#define OFF_E2 180224    // 512x512
#define OFF_E3 442368    // 128x512
#define OFF_G1 507904    // 512x256
#define OFF_G2 638976    // 512x512
#define OFF_G3 901120    // 512x512
#define OFF_N1 1163264   // 512x672
#define OFF_N2 1507328   // 512x512
#define OFF_N3 1769472   // 128x512

// ---------------------------------------------------------------------------
// Helpers
// ---------------------------------------------------------------------------
__device__ __forceinline__ float rna_tf32(float x) {
    uint32_t u;
    asm("cvt.rna.tf32.f32 %0, %1;" : "=r"(u) : "f"(x));
    return __uint_as_float(u);
}

#define CP_ASYNC16(dst, src) \
    asm volatile("cp.async.cg.shared.global [%0], [%1], 16;" :: "r"(dst), "l"(src))
#define CP_COMMIT() asm volatile("cp.async.commit_group;" ::: "memory")
#define CP_WAIT0()  asm volatile("cp.async.wait_group 0;" ::: "memory")

// ---------------------------------------------------------------------------
// tf32 mma.sync GEMM: C[M,N] = A[M,Kp] @ Bt[N,Kp]^T + bias (+relu)(+resid)
// BM=128, BN in {256,128}, BK=32. Warp tile 64x64 (m16n8k8, mt=4, nt=8).
// M%128==0, N%BN==0, K%32==0 guaranteed by the padded shapes.
// ---------------------------------------------------------------------------
template<int BN>
__global__ void __launch_bounds__(BN == 256 ? 256 : 128, 1)
mma_gemm(const float* __restrict__ A, int lda,
         const float* __restrict__ Bt,
         const float* __restrict__ bias, const float* __restrict__ resid,
         float* __restrict__ C, int N, int K, int doRelu)
{
    constexpr int T    = (BN == 256) ? 256 : 128;   // threads
    constexpr int AELE = 128 * 36;                  // floats per A buffer
    constexpr int BELE = BN * 36;                   // floats per B buffer
    extern __shared__ float sm[];
    float* AsBuf = sm;                 // [2][AELE]
    float* BsBuf = sm + 2 * AELE;      // [2][BELE]

    const int tid  = threadIdx.x;
    const int warp = tid >> 5, lane = tid & 31;
    const int bm = blockIdx.y * 128;
    const int bn = blockIdx.x * BN;
    const int warpM = warp & 1;        // 2 M bands of 64
    const int warpN = warp >> 1;       // BN/64 N bands of 64
    const int grp = lane >> 2;         // 0..7
    const int ctg = lane & 3;          // 0..3

    uint32_t sbase;
    asm("{ .reg .u64 t; cvta.to.shared.u64 t, %1; cvt.u32.u64 %0, t; }"
        : "=r"(sbase) : "l"(sm));

    const float* Abase = A + (size_t)bm * lda;
    const float* Bbase = Bt + (size_t)bn * K;
    const int KT = K / 32;

    float acc[4][8][4];
#pragma unroll
    for (int mi = 0; mi < 4; ++mi)
#pragma unroll
        for (int nj = 0; nj < 8; ++nj)
#pragma unroll
            for (int q = 0; q < 4; ++q) acc[mi][nj][q] = 0.f;

    // ---- async tile loader: A 128x32, B BNx32, pad-36 layout ----
    auto load_tile = [&](int kt) {
        const int buf = kt & 1;
        const int k0 = kt * 32;
        uint32_t sa = sbase + (uint32_t)(buf * AELE) * 4u;
#pragma unroll
        for (int i = 0; i < 1024 / T; ++i) {
            int id = tid + T * i;
            int r = id >> 3, c = id & 7;
            CP_ASYNC16(sa + (uint32_t)(r * 36 + c * 4) * 4u,
                       Abase + (size_t)r * lda + k0 + c * 4);
        }
        uint32_t sb = sbase + (uint32_t)((2 * AELE) + buf * BELE) * 4u;
#pragma unroll
        for (int i = 0; i < (BN * 8) / T; ++i) {
            int id = tid + T * i;
            int r = id >> 3, c = id & 7;
            CP_ASYNC16(sb + (uint32_t)(r * 36 + c * 4) * 4u,
                       Bbase + (size_t)r * K + k0 + c * 4);
        }
        CP_COMMIT();
    };

    load_tile(0);

    for (int kt = 0; kt < KT; ++kt) {
        CP_WAIT0();
        __syncthreads();
        if (kt + 1 < KT) load_tile(kt + 1);

        const float* As = AsBuf + (kt & 1) * AELE;
        const float* Bs = BsBuf + (kt & 1) * BELE;

#pragma unroll
        for (int ks = 0; ks < 4; ++ks) {
            const int kc = ks * 8 + ctg;
            uint32_t a[4][4], b[8][2];
#pragma unroll
            for (int mi = 0; mi < 4; ++mi) {
                const float* p = As + (warpM * 64 + mi * 16 + grp) * 36 + kc;
                a[mi][0] = __float_as_uint(p[0]);
                a[mi][1] = __float_as_uint(p[8 * 36]);
                a[mi][2] = __float_as_uint(p[4]);
                a[mi][3] = __float_as_uint(p[8 * 36 + 4]);
            }
#pragma unroll
            for (int nj = 0; nj < 8; ++nj) {
                const float* p = Bs + (warpN * 64 + nj * 8 + grp) * 36 + kc;
                b[nj][0] = __float_as_uint(p[0]);
                b[nj][1] = __float_as_uint(p[4]);
            }
#pragma unroll
            for (int mi = 0; mi < 4; ++mi)
#pragma unroll
                for (int nj = 0; nj < 8; ++nj)
                    asm volatile(
                        "mma.sync.aligned.m16n8k8.row.col.f32.tf32.tf32.f32 "
                        "{%0,%1,%2,%3}, {%4,%5,%6,%7}, {%8,%9}, {%0,%1,%2,%3};"
                        : "+f"(acc[mi][nj][0]), "+f"(acc[mi][nj][1]),
                          "+f"(acc[mi][nj][2]), "+f"(acc[mi][nj][3])
                        : "r"(a[mi][0]), "r"(a[mi][1]), "r"(a[mi][2]), "r"(a[mi][3]),
                          "r"(b[nj][0]), "r"(b[nj][1]));
        }
    }

    // ---- epilogue ----
#pragma unroll
    for (int mi = 0; mi < 4; ++mi) {
        const int r0 = bm + warpM * 64 + mi * 16 + grp;
#pragma unroll
        for (int nj = 0; nj < 8; ++nj) {
            const int col = bn + warpN * 64 + nj * 8 + ctg * 2;
            const float bz0 = bias[col], bz1 = bias[col + 1];
            float v00 = acc[mi][nj][0] + bz0, v01 = acc[mi][nj][1] + bz1;
            float v10 = acc[mi][nj][2] + bz0, v11 = acc[mi][nj][3] + bz1;
            if (doRelu) {
                v00 = rna_tf32(fmaxf(v00, 0.f));
                v01 = rna_tf32(fmaxf(v01, 0.f));
                v10 = rna_tf32(fmaxf(v10, 0.f));
                v11 = rna_tf32(fmaxf(v11, 0.f));
            }
            if (resid) {
                const float* rp0 = resid + (size_t)r0 * N + col;
                const float* rp1 = resid + (size_t)(r0 + 8) * N + col;
                v00 += rp0[0]; v01 += rp0[1];
                v10 += rp1[0]; v11 += rp1[1];
            }
            *(float2*)(C + (size_t)r0 * N + col)       = make_float2(v00, v01);
            *(float2*)(C + (size_t)(r0 + 8) * N + col) = make_float2(v10, v11);
        }
    }
}

// ---------------------------------------------------------------------------
// im2col (stride==kernel==10) with K padded 300 -> 320 (zeros), tf32-rounded
// ---------------------------------------------------------------------------
__global__ void im2col_kernel(const float* __restrict__ obs) {
    size_t idx = (size_t)blockIdx.x * 256 + threadIdx.x;
    if (idx >= (size_t)M_CONV * K_CONVP) return;
    int m  = (int)(idx / K_CONVP);
    int kk = (int)(idx % K_CONVP);
    float v = 0.f;
    if (kk < K_CONV) {
        int b = m / 25, p = m % 25;
        int py = p / 5, px = p % 5;
        int c = kk / 100, rr = kk % 100;
        int ky = rr / 10, kx = rr % 10;
        v = rna_tf32(obs[((size_t)(b * 3 + c) * 50 + py * 10 + ky) * 50 + px * 10 + kx]);
    }
    g_acol[idx] = v;
}

// conv1_w [512][300] -> [512][320] padded, rounded
__global__ void padcopy_kernel(const float* __restrict__ w, float* __restrict__ dst,
                               int N, int K, int Kp) {
    int idx = blockIdx.x * 256 + threadIdx.x;
    if (idx >= N * Kp) return;
    int n = idx / Kp, k = idx % Kp;
    dst[idx] = (k < K) ? rna_tf32(w[n * K + k]) : 0.f;
}

// dense weights [K][N] -> dst[n][k] transposed, K padded, rounded
__global__ void transpose_pad_kernel(const float* __restrict__ w, float* __restrict__ dst,
                                     int N, int K, int Kp) {
    int idx = blockIdx.x * 256 + threadIdx.x;
    if (idx >= N * Kp) return;
    int n = idx / Kp, k = idx % Kp;
    dst[idx] = (k < K) ? rna_tf32(w[k * N + n]) : 0.f;
}

// ---------------------------------------------------------------------------
// BatchNorm stats (deterministic 2-stage)
// ---------------------------------------------------------------------------
__global__ void bn_stats1_kernel() {
    int c = threadIdx.x;
    size_t r0 = (size_t)blockIdx.x * 256;
    float s = 0.f, ss = 0.f;
    for (int i = 0; i < 256; ++i) {
        float v = g_y[(r0 + i) * HID + c];
        s += v; ss += v * v;
    }
    g_part[(size_t)blockIdx.x * 1024 + c]       = s;
    g_part[(size_t)blockIdx.x * 1024 + 512 + c] = ss;
}

__global__ void bn_stats2_kernel(const float* __restrict__ gamma,
                                 const float* __restrict__ beta) {
    int c = threadIdx.x;
    float s = 0.f, ss = 0.f;
    for (int b = 0; b < 400; ++b) {
        s  += g_part[(size_t)b * 1024 + c];
        ss += g_part[(size_t)b * 1024 + 512 + c];
    }
    const float inv_n = 1.f / (float)M_CONV;
    float mu  = s * inv_n;
    float var = ss * inv_n - mu * mu;
    float sc = gamma[c] * rsqrtf(var + EPS_F);
    g_scale[c] = sc;
    g_shift[c] = beta[c] - mu * sc;
}

// ---------------------------------------------------------------------------
// BN normalize + relu + conv2(1x1) + sigmoid -> g_x (stride FEATP), rounded
// ---------------------------------------------------------------------------
__global__ void conv2_sigmoid_kernel(const float* __restrict__ w2,
                                     const float* __restrict__ b2) {
    __shared__ float ws[5 * HID];
    __shared__ float bs[5];
    int tid = threadIdx.x;
    for (int i = tid; i < 5 * HID; i += 256) ws[i] = w2[i];
    if (tid < 5) bs[tid] = b2[tid];
    __syncthreads();

    int warp = tid >> 5, lane = tid & 31;
    size_t m = (size_t)blockIdx.x * 8 + warp;
    const float* y = g_y + m * HID;
    float a0 = 0.f, a1 = 0.f, a2 = 0.f, a3 = 0.f, a4 = 0.f;
#pragma unroll
    for (int i = 0; i < 16; ++i) {
        int c = lane + 32 * i;
        float h = fmaxf(fmaf(y[c], g_scale[c], g_shift[c]), 0.f);
        a0 = fmaf(h, ws[c],           a0);
        a1 = fmaf(h, ws[HID + c],     a1);
        a2 = fmaf(h, ws[2 * HID + c], a2);
        a3 = fmaf(h, ws[3 * HID + c], a3);
        a4 = fmaf(h, ws[4 * HID + c], a4);
    }
#pragma unroll
    for (int o = 16; o > 0; o >>= 1) {
        a0 += __shfl_down_sync(0xffffffffu, a0, o);
        a1 += __shfl_down_sync(0xffffffffu, a1, o);
        a2 += __shfl_down_sync(0xffffffffu, a2, o);
        a3 += __shfl_down_sync(0xffffffffu, a3, o);
        a4 += __shfl_down_sync(0xffffffffu, a4, o);
    }
    if (lane == 0) {
        int b = (int)(m / 25), f = (int)(m % 25);
        float* xb = g_x + (size_t)b * 5 * FEATP + f;
        xb[0 * FEATP] = rna_tf32(1.f / (1.f + expf(-(a0 + bs[0]))));
        xb[1 * FEATP] = rna_tf32(1.f / (1.f + expf(-(a1 + bs[1]))));
        xb[2 * FEATP] = rna_tf32(1.f / (1.f + expf(-(a2 + bs[2]))));
        xb[3 * FEATP] = rna_tf32(1.f / (1.f + expf(-(a3 + bs[3]))));
        xb[4 * FEATP] = rna_tf32(1.f / (1.f + expf(-(a4 + bs[4]))));
    }
}

// zero the pad columns of g_x (cols 25..31)
__global__ void pad_x_kernel() {
    int idx = blockIdx.x * 256 + threadIdx.x;
    if (idx >= M_OBJ * (FEATP - FEAT)) return;
    int row = idx / (FEATP - FEAT), j = FEAT + idx % (FEATP - FEAT);
    g_x[(size_t)row * FEATP + j] = 0.f;
}

// ---------------------------------------------------------------------------
// LayerNorm(512) + ReLU in place, outputs tf32-rounded (they feed GEMM A)
// ---------------------------------------------------------------------------
__global__ void ln_relu_kernel(float* __restrict__ H,
                               const float* __restrict__ g,
                               const float* __restrict__ b) {
    __shared__ float sh[8];
    float* h = H + (size_t)blockIdx.x * HID;
    int tid = threadIdx.x, lane = tid & 31, w = tid >> 5;

    float x0 = h[tid], x1 = h[tid + 256];
    float s = x0 + x1;
#pragma unroll
    for (int o = 16; o > 0; o >>= 1) s += __shfl_down_sync(0xffffffffu, s, o);
    if (lane == 0) sh[w] = s;
    __syncthreads();
    if (tid == 0) {
        float t = 0.f;
#pragma unroll
        for (int i = 0; i < 8; ++i) t += sh[i];
        sh[0] = t;
    }
    __syncthreads();
    float mean = sh[0] * (1.f / (float)HID);
    __syncthreads();

    float d0 = x0 - mean, d1 = x1 - mean;
    float ss = d0 * d0 + d1 * d1;
#pragma unroll
    for (int o = 16; o > 0; o >>= 1) ss += __shfl_down_sync(0xffffffffu, ss, o);
    if (lane == 0) sh[w] = ss;
    __syncthreads();
    if (tid == 0) {
        float t = 0.f;
#pragma unroll
        for (int i = 0; i < 8; ++i) t += sh[i];
        sh[0] = t;
    }
    __syncthreads();
    float inv = rsqrtf(sh[0] * (1.f / (float)HID) + EPS_F);

    h[tid]       = rna_tf32(fmaxf(fmaf(d0 * inv, g[tid],       b[tid]),       0.f));
    h[tid + 256] = rna_tf32(fmaxf(fmaf(d1 * inv, g[tid + 256], b[tid + 256]), 0.f));
}

// ---------------------------------------------------------------------------
// Edge gather / aggregate / node-input assembly
// ---------------------------------------------------------------------------
__global__ void gather_ein_kernel() {
    size_t idx = (size_t)blockIdx.x * 256 + threadIdx.x;
    if (idx >= (size_t)M_EDGE * 256) return;
    int r = (int)(idx >> 8);
    int j = (int)(idx & 255);
    int b = r / 20, p = r % 20;
    int i = p >> 2, t = p & 3;
    int tgt = t + (t >= i ? 1 : 0);
    int obj = (j < 128) ? i : tgt;
    g_ein[idx] = rna_tf32(g_state[((size_t)b * KOBJ + obj) * EMB + (j & 127)]);
}

__global__ void agg_kernel() {
    size_t idx = (size_t)blockIdx.x * 256 + threadIdx.x;
    if (idx >= (size_t)M_OBJ * HID) return;
    int r = (int)(idx >> 9);
    int j = (int)(idx & 511);
    int b = r / KOBJ, k = r % KOBJ;
    size_t base = ((size_t)b * 20 + k * 4) * HID + j;
    g_agg[idx] = g_bufA[base] + g_bufA[base + HID] +
                 g_bufA[base + 2 * HID] + g_bufA[base + 3 * HID];
}

__global__ void node_in_kernel(const int* __restrict__ action) {
    size_t idx = (size_t)blockIdx.x * 256 + threadIdx.x;
    if (idx >= (size_t)M_OBJ * NODE_INP) return;
    int r = (int)(idx / NODE_INP);
    int j = (int)(idx % NODE_INP);
    int b = r / KOBJ, k = r % KOBJ;
    float v;
    if (j < EMB) {
        v = rna_tf32(g_state[(size_t)r * EMB + j]);
    } else if (j < EMB + ADIM) {
        v = (action[b] == k * ADIM + (j - EMB)) ? 1.f : 0.f;
    } else if (j < NODE_IN) {
        v = rna_tf32(g_agg[(size_t)r * HID + (j - EMB - ADIM)]);
    } else {
        v = 0.f;
    }
    g_nin[idx] = v;
}

// ---------------------------------------------------------------------------
// Launch
// ---------------------------------------------------------------------------
extern "C" void kernel_launch(void* const* d_in, const int* in_sizes, int n_in,
                              void* d_out, int out_size) {
    const float* obs     = (const float*)d_in[0];
    const int*   action  = (const int*)d_in[1];
    const float* conv1_w = (const float*)d_in[2];
    const float* conv1_b = (const float*)d_in[3];
    const float* bn1_g   = (const float*)d_in[4];
    const float* bn1_b   = (const float*)d_in[5];
    const float* conv2_w = (const float*)d_in[6];
    const float* conv2_b = (const float*)d_in[7];
    const float* enc_w1  = (const float*)d_in[8];
    const float* enc_b1  = (const float*)d_in[9];
    const float* enc_w2  = (const float*)d_in[10];
    const float* enc_b2  = (const float*)d_in[11];
    const float* enc_lng = (const float*)d_in[12];
    const float* enc_lnb = (const float*)d_in[13];
    const float* enc_w3  = (const float*)d_in[14];
    const float* enc_b3  = (const float*)d_in[15];
    const float* edge_w1 = (const float*)d_in[16];
    const float* edge_b1 = (const float*)d_in[17];
    const float* edge_w2 = (const float*)d_in[18];
    const float* edge_b2 = (const float*)d_in[19];
    const float* edge_lng= (const float*)d_in[20];
    const float* edge_lnb= (const float*)d_in[21];
    const float* edge_w3 = (const float*)d_in[22];
    const float* edge_b3 = (const float*)d_in[23];
    const float* node_w1 = (const float*)d_in[24];
    const float* node_b1 = (const float*)d_in[25];
    const float* node_w2 = (const float*)d_in[26];
    const float* node_b2 = (const float*)d_in[27];
    const float* node_lng= (const float*)d_in[28];
    const float* node_lnb= (const float*)d_in[29];
    const float* node_w3 = (const float*)d_in[30];
    const float* node_b3 = (const float*)d_in[31];
    float* out = (float*)d_out;

    float *p_acol, *p_y, *p_x, *p_state, *p_ein, *p_bufA, *p_bufB, *p_nin, *p_wts;
    cudaGetSymbolAddress((void**)&p_acol,  g_acol);
    cudaGetSymbolAddress((void**)&p_y,     g_y);
    cudaGetSymbolAddress((void**)&p_x,     g_x);
    cudaGetSymbolAddress((void**)&p_state, g_state);
    cudaGetSymbolAddress((void**)&p_ein,   g_ein);
    cudaGetSymbolAddress((void**)&p_bufA,  g_bufA);
    cudaGetSymbolAddress((void**)&p_bufB,  g_bufB);
    cudaGetSymbolAddress((void**)&p_nin,   g_nin);
    cudaGetSymbolAddress((void**)&p_wts,   g_wts);

    const int SMEM256 = (2 * 128 * 36 + 2 * 256 * 36) * 4;   // 110592
    const int SMEM128 = (2 * 128 * 36 + 2 * 128 * 36) * 4;   // 73728
    cudaFuncSetAttribute(mma_gemm<256>, cudaFuncAttributeMaxDynamicSharedMemorySize, SMEM256);
    cudaFuncSetAttribute(mma_gemm<128>, cudaFuncAttributeMaxDynamicSharedMemorySize, SMEM128);

    // --- weight prep (transpose + K-pad + tf32 round) ---
    padcopy_kernel<<<(512 * K_CONVP + 255) / 256, 256>>>(conv1_w, p_wts + OFF_C1, 512, K_CONV, K_CONVP);
    transpose_pad_kernel<<<(512 * 32 + 255) / 256, 256>>>(enc_w1, p_wts + OFF_E1, 512, FEAT, FEATP);
    transpose_pad_kernel<<<(512 * 512 + 255) / 256, 256>>>(enc_w2, p_wts + OFF_E2, 512, 512, 512);
    transpose_pad_kernel<<<(128 * 512 + 255) / 256, 256>>>(enc_w3, p_wts + OFF_E3, 128, 512, 512);
    transpose_pad_kernel<<<(512 * 256 + 255) / 256, 256>>>(edge_w1, p_wts + OFF_G1, 512, 256, 256);
    transpose_pad_kernel<<<(512 * 512 + 255) / 256, 256>>>(edge_w2, p_wts + OFF_G2, 512, 512, 512);
    transpose_pad_kernel<<<(512 * 512 + 255) / 256, 256>>>(edge_w3, p_wts + OFF_G3, 512, 512, 512);
    transpose_pad_kernel<<<(512 * NODE_INP + 255) / 256, 256>>>(node_w1, p_wts + OFF_N1, 512, NODE_IN, NODE_INP);
    transpose_pad_kernel<<<(512 * 512 + 255) / 256, 256>>>(node_w2, p_wts + OFF_N2, 512, 512, 512);
    transpose_pad_kernel<<<(128 * 512 + 255) / 256, 256>>>(node_w3, p_wts + OFF_N3, 128, 512, 512);

    // --- conv1 as GEMM (tf32 mma.sync) ---
    im2col_kernel<<<(unsigned)(((size_t)M_CONV * K_CONVP + 255) / 256), 256>>>(obs);
    mma_gemm<256><<<dim3(2, M_CONV / 128), 256, SMEM256>>>(
        p_acol, K_CONVP, p_wts + OFF_C1, conv1_b, nullptr, p_y, 512, K_CONVP, 0);

    // --- BN + conv2 + sigmoid ---
    bn_stats1_kernel<<<400, 512>>>();
    bn_stats2_kernel<<<1, 512>>>(bn1_g, bn1_b);
    conv2_sigmoid_kernel<<<M_CONV / 8, 256>>>(conv2_w, conv2_b);
    pad_x_kernel<<<(M_OBJ * (FEATP - FEAT) + 255) / 256, 256>>>();

    // --- encoder MLP: 32 -> 512 -> 512(LN) -> 128 ---
    mma_gemm<256><<<dim3(2, M_OBJ / 128), 256, SMEM256>>>(
        p_x, FEATP, p_wts + OFF_E1, enc_b1, nullptr, p_bufA, 512, FEATP, 1);
    mma_gemm<256><<<dim3(2, M_OBJ / 128), 256, SMEM256>>>(
        p_bufA, 512, p_wts + OFF_E2, enc_b2, nullptr, p_bufB, 512, 512, 0);
    ln_relu_kernel<<<M_OBJ, 256>>>(p_bufB, enc_lng, enc_lnb);
    mma_gemm<128><<<dim3(1, M_OBJ / 128), 128, SMEM128>>>(
        p_bufB, 512, p_wts + OFF_E3, enc_b3, nullptr, p_state, 128, 512, 0);

    // --- edge MLP: gather -> 256 -> 512 -> 512(LN) -> 512 ---
    gather_ein_kernel<<<(unsigned)(((size_t)M_EDGE * 256 + 255) / 256), 256>>>();
    mma_gemm<256><<<dim3(2, M_EDGE / 128), 256, SMEM256>>>(
        p_ein, 256, p_wts + OFF_G1, edge_b1, nullptr, p_bufA, 512, 256, 1);
    mma_gemm<256><<<dim3(2, M_EDGE / 128), 256, SMEM256>>>(
        p_bufA, 512, p_wts + OFF_G2, edge_b2, nullptr, p_bufB, 512, 512, 0);
    ln_relu_kernel<<<M_EDGE, 256>>>(p_bufB, edge_lng, edge_lnb);
    mma_gemm<256><<<dim3(2, M_EDGE / 128), 256, SMEM256>>>(
        p_bufB, 512, p_wts + OFF_G3, edge_b3, nullptr, p_bufA, 512, 512, 0);

    // --- aggregate + node input ---
    agg_kernel<<<(unsigned)(((size_t)M_OBJ * HID + 255) / 256), 256>>>();
    node_in_kernel<<<(unsigned)(((size_t)M_OBJ * NODE_INP + 255) / 256), 256>>>(action);

    // --- node MLP: 672 -> 512 -> 512(LN) -> 128, residual add state ---
    mma_gemm<256><<<dim3(2, M_OBJ / 128), 256, SMEM256>>>(
        p_nin, NODE_INP, p_wts + OFF_N1, node_b1, nullptr, p_bufB, 512, NODE_INP, 1);
    mma_gemm<256><<<dim3(2, M_OBJ / 128), 256, SMEM256>>>(
        p_bufB, 512, p_wts + OFF_N2, node_b2, nullptr, p_bufA, 512, 512, 0);
    ln_relu_kernel<<<M_OBJ, 256>>>(p_bufA, node_lng, node_lnb);
    mma_gemm<128><<<dim3(1, M_OBJ / 128), 128, SMEM128>>>(
        p_bufA, 512, p_wts + OFF_N3, node_b3, p_state, out, 128, 512, 0);
}

// round 9
// speedup vs baseline: 3.3662x; 1.3187x over previous
#include <cuda_runtime.h>
#include <cuda_fp16.h>
#include <stdint.h>
#include <math.h>

// ---------------------------------------------------------------------------
// Problem constants
// ---------------------------------------------------------------------------
#define BB      4096
#define KOBJ    5
#define EMB     128
#define HID     512
#define ADIM    4
#define FEAT    25
#define EPS_F   1e-5f

#define M_CONV  (BB * 25)          // 102400
#define K_CONV  300
#define K_CONVP 320                // padded to %32
#define M_OBJ   (BB * KOBJ)        // 20480
#define M_EDGE  (BB * 20)          // 81920
#define NODE_IN 644
#define NODE_INP 672               // padded
#define FEATP   32                 // padded

// ---------------------------------------------------------------------------
// Scratch (device globals)
// ---------------------------------------------------------------------------
static __device__ float g_acol[(size_t)M_CONV * K_CONVP];
static __device__ float g_y[(size_t)M_CONV * HID];
static __device__ float g_part[800 * 1024];
static __device__ float g_scale[HID];
static __device__ float g_shift[HID];
static __device__ float g_x[(size_t)M_OBJ * FEATP];
static __device__ float g_state[(size_t)M_OBJ * EMB];
static __device__ float g_ein[(size_t)M_EDGE * 2 * EMB];
static __device__ float g_bufA[(size_t)M_EDGE * HID];
static __device__ float g_bufB[(size_t)M_EDGE * HID];
static __device__ float g_agg[(size_t)M_OBJ * HID];
static __device__ float g_nin[(size_t)M_OBJ * NODE_INP];
static __device__ __half g_wtsh[1835008];   // transposed+padded weights (fp16)

#define OFF_C1 0         // 512x320
#define OFF_E1 163840    // 512x32
#define OFF_E2 180224    // 512x512
#define OFF_E3 442368    // 128x512
#define OFF_G1 507904    // 512x256
#define OFF_G2 638976    // 512x512
#define OFF_G3 901120    // 512x512
#define OFF_N1 1163264   // 512x672
#define OFF_N2 1507328   // 512x512
#define OFF_N3 1769472   // 128x512

// ---------------------------------------------------------------------------
// Helpers
// ---------------------------------------------------------------------------
#define CP_ASYNC16(dst, src) \
    asm volatile("cp.async.cg.shared.global [%0], [%1], 16;" :: "r"(dst), "l"(src))
#define CP_COMMIT() asm volatile("cp.async.commit_group;" ::: "memory")
#define CP_WAIT0()  asm volatile("cp.async.wait_group 0;" ::: "memory")

__device__ __forceinline__ uint32_t h2pack(float2 f) {
    __half2 h = __float22half2_rn(f);
    return *(uint32_t*)&h;
}

// ---------------------------------------------------------------------------
// fp16 mma.sync GEMM: C[M,N] = A[M,Kp](f32) @ Bt[N,Kp](f16)^T + bias
// (+relu)(+resid) or (aggMode) sum-of-4-rows -> C has M/4 rows.
// BM=128, BN in {256,128}, BK=32. Warp tile 64x64 (m16n8k16, mi=4, nj=8).
// A smem fp32 stride-40 pad; B smem fp16 stride-40 pad (both conflict-free).
// ---------------------------------------------------------------------------
template<int BN>
__global__ void __launch_bounds__(BN == 256 ? 256 : 128, 1)
mma_gemm(const float* __restrict__ A, int lda,
         const __half* __restrict__ Bt,
         const float* __restrict__ bias, const float* __restrict__ resid,
         float* __restrict__ C, int N, int K, int doRelu, int aggMode)
{
    constexpr int T    = (BN == 256) ? 256 : 128;
    constexpr int AELE = 128 * 40;            // floats per A buffer
    constexpr int BELE = BN * 40;             // halves per B buffer
    extern __shared__ char smraw[];
    float*  AsBuf = (float*)smraw;                          // [2][AELE]
    __half* BsBuf = (__half*)(smraw + 2 * AELE * 4);        // [2][BELE]

    const int tid  = threadIdx.x;
    const int warp = tid >> 5, lane = tid & 31;
    const int bm = blockIdx.y * 128;
    const int bn = blockIdx.x * BN;
    const int warpM = warp & 1;       // 2 M bands of 64
    const int warpN = warp >> 1;      // BN/64 N bands of 64
    const int g = lane >> 2;          // 0..7
    const int t = lane & 3;           // 0..3

    uint32_t sbase;
    asm("{ .reg .u64 u; cvta.to.shared.u64 u, %1; cvt.u32.u64 %0, u; }"
        : "=r"(sbase) : "l"(smraw));
    const uint32_t sA = sbase;
    const uint32_t sB = sbase + 2 * AELE * 4;

    const float*  Abase = A  + (size_t)bm * lda;
    const __half* Bbase = Bt + (size_t)bn * K;
    const int KT = K / 32;

    float acc[4][8][4];
#pragma unroll
    for (int mi = 0; mi < 4; ++mi)
#pragma unroll
        for (int nj = 0; nj < 8; ++nj)
#pragma unroll
            for (int q = 0; q < 4; ++q) acc[mi][nj][q] = 0.f;

    auto load_tile = [&](int kt) {
        const int buf = kt & 1;
        const int k0 = kt * 32;
        uint32_t da = sA + (uint32_t)(buf * AELE) * 4u;
#pragma unroll
        for (int i = 0; i < 1024 / T; ++i) {
            int id = tid + T * i;
            int r = id >> 3, c4 = id & 7;
            CP_ASYNC16(da + (uint32_t)(r * 40 + c4 * 4) * 4u,
                       Abase + (size_t)r * lda + k0 + c4 * 4);
        }
        uint32_t db = sB + (uint32_t)(buf * BELE) * 2u;
#pragma unroll
        for (int i = 0; i < (BN * 4) / T; ++i) {
            int id = tid + T * i;
            int r = id >> 2, c = id & 3;
            CP_ASYNC16(db + (uint32_t)(r * 40 + c * 8) * 2u,
                       Bbase + (size_t)r * K + k0 + c * 8);
        }
        CP_COMMIT();
    };

    load_tile(0);

    for (int kt = 0; kt < KT; ++kt) {
        CP_WAIT0();
        __syncthreads();
        if (kt + 1 < KT) load_tile(kt + 1);

        const float*  As = AsBuf + (kt & 1) * AELE;
        const __half* Bs = BsBuf + (kt & 1) * BELE;

#pragma unroll
        for (int ks = 0; ks < 2; ++ks) {
            const int kc = ks * 16 + 2 * t;
            uint32_t a[4][4], b[8][2];
#pragma unroll
            for (int mi = 0; mi < 4; ++mi) {
                const float* p0 = As + (warpM * 64 + mi * 16 + g) * 40 + kc;
                const float* p1 = p0 + 8 * 40;
                a[mi][0] = h2pack(*(const float2*)(p0));
                a[mi][1] = h2pack(*(const float2*)(p1));
                a[mi][2] = h2pack(*(const float2*)(p0 + 8));
                a[mi][3] = h2pack(*(const float2*)(p1 + 8));
            }
#pragma unroll
            for (int nj = 0; nj < 8; ++nj) {
                const __half* q = Bs + (warpN * 64 + nj * 8 + g) * 40 + kc;
                b[nj][0] = *(const uint32_t*)(q);
                b[nj][1] = *(const uint32_t*)(q + 8);
            }
#pragma unroll
            for (int mi = 0; mi < 4; ++mi)
#pragma unroll
                for (int nj = 0; nj < 8; ++nj)
                    asm volatile(
                        "mma.sync.aligned.m16n8k16.row.col.f32.f16.f16.f32 "
                        "{%0,%1,%2,%3}, {%4,%5,%6,%7}, {%8,%9}, {%0,%1,%2,%3};"
                        : "+f"(acc[mi][nj][0]), "+f"(acc[mi][nj][1]),
                          "+f"(acc[mi][nj][2]), "+f"(acc[mi][nj][3])
                        : "r"(a[mi][0]), "r"(a[mi][1]), "r"(a[mi][2]), "r"(a[mi][3]),
                          "r"(b[nj][0]), "r"(b[nj][1]));
        }
    }

    // ---- epilogue ----
    if (!aggMode) {
#pragma unroll
        for (int mi = 0; mi < 4; ++mi) {
            const int r0 = bm + warpM * 64 + mi * 16 + g;
#pragma unroll
            for (int nj = 0; nj < 8; ++nj) {
                const int col = bn + warpN * 64 + nj * 8 + t * 2;
                const float bz0 = bias[col], bz1 = bias[col + 1];
                float v00 = acc[mi][nj][0] + bz0, v01 = acc[mi][nj][1] + bz1;
                float v10 = acc[mi][nj][2] + bz0, v11 = acc[mi][nj][3] + bz1;
                if (doRelu) {
                    v00 = fmaxf(v00, 0.f); v01 = fmaxf(v01, 0.f);
                    v10 = fmaxf(v10, 0.f); v11 = fmaxf(v11, 0.f);
                }
                if (resid) {
                    const float* rp0 = resid + (size_t)r0 * N + col;
                    const float* rp1 = resid + (size_t)(r0 + 8) * N + col;
                    v00 += rp0[0]; v01 += rp0[1];
                    v10 += rp1[0]; v11 += rp1[1];
                }
                *(float2*)(C + (size_t)r0 * N + col)       = make_float2(v00, v01);
                *(float2*)(C + (size_t)(r0 + 8) * N + col) = make_float2(v10, v11);
            }
        }
    } else {
        // sum groups of 4 consecutive rows (edge->node aggregation), write M/4 rows
#pragma unroll
        for (int mi = 0; mi < 4; ++mi) {
            const int base = bm + warpM * 64 + mi * 16;
#pragma unroll
            for (int nj = 0; nj < 8; ++nj) {
                const int col = bn + warpN * 64 + nj * 8 + t * 2;
                const float bz0 = bias[col], bz1 = bias[col + 1];
                float v00 = acc[mi][nj][0] + bz0, v01 = acc[mi][nj][1] + bz1;
                float v10 = acc[mi][nj][2] + bz0, v11 = acc[mi][nj][3] + bz1;
#pragma unroll
                for (int o = 4; o <= 8; o <<= 1) {
                    v00 += __shfl_xor_sync(0xffffffffu, v00, o);
                    v01 += __shfl_xor_sync(0xffffffffu, v01, o);
                    v10 += __shfl_xor_sync(0xffffffffu, v10, o);
                    v11 += __shfl_xor_sync(0xffffffffu, v11, o);
                }
                if ((lane & 12) == 0) {                 // g == 0 or g == 4
                    const int gblk = lane >> 4;         // 0 or 1
                    const int r0 = (base >> 2) + gblk;  // rows base+4*gblk .. +3
                    *(float2*)(C + (size_t)r0 * N + col)       = make_float2(v00, v01);
                    *(float2*)(C + (size_t)(r0 + 2) * N + col) = make_float2(v10, v11);
                }
            }
        }
    }
}

// ---------------------------------------------------------------------------
// im2col (stride==kernel==10) with K padded 300 -> 320 (zeros)
// ---------------------------------------------------------------------------
__global__ void im2col_kernel(const float* __restrict__ obs) {
    size_t idx = (size_t)blockIdx.x * 256 + threadIdx.x;
    if (idx >= (size_t)M_CONV * K_CONVP) return;
    int m  = (int)(idx / K_CONVP);
    int kk = (int)(idx % K_CONVP);
    float v = 0.f;
    if (kk < K_CONV) {
        int b = m / 25, p = m % 25;
        int py = p / 5, px = p % 5;
        int c = kk / 100, rr = kk % 100;
        int ky = rr / 10, kx = rr % 10;
        v = obs[((size_t)(b * 3 + c) * 50 + py * 10 + ky) * 50 + px * 10 + kx];
    }
    g_acol[idx] = v;
}

// conv1_w [512][300] -> half [512][320] padded
__global__ void padcopy_h_kernel(const float* __restrict__ w, __half* __restrict__ dst,
                                 int N, int K, int Kp) {
    int idx = blockIdx.x * 256 + threadIdx.x;
    if (idx >= N * Kp) return;
    int n = idx / Kp, k = idx % Kp;
    dst[idx] = (k < K) ? __float2half(w[n * K + k]) : __half(0.f);
}

// dense weights [K][N] -> half dst[n][k] transposed, K padded
__global__ void transpose_pad_h_kernel(const float* __restrict__ w, __half* __restrict__ dst,
                                       int N, int K, int Kp) {
    int idx = blockIdx.x * 256 + threadIdx.x;
    if (idx >= N * Kp) return;
    int n = idx / Kp, k = idx % Kp;
    dst[idx] = (k < K) ? __float2half(w[k * N + n]) : __half(0.f);
}

// ---------------------------------------------------------------------------
// BatchNorm stats (deterministic 2-stage)
// ---------------------------------------------------------------------------
__global__ void bn_stats1_kernel() {
    int c = threadIdx.x;
    size_t r0 = (size_t)blockIdx.x * 256;
    float s = 0.f, ss = 0.f;
    for (int i = 0; i < 256; ++i) {
        float v = g_y[(r0 + i) * HID + c];
        s += v; ss += v * v;
    }
    g_part[(size_t)blockIdx.x * 1024 + c]       = s;
    g_part[(size_t)blockIdx.x * 1024 + 512 + c] = ss;
}

__global__ void bn_stats2_kernel(const float* __restrict__ gamma,
                                 const float* __restrict__ beta) {
    int c = threadIdx.x;
    float s = 0.f, ss = 0.f;
    for (int b = 0; b < 400; ++b) {
        s  += g_part[(size_t)b * 1024 + c];
        ss += g_part[(size_t)b * 1024 + 512 + c];
    }
    const float inv_n = 1.f / (float)M_CONV;
    float mu  = s * inv_n;
    float var = ss * inv_n - mu * mu;
    float sc = gamma[c] * rsqrtf(var + EPS_F);
    g_scale[c] = sc;
    g_shift[c] = beta[c] - mu * sc;
}

// ---------------------------------------------------------------------------
// BN normalize + relu + conv2(1x1) + sigmoid -> g_x (stride FEATP)
// ---------------------------------------------------------------------------
__global__ void conv2_sigmoid_kernel(const float* __restrict__ w2,
                                     const float* __restrict__ b2) {
    __shared__ float ws[5 * HID];
    __shared__ float bs[5];
    int tid = threadIdx.x;
    for (int i = tid; i < 5 * HID; i += 256) ws[i] = w2[i];
    if (tid < 5) bs[tid] = b2[tid];
    __syncthreads();

    int warp = tid >> 5, lane = tid & 31;
    size_t m = (size_t)blockIdx.x * 8 + warp;
    const float* y = g_y + m * HID;
    float a0 = 0.f, a1 = 0.f, a2 = 0.f, a3 = 0.f, a4 = 0.f;
#pragma unroll
    for (int i = 0; i < 16; ++i) {
        int c = lane + 32 * i;
        float h = fmaxf(fmaf(y[c], g_scale[c], g_shift[c]), 0.f);
        a0 = fmaf(h, ws[c],           a0);
        a1 = fmaf(h, ws[HID + c],     a1);
        a2 = fmaf(h, ws[2 * HID + c], a2);
        a3 = fmaf(h, ws[3 * HID + c], a3);
        a4 = fmaf(h, ws[4 * HID + c], a4);
    }
#pragma unroll
    for (int o = 16; o > 0; o >>= 1) {
        a0 += __shfl_down_sync(0xffffffffu, a0, o);
        a1 += __shfl_down_sync(0xffffffffu, a1, o);
        a2 += __shfl_down_sync(0xffffffffu, a2, o);
        a3 += __shfl_down_sync(0xffffffffu, a3, o);
        a4 += __shfl_down_sync(0xffffffffu, a4, o);
    }
    if (lane == 0) {
        int b = (int)(m / 25), f = (int)(m % 25);
        float* xb = g_x + (size_t)b * 5 * FEATP + f;
        xb[0 * FEATP] = 1.f / (1.f + expf(-(a0 + bs[0])));
        xb[1 * FEATP] = 1.f / (1.f + expf(-(a1 + bs[1])));
        xb[2 * FEATP] = 1.f / (1.f + expf(-(a2 + bs[2])));
        xb[3 * FEATP] = 1.f / (1.f + expf(-(a3 + bs[3])));
        xb[4 * FEATP] = 1.f / (1.f + expf(-(a4 + bs[4])));
    }
}

// zero the pad columns of g_x (cols 25..31)
__global__ void pad_x_kernel() {
    int idx = blockIdx.x * 256 + threadIdx.x;
    if (idx >= M_OBJ * (FEATP - FEAT)) return;
    int row = idx / (FEATP - FEAT), j = FEAT + idx % (FEATP - FEAT);
    g_x[(size_t)row * FEATP + j] = 0.f;
}

// ---------------------------------------------------------------------------
// LayerNorm(512) + ReLU in place
// ---------------------------------------------------------------------------
__global__ void ln_relu_kernel(float* __restrict__ H,
                               const float* __restrict__ g,
                               const float* __restrict__ b) {
    __shared__ float sh[8];
    float* h = H + (size_t)blockIdx.x * HID;
    int tid = threadIdx.x, lane = tid & 31, w = tid >> 5;

    float x0 = h[tid], x1 = h[tid + 256];
    float s = x0 + x1;
#pragma unroll
    for (int o = 16; o > 0; o >>= 1) s += __shfl_down_sync(0xffffffffu, s, o);
    if (lane == 0) sh[w] = s;
    __syncthreads();
    if (tid == 0) {
        float tt = 0.f;
#pragma unroll
        for (int i = 0; i < 8; ++i) tt += sh[i];
        sh[0] = tt;
    }
    __syncthreads();
    float mean = sh[0] * (1.f / (float)HID);
    __syncthreads();

    float d0 = x0 - mean, d1 = x1 - mean;
    float ss = d0 * d0 + d1 * d1;
#pragma unroll
    for (int o = 16; o > 0; o >>= 1) ss += __shfl_down_sync(0xffffffffu, ss, o);
    if (lane == 0) sh[w] = ss;
    __syncthreads();
    if (tid == 0) {
        float tt = 0.f;
#pragma unroll
        for (int i = 0; i < 8; ++i) tt += sh[i];
        sh[0] = tt;
    }
    __syncthreads();
    float inv = rsqrtf(sh[0] * (1.f / (float)HID) + EPS_F);

    h[tid]       = fmaxf(fmaf(d0 * inv, g[tid],       b[tid]),       0.f);
    h[tid + 256] = fmaxf(fmaf(d1 * inv, g[tid + 256], b[tid + 256]), 0.f);
}

// ---------------------------------------------------------------------------
// Edge gather / node-input assembly
// ---------------------------------------------------------------------------
__global__ void gather_ein_kernel() {
    size_t idx = (size_t)blockIdx.x * 256 + threadIdx.x;
    if (idx >= (size_t)M_EDGE * 256) return;
    int r = (int)(idx >> 8);
    int j = (int)(idx & 255);
    int b = r / 20, p = r % 20;
    int i = p >> 2, t = p & 3;
    int tgt = t + (t >= i ? 1 : 0);
    int obj = (j < 128) ? i : tgt;
    g_ein[idx] = g_state[((size_t)b * KOBJ + obj) * EMB + (j & 127)];
}

__global__ void node_in_kernel(const int* __restrict__ action) {
    size_t idx = (size_t)blockIdx.x * 256 + threadIdx.x;
    if (idx >= (size_t)M_OBJ * NODE_INP) return;
    int r = (int)(idx / NODE_INP);
    int j = (int)(idx % NODE_INP);
    int b = r / KOBJ, k = r % KOBJ;
    float v;
    if (j < EMB) {
        v = g_state[(size_t)r * EMB + j];
    } else if (j < EMB + ADIM) {
        v = (action[b] == k * ADIM + (j - EMB)) ? 1.f : 0.f;
    } else if (j < NODE_IN) {
        v = g_agg[(size_t)r * HID + (j - EMB - ADIM)];
    } else {
        v = 0.f;
    }
    g_nin[idx] = v;
}

// ---------------------------------------------------------------------------
// Launch
// ---------------------------------------------------------------------------
extern "C" void kernel_launch(void* const* d_in, const int* in_sizes, int n_in,
                              void* d_out, int out_size) {
    const float* obs     = (const float*)d_in[0];
    const int*   action  = (const int*)d_in[1];
    const float* conv1_w = (const float*)d_in[2];
    const float* conv1_b = (const float*)d_in[3];
    const float* bn1_g   = (const float*)d_in[4];
    const float* bn1_b   = (const float*)d_in[5];
    const float* conv2_w = (const float*)d_in[6];
    const float* conv2_b = (const float*)d_in[7];
    const float* enc_w1  = (const float*)d_in[8];
    const float* enc_b1  = (const float*)d_in[9];
    const float* enc_w2  = (const float*)d_in[10];
    const float* enc_b2  = (const float*)d_in[11];
    const float* enc_lng = (const float*)d_in[12];
    const float* enc_lnb = (const float*)d_in[13];
    const float* enc_w3  = (const float*)d_in[14];
    const float* enc_b3  = (const float*)d_in[15];
    const float* edge_w1 = (const float*)d_in[16];
    const float* edge_b1 = (const float*)d_in[17];
    const float* edge_w2 = (const float*)d_in[18];
    const float* edge_b2 = (const float*)d_in[19];
    const float* edge_lng= (const float*)d_in[20];
    const float* edge_lnb= (const float*)d_in[21];
    const float* edge_w3 = (const float*)d_in[22];
    const float* edge_b3 = (const float*)d_in[23];
    const float* node_w1 = (const float*)d_in[24];
    const float* node_b1 = (const float*)d_in[25];
    const float* node_w2 = (const float*)d_in[26];
    const float* node_b2 = (const float*)d_in[27];
    const float* node_lng= (const float*)d_in[28];
    const float* node_lnb= (const float*)d_in[29];
    const float* node_w3 = (const float*)d_in[30];
    const float* node_b3 = (const float*)d_in[31];
    float* out = (float*)d_out;

    float *p_acol, *p_y, *p_x, *p_state, *p_ein, *p_bufA, *p_bufB, *p_agg, *p_nin;
    __half* p_wts;
    cudaGetSymbolAddress((void**)&p_acol,  g_acol);
    cudaGetSymbolAddress((void**)&p_y,     g_y);
    cudaGetSymbolAddress((void**)&p_x,     g_x);
    cudaGetSymbolAddress((void**)&p_state, g_state);
    cudaGetSymbolAddress((void**)&p_ein,   g_ein);
    cudaGetSymbolAddress((void**)&p_bufA,  g_bufA);
    cudaGetSymbolAddress((void**)&p_bufB,  g_bufB);
    cudaGetSymbolAddress((void**)&p_agg,   g_agg);
    cudaGetSymbolAddress((void**)&p_nin,   g_nin);
    cudaGetSymbolAddress((void**)&p_wts,   g_wtsh);

    const int SMEM256 = 2 * 128 * 40 * 4 + 2 * 256 * 40 * 2;   // 81920
    const int SMEM128 = 2 * 128 * 40 * 4 + 2 * 128 * 40 * 2;   // 61440
    cudaFuncSetAttribute(mma_gemm<256>, cudaFuncAttributeMaxDynamicSharedMemorySize, SMEM256);
    cudaFuncSetAttribute(mma_gemm<128>, cudaFuncAttributeMaxDynamicSharedMemorySize, SMEM128);

    // --- weight prep (transpose + K-pad + fp16 convert) ---
    padcopy_h_kernel<<<(512 * K_CONVP + 255) / 256, 256>>>(conv1_w, p_wts + OFF_C1, 512, K_CONV, K_CONVP);
    transpose_pad_h_kernel<<<(512 * 32 + 255) / 256, 256>>>(enc_w1, p_wts + OFF_E1, 512, FEAT, FEATP);
    transpose_pad_h_kernel<<<(512 * 512 + 255) / 256, 256>>>(enc_w2, p_wts + OFF_E2, 512, 512, 512);
    transpose_pad_h_kernel<<<(128 * 512 + 255) / 256, 256>>>(enc_w3, p_wts + OFF_E3, 128, 512, 512);
    transpose_pad_h_kernel<<<(512 * 256 + 255) / 256, 256>>>(edge_w1, p_wts + OFF_G1, 512, 256, 256);
    transpose_pad_h_kernel<<<(512 * 512 + 255) / 256, 256>>>(edge_w2, p_wts + OFF_G2, 512, 512, 512);
    transpose_pad_h_kernel<<<(512 * 512 + 255) / 256, 256>>>(edge_w3, p_wts + OFF_G3, 512, 512, 512);
    transpose_pad_h_kernel<<<(512 * NODE_INP + 255) / 256, 256>>>(node_w1, p_wts + OFF_N1, 512, NODE_IN, NODE_INP);
    transpose_pad_h_kernel<<<(512 * 512 + 255) / 256, 256>>>(node_w2, p_wts + OFF_N2, 512, 512, 512);
    transpose_pad_h_kernel<<<(128 * 512 + 255) / 256, 256>>>(node_w3, p_wts + OFF_N3, 128, 512, 512);

    // --- conv1 as GEMM ---
    im2col_kernel<<<(unsigned)(((size_t)M_CONV * K_CONVP + 255) / 256), 256>>>(obs);
    mma_gemm<256><<<dim3(2, M_CONV / 128), 256, SMEM256>>>(
        p_acol, K_CONVP, p_wts + OFF_C1, conv1_b, nullptr, p_y, 512, K_CONVP, 0, 0);

    // --- BN + conv2 + sigmoid ---
    bn_stats1_kernel<<<400, 512>>>();
    bn_stats2_kernel<<<1, 512>>>(bn1_g, bn1_b);
    conv2_sigmoid_kernel<<<M_CONV / 8, 256>>>(conv2_w, conv2_b);
    pad_x_kernel<<<(M_OBJ * (FEATP - FEAT) + 255) / 256, 256>>>();

    // --- encoder MLP: 32 -> 512 -> 512(LN) -> 128 ---
    mma_gemm<256><<<dim3(2, M_OBJ / 128), 256, SMEM256>>>(
        p_x, FEATP, p_wts + OFF_E1, enc_b1, nullptr, p_bufA, 512, FEATP, 1, 0);
    mma_gemm<256><<<dim3(2, M_OBJ / 128), 256, SMEM256>>>(
        p_bufA, 512, p_wts + OFF_E2, enc_b2, nullptr, p_bufB, 512, 512, 0, 0);
    ln_relu_kernel<<<M_OBJ, 256>>>(p_bufB, enc_lng, enc_lnb);
    mma_gemm<128><<<dim3(1, M_OBJ / 128), 128, SMEM128>>>(
        p_bufB, 512, p_wts + OFF_E3, enc_b3, nullptr, p_state, 128, 512, 0, 0);

    // --- edge MLP: gather -> 256 -> 512 -> 512(LN) -> 512(+agg fused) ---
    gather_ein_kernel<<<(unsigned)(((size_t)M_EDGE * 256 + 255) / 256), 256>>>();
    mma_gemm<256><<<dim3(2, M_EDGE / 128), 256, SMEM256>>>(
        p_ein, 256, p_wts + OFF_G1, edge_b1, nullptr, p_bufA, 512, 256, 1, 0);
    mma_gemm<256><<<dim3(2, M_EDGE / 128), 256, SMEM256>>>(
        p_bufA, 512, p_wts + OFF_G2, edge_b2, nullptr, p_bufB, 512, 512, 0, 0);
    ln_relu_kernel<<<M_EDGE, 256>>>(p_bufB, edge_lng, edge_lnb);
    mma_gemm<256><<<dim3(2, M_EDGE / 128), 256, SMEM256>>>(
        p_bufB, 512, p_wts + OFF_G3, edge_b3, nullptr, p_agg, 512, 512, 0, 1);

    // --- node input assembly ---
    node_in_kernel<<<(unsigned)(((size_t)M_OBJ * NODE_INP + 255) / 256), 256>>>(action);

    // --- node MLP: 672 -> 512 -> 512(LN) -> 128, residual add state ---
    mma_gemm<256><<<dim3(2, M_OBJ / 128), 256, SMEM256>>>(
        p_nin, NODE_INP, p_wts + OFF_N1, node_b1, nullptr, p_bufB, 512, NODE_INP, 1, 0);
    mma_gemm<256><<<dim3(2, M_OBJ / 128), 256, SMEM256>>>(
        p_bufB, 512, p_wts + OFF_N2, node_b2, nullptr, p_bufA, 512, 512, 0, 0);
    ln_relu_kernel<<<M_OBJ, 256>>>(p_bufA, node_lng, node_lnb);
    mma_gemm<128><<<dim3(1, M_OBJ / 128), 128, SMEM128>>>(
        p_bufA, 512, p_wts + OFF_N3, node_b3, p_state, out, 128, 512, 0, 0);
}

// round 10
// speedup vs baseline: 3.4643x; 1.0292x over previous
#include <cuda_runtime.h>
#include <cuda_fp16.h>
#include <stdint.h>
#include <math.h>

// ---------------------------------------------------------------------------
// Problem constants
// ---------------------------------------------------------------------------
#define BB      4096
#define KOBJ    5
#define EMB     128
#define HID     512
#define ADIM    4
#define FEAT    25
#define EPS_F   1e-5f

#define M_CONV  (BB * 25)          // 102400
#define K_CONV  300
#define K_CONVP 320                // padded to %32
#define M_OBJ   (BB * KOBJ)        // 20480
#define M_EDGE  (BB * 20)          // 81920
#define NODE_IN 644
#define NODE_INP 672               // padded
#define FEATP   32                 // padded

// ---------------------------------------------------------------------------
// Scratch (device globals)
// ---------------------------------------------------------------------------
static __device__ __half g_acolh[(size_t)M_CONV * K_CONVP];   // conv1 A (fp16)
static __device__ float  g_y[(size_t)M_CONV * HID];           // conv1 out (fp32: BN needs it)
static __device__ float  g_part[800 * 1024];
static __device__ float  g_scale[HID];
static __device__ float  g_shift[HID];
static __device__ __half g_xh[(size_t)M_OBJ * FEATP];         // encoder input (fp16)
static __device__ float  g_state[(size_t)M_OBJ * EMB];        // fp32 (residual)
static __device__ __half g_einh[(size_t)M_EDGE * 2 * EMB];    // edge input (fp16)
static __device__ __half g_bufh[(size_t)M_EDGE * HID];        // fp16 activations (A operands)
static __device__ float  g_bufB[(size_t)M_EDGE * HID];        // fp32 pre-LN buffer
static __device__ float  g_agg[(size_t)M_OBJ * HID];          // fp32 aggregate
static __device__ __half g_ninh[(size_t)M_OBJ * NODE_INP];    // node input (fp16)
static __device__ __half g_wtsh[1835008];                     // fp16 transposed weights

#define OFF_C1 0         // 512x320
#define OFF_E1 163840    // 512x32
#define OFF_E2 180224    // 512x512
#define OFF_E3 442368    // 128x512
#define OFF_G1 507904    // 512x256
#define OFF_G2 638976    // 512x512
#define OFF_G3 901120    // 512x512
#define OFF_N1 1163264   // 512x672
#define OFF_N2 1507328   // 512x512
#define OFF_N3 1769472   // 128x512

// ---------------------------------------------------------------------------
// Helpers
// ---------------------------------------------------------------------------
#define CP_ASYNC16(dst, src) \
    asm volatile("cp.async.cg.shared.global [%0], [%1], 16;" :: "r"(dst), "l"(src))
#define CP_COMMIT() asm volatile("cp.async.commit_group;" ::: "memory")
#define CP_WAIT0()  asm volatile("cp.async.wait_group 0;" ::: "memory")

#define LDSM_X4(r, addr)                                                      \
    asm volatile("ldmatrix.sync.aligned.m8n8.x4.shared.b16 {%0,%1,%2,%3}, [%4];" \
        : "=r"((r)[0]), "=r"((r)[1]), "=r"((r)[2]), "=r"((r)[3]) : "r"(addr))

// ---------------------------------------------------------------------------
// fp16 mma.sync GEMM: C[M,N] = A[M,Kp](f16) @ Bt[N,Kp](f16)^T + bias
// (+relu)(+resid) ; aggMode: sum-of-4-rows -> C has M/4 rows ;
// outHalf: C written as fp16.
// BM=128, BN in {256,128}, BK=32. Warp tile 64x64 (m16n8k16, mi=4, nj=8).
// Both operands fp16 in SMEM, stride-40-half pad, ldmatrix.x4 loads.
// ---------------------------------------------------------------------------
template<int BN>
__global__ void __launch_bounds__(BN == 256 ? 256 : 128, 1)
mma_gemm(const __half* __restrict__ A, int lda,
         const __half* __restrict__ Bt,
         const float* __restrict__ bias, const float* __restrict__ resid,
         void* __restrict__ Cv, int N, int K, int doRelu, int aggMode, int outHalf)
{
    constexpr int T     = (BN == 256) ? 256 : 128;
    constexpr int AELEB = 128 * 40 * 2;       // bytes per A buffer (10240)
    constexpr int BELEB = BN * 40 * 2;        // bytes per B buffer
    extern __shared__ char smraw[];

    const int tid  = threadIdx.x;
    const int warp = tid >> 5, lane = tid & 31;
    const int bm = blockIdx.y * 128;
    const int bn = blockIdx.x * BN;
    const int warpM = warp & 1;
    const int warpN = warp >> 1;
    const int g = lane >> 2;
    const int t = lane & 3;

    uint32_t sbase;
    asm("{ .reg .u64 u; cvta.to.shared.u64 u, %1; cvt.u32.u64 %0, u; }"
        : "=r"(sbase) : "l"(smraw));
    const uint32_t sA = sbase;
    const uint32_t sB = sbase + 2 * AELEB;

    const __half* Abase = A  + (size_t)bm * lda;
    const __half* Bbase = Bt + (size_t)bn * K;
    const int KT = K / 32;

    float acc[4][8][4];
#pragma unroll
    for (int mi = 0; mi < 4; ++mi)
#pragma unroll
        for (int nj = 0; nj < 8; ++nj)
#pragma unroll
            for (int q = 0; q < 4; ++q) acc[mi][nj][q] = 0.f;

    auto load_tile = [&](int kt) {
        const int buf = kt & 1;
        const int k0 = kt * 32;
        uint32_t da = sA + (uint32_t)(buf * AELEB);
#pragma unroll
        for (int i = 0; i < 512 / T; ++i) {
            int id = tid + T * i;
            int r = id >> 2, c = id & 3;
            CP_ASYNC16(da + (uint32_t)(r * 40 + c * 8) * 2u,
                       Abase + (size_t)r * lda + k0 + c * 8);
        }
        uint32_t db = sB + (uint32_t)(buf * BELEB);
#pragma unroll
        for (int i = 0; i < (BN * 4) / T; ++i) {
            int id = tid + T * i;
            int r = id >> 2, c = id & 3;
            CP_ASYNC16(db + (uint32_t)(r * 40 + c * 8) * 2u,
                       Bbase + (size_t)r * K + k0 + c * 8);
        }
        CP_COMMIT();
    };

    // ldmatrix per-thread base addresses (row16 = lane&15, colgroup = lane>>4)
    const uint32_t aAddr0 = sA + (uint32_t)(((warpM * 64 + (lane & 15)) * 40
                                             + (lane >> 4) * 8) * 2);
    const uint32_t bAddr0 = sB + (uint32_t)(((warpN * 64 + (lane & 15)) * 40
                                             + (lane >> 4) * 8) * 2);

    load_tile(0);

    for (int kt = 0; kt < KT; ++kt) {
        CP_WAIT0();
        __syncthreads();
        if (kt + 1 < KT) load_tile(kt + 1);

        const uint32_t abuf = aAddr0 + (kt & 1) * AELEB;
        const uint32_t bbuf = bAddr0 + (kt & 1) * BELEB;

#pragma unroll
        for (int ks = 0; ks < 2; ++ks) {
            const uint32_t kofs = ks * 32;     // 16 halves
            uint32_t a[4][4], b[4][4];
#pragma unroll
            for (int mi = 0; mi < 4; ++mi)
                LDSM_X4(a[mi], abuf + mi * 1280 + kofs);
#pragma unroll
            for (int njp = 0; njp < 4; ++njp)
                LDSM_X4(b[njp], bbuf + njp * 1280 + kofs);
#pragma unroll
            for (int mi = 0; mi < 4; ++mi)
#pragma unroll
                for (int nj = 0; nj < 8; ++nj) {
                    const uint32_t b0 = (nj & 1) ? b[nj >> 1][1] : b[nj >> 1][0];
                    const uint32_t b1 = (nj & 1) ? b[nj >> 1][3] : b[nj >> 1][2];
                    asm volatile(
                        "mma.sync.aligned.m16n8k16.row.col.f32.f16.f16.f32 "
                        "{%0,%1,%2,%3}, {%4,%5,%6,%7}, {%8,%9}, {%0,%1,%2,%3};"
                        : "+f"(acc[mi][nj][0]), "+f"(acc[mi][nj][1]),
                          "+f"(acc[mi][nj][2]), "+f"(acc[mi][nj][3])
                        : "r"(a[mi][0]), "r"(a[mi][1]), "r"(a[mi][2]), "r"(a[mi][3]),
                          "r"(b0), "r"(b1));
                }
        }
    }

    // ---- epilogue ----
    if (!aggMode) {
#pragma unroll
        for (int mi = 0; mi < 4; ++mi) {
            const int r0 = bm + warpM * 64 + mi * 16 + g;
#pragma unroll
            for (int nj = 0; nj < 8; ++nj) {
                const int col = bn + warpN * 64 + nj * 8 + t * 2;
                const float bz0 = bias[col], bz1 = bias[col + 1];
                float v00 = acc[mi][nj][0] + bz0, v01 = acc[mi][nj][1] + bz1;
                float v10 = acc[mi][nj][2] + bz0, v11 = acc[mi][nj][3] + bz1;
                if (doRelu) {
                    v00 = fmaxf(v00, 0.f); v01 = fmaxf(v01, 0.f);
                    v10 = fmaxf(v10, 0.f); v11 = fmaxf(v11, 0.f);
                }
                if (resid) {
                    const float* rp0 = resid + (size_t)r0 * N + col;
                    const float* rp1 = resid + (size_t)(r0 + 8) * N + col;
                    v00 += rp0[0]; v01 += rp0[1];
                    v10 += rp1[0]; v11 += rp1[1];
                }
                if (outHalf) {
                    __half* Ch = (__half*)Cv;
                    *(__half2*)(Ch + (size_t)r0 * N + col)       = __floats2half2_rn(v00, v01);
                    *(__half2*)(Ch + (size_t)(r0 + 8) * N + col) = __floats2half2_rn(v10, v11);
                } else {
                    float* C = (float*)Cv;
                    *(float2*)(C + (size_t)r0 * N + col)       = make_float2(v00, v01);
                    *(float2*)(C + (size_t)(r0 + 8) * N + col) = make_float2(v10, v11);
                }
            }
        }
    } else {
        // sum groups of 4 consecutive rows (edge->node aggregation), fp32 C
        float* C = (float*)Cv;
#pragma unroll
        for (int mi = 0; mi < 4; ++mi) {
            const int base = bm + warpM * 64 + mi * 16;
#pragma unroll
            for (int nj = 0; nj < 8; ++nj) {
                const int col = bn + warpN * 64 + nj * 8 + t * 2;
                const float bz0 = bias[col], bz1 = bias[col + 1];
                float v00 = acc[mi][nj][0] + bz0, v01 = acc[mi][nj][1] + bz1;
                float v10 = acc[mi][nj][2] + bz0, v11 = acc[mi][nj][3] + bz1;
#pragma unroll
                for (int o = 4; o <= 8; o <<= 1) {
                    v00 += __shfl_xor_sync(0xffffffffu, v00, o);
                    v01 += __shfl_xor_sync(0xffffffffu, v01, o);
                    v10 += __shfl_xor_sync(0xffffffffu, v10, o);
                    v11 += __shfl_xor_sync(0xffffffffu, v11, o);
                }
                if ((lane & 12) == 0) {
                    const int gblk = lane >> 4;
                    const int r0 = (base >> 2) + gblk;
                    *(float2*)(C + (size_t)r0 * N + col)       = make_float2(v00, v01);
                    *(float2*)(C + (size_t)(r0 + 2) * N + col) = make_float2(v10, v11);
                }
            }
        }
    }
}

// ---------------------------------------------------------------------------
// im2col (stride==kernel==10) with K padded 300 -> 320, fp16 output
// ---------------------------------------------------------------------------
__global__ void im2col_kernel(const float* __restrict__ obs) {
    size_t idx = (size_t)blockIdx.x * 256 + threadIdx.x;
    if (idx >= (size_t)M_CONV * K_CONVP) return;
    int m  = (int)(idx / K_CONVP);
    int kk = (int)(idx % K_CONVP);
    float v = 0.f;
    if (kk < K_CONV) {
        int b = m / 25, p = m % 25;
        int py = p / 5, px = p % 5;
        int c = kk / 100, rr = kk % 100;
        int ky = rr / 10, kx = rr % 10;
        v = obs[((size_t)(b * 3 + c) * 50 + py * 10 + ky) * 50 + px * 10 + kx];
    }
    g_acolh[idx] = __float2half(v);
}

// conv1_w [512][300] -> half [512][320] padded
__global__ void padcopy_h_kernel(const float* __restrict__ w, __half* __restrict__ dst,
                                 int N, int K, int Kp) {
    int idx = blockIdx.x * 256 + threadIdx.x;
    if (idx >= N * Kp) return;
    int n = idx / Kp, k = idx % Kp;
    dst[idx] = (k < K) ? __float2half(w[n * K + k]) : __half(0.f);
}

// dense weights [K][N] -> half dst[n][k] transposed, K padded
__global__ void transpose_pad_h_kernel(const float* __restrict__ w, __half* __restrict__ dst,
                                       int N, int K, int Kp) {
    int idx = blockIdx.x * 256 + threadIdx.x;
    if (idx >= N * Kp) return;
    int n = idx / Kp, k = idx % Kp;
    dst[idx] = (k < K) ? __float2half(w[k * N + n]) : __half(0.f);
}

// ---------------------------------------------------------------------------
// BatchNorm stats (deterministic 2-stage)
// ---------------------------------------------------------------------------
__global__ void bn_stats1_kernel() {
    int c = threadIdx.x;
    size_t r0 = (size_t)blockIdx.x * 256;
    float s = 0.f, ss = 0.f;
    for (int i = 0; i < 256; ++i) {
        float v = g_y[(r0 + i) * HID + c];
        s += v; ss += v * v;
    }
    g_part[(size_t)blockIdx.x * 1024 + c]       = s;
    g_part[(size_t)blockIdx.x * 1024 + 512 + c] = ss;
}

__global__ void bn_stats2_kernel(const float* __restrict__ gamma,
                                 const float* __restrict__ beta) {
    int c = threadIdx.x;
    float s = 0.f, ss = 0.f;
    for (int b = 0; b < 400; ++b) {
        s  += g_part[(size_t)b * 1024 + c];
        ss += g_part[(size_t)b * 1024 + 512 + c];
    }
    const float inv_n = 1.f / (float)M_CONV;
    float mu  = s * inv_n;
    float var = ss * inv_n - mu * mu;
    float sc = gamma[c] * rsqrtf(var + EPS_F);
    g_scale[c] = sc;
    g_shift[c] = beta[c] - mu * sc;
}

// ---------------------------------------------------------------------------
// BN normalize + relu + conv2(1x1) + sigmoid -> g_xh (fp16, stride FEATP)
// ---------------------------------------------------------------------------
__global__ void conv2_sigmoid_kernel(const float* __restrict__ w2,
                                     const float* __restrict__ b2) {
    __shared__ float ws[5 * HID];
    __shared__ float bs[5];
    int tid = threadIdx.x;
    for (int i = tid; i < 5 * HID; i += 256) ws[i] = w2[i];
    if (tid < 5) bs[tid] = b2[tid];
    __syncthreads();

    int warp = tid >> 5, lane = tid & 31;
    size_t m = (size_t)blockIdx.x * 8 + warp;
    const float* y = g_y + m * HID;
    float a0 = 0.f, a1 = 0.f, a2 = 0.f, a3 = 0.f, a4 = 0.f;
#pragma unroll
    for (int i = 0; i < 16; ++i) {
        int c = lane + 32 * i;
        float h = fmaxf(fmaf(y[c], g_scale[c], g_shift[c]), 0.f);
        a0 = fmaf(h, ws[c],           a0);
        a1 = fmaf(h, ws[HID + c],     a1);
        a2 = fmaf(h, ws[2 * HID + c], a2);
        a3 = fmaf(h, ws[3 * HID + c], a3);
        a4 = fmaf(h, ws[4 * HID + c], a4);
    }
#pragma unroll
    for (int o = 16; o > 0; o >>= 1) {
        a0 += __shfl_down_sync(0xffffffffu, a0, o);
        a1 += __shfl_down_sync(0xffffffffu, a1, o);
        a2 += __shfl_down_sync(0xffffffffu, a2, o);
        a3 += __shfl_down_sync(0xffffffffu, a3, o);
        a4 += __shfl_down_sync(0xffffffffu, a4, o);
    }
    if (lane == 0) {
        int b = (int)(m / 25), f = (int)(m % 25);
        __half* xb = g_xh + (size_t)b * 5 * FEATP + f;
        xb[0 * FEATP] = __float2half(1.f / (1.f + expf(-(a0 + bs[0]))));
        xb[1 * FEATP] = __float2half(1.f / (1.f + expf(-(a1 + bs[1]))));
        xb[2 * FEATP] = __float2half(1.f / (1.f + expf(-(a2 + bs[2]))));
        xb[3 * FEATP] = __float2half(1.f / (1.f + expf(-(a3 + bs[3]))));
        xb[4 * FEATP] = __float2half(1.f / (1.f + expf(-(a4 + bs[4]))));
    }
}

// zero the pad columns of g_xh (cols 25..31)
__global__ void pad_x_kernel() {
    int idx = blockIdx.x * 256 + threadIdx.x;
    if (idx >= M_OBJ * (FEATP - FEAT)) return;
    int row = idx / (FEATP - FEAT), j = FEAT + idx % (FEATP - FEAT);
    g_xh[(size_t)row * FEATP + j] = __half(0.f);
}

// ---------------------------------------------------------------------------
// LayerNorm(512) + ReLU: fp32 in, fp16 out (feeds next GEMM A)
// ---------------------------------------------------------------------------
__global__ void ln_relu_kernel(const float* __restrict__ Hin,
                               __half* __restrict__ Hout,
                               const float* __restrict__ g,
                               const float* __restrict__ b) {
    __shared__ float sh[8];
    const float* h = Hin + (size_t)blockIdx.x * HID;
    __half* ho = Hout + (size_t)blockIdx.x * HID;
    int tid = threadIdx.x, lane = tid & 31, w = tid >> 5;

    float x0 = h[tid], x1 = h[tid + 256];
    float s = x0 + x1;
#pragma unroll
    for (int o = 16; o > 0; o >>= 1) s += __shfl_down_sync(0xffffffffu, s, o);
    if (lane == 0) sh[w] = s;
    __syncthreads();
    if (tid == 0) {
        float tt = 0.f;
#pragma unroll
        for (int i = 0; i < 8; ++i) tt += sh[i];
        sh[0] = tt;
    }
    __syncthreads();
    float mean = sh[0] * (1.f / (float)HID);
    __syncthreads();

    float d0 = x0 - mean, d1 = x1 - mean;
    float ss = d0 * d0 + d1 * d1;
#pragma unroll
    for (int o = 16; o > 0; o >>= 1) ss += __shfl_down_sync(0xffffffffu, ss, o);
    if (lane == 0) sh[w] = ss;
    __syncthreads();
    if (tid == 0) {
        float tt = 0.f;
#pragma unroll
        for (int i = 0; i < 8; ++i) tt += sh[i];
        sh[0] = tt;
    }
    __syncthreads();
    float inv = rsqrtf(sh[0] * (1.f / (float)HID) + EPS_F);

    ho[tid]       = __float2half(fmaxf(fmaf(d0 * inv, g[tid],       b[tid]),       0.f));
    ho[tid + 256] = __float2half(fmaxf(fmaf(d1 * inv, g[tid + 256], b[tid + 256]), 0.f));
}

// ---------------------------------------------------------------------------
// Edge gather / node-input assembly (fp16 outputs)
// ---------------------------------------------------------------------------
__global__ void gather_ein_kernel() {
    size_t idx = (size_t)blockIdx.x * 256 + threadIdx.x;
    if (idx >= (size_t)M_EDGE * 256) return;
    int r = (int)(idx >> 8);
    int j = (int)(idx & 255);
    int b = r / 20, p = r % 20;
    int i = p >> 2, t = p & 3;
    int tgt = t + (t >= i ? 1 : 0);
    int obj = (j < 128) ? i : tgt;
    g_einh[idx] = __float2half(g_state[((size_t)b * KOBJ + obj) * EMB + (j & 127)]);
}

__global__ void node_in_kernel(const int* __restrict__ action) {
    size_t idx = (size_t)blockIdx.x * 256 + threadIdx.x;
    if (idx >= (size_t)M_OBJ * NODE_INP) return;
    int r = (int)(idx / NODE_INP);
    int j = (int)(idx % NODE_INP);
    int b = r / KOBJ, k = r % KOBJ;
    float v;
    if (j < EMB) {
        v = g_state[(size_t)r * EMB + j];
    } else if (j < EMB + ADIM) {
        v = (action[b] == k * ADIM + (j - EMB)) ? 1.f : 0.f;
    } else if (j < NODE_IN) {
        v = g_agg[(size_t)r * HID + (j - EMB - ADIM)];
    } else {
        v = 0.f;
    }
    g_ninh[idx] = __float2half(v);
}

// ---------------------------------------------------------------------------
// Launch
// ---------------------------------------------------------------------------
extern "C" void kernel_launch(void* const* d_in, const int* in_sizes, int n_in,
                              void* d_out, int out_size) {
    const float* obs     = (const float*)d_in[0];
    const int*   action  = (const int*)d_in[1];
    const float* conv1_w = (const float*)d_in[2];
    const float* conv1_b = (const float*)d_in[3];
    const float* bn1_g   = (const float*)d_in[4];
    const float* bn1_b   = (const float*)d_in[5];
    const float* conv2_w = (const float*)d_in[6];
    const float* conv2_b = (const float*)d_in[7];
    const float* enc_w1  = (const float*)d_in[8];
    const float* enc_b1  = (const float*)d_in[9];
    const float* enc_w2  = (const float*)d_in[10];
    const float* enc_b2  = (const float*)d_in[11];
    const float* enc_lng = (const float*)d_in[12];
    const float* enc_lnb = (const float*)d_in[13];
    const float* enc_w3  = (const float*)d_in[14];
    const float* enc_b3  = (const float*)d_in[15];
    const float* edge_w1 = (const float*)d_in[16];
    const float* edge_b1 = (const float*)d_in[17];
    const float* edge_w2 = (const float*)d_in[18];
    const float* edge_b2 = (const float*)d_in[19];
    const float* edge_lng= (const float*)d_in[20];
    const float* edge_lnb= (const float*)d_in[21];
    const float* edge_w3 = (const float*)d_in[22];
    const float* edge_b3 = (const float*)d_in[23];
    const float* node_w1 = (const float*)d_in[24];
    const float* node_b1 = (const float*)d_in[25];
    const float* node_w2 = (const float*)d_in[26];
    const float* node_b2 = (const float*)d_in[27];
    const float* node_lng= (const float*)d_in[28];
    const float* node_lnb= (const float*)d_in[29];
    const float* node_w3 = (const float*)d_in[30];
    const float* node_b3 = (const float*)d_in[31];
    float* out = (float*)d_out;

    float *p_y, *p_state, *p_bufB, *p_agg;
    __half *p_acolh, *p_xh, *p_einh, *p_bufh, *p_ninh, *p_wts;
    cudaGetSymbolAddress((void**)&p_acolh, g_acolh);
    cudaGetSymbolAddress((void**)&p_y,     g_y);
    cudaGetSymbolAddress((void**)&p_xh,    g_xh);
    cudaGetSymbolAddress((void**)&p_state, g_state);
    cudaGetSymbolAddress((void**)&p_einh,  g_einh);
    cudaGetSymbolAddress((void**)&p_bufh,  g_bufh);
    cudaGetSymbolAddress((void**)&p_bufB,  g_bufB);
    cudaGetSymbolAddress((void**)&p_agg,   g_agg);
    cudaGetSymbolAddress((void**)&p_ninh,  g_ninh);
    cudaGetSymbolAddress((void**)&p_wts,   g_wtsh);

    const int SMEM256 = 2 * 128 * 40 * 2 + 2 * 256 * 40 * 2;   // 61440
    const int SMEM128 = 2 * 128 * 40 * 2 + 2 * 128 * 40 * 2;   // 40960
    cudaFuncSetAttribute(mma_gemm<256>, cudaFuncAttributeMaxDynamicSharedMemorySize, SMEM256);
    cudaFuncSetAttribute(mma_gemm<128>, cudaFuncAttributeMaxDynamicSharedMemorySize, SMEM128);

    // --- weight prep (transpose + K-pad + fp16 convert) ---
    padcopy_h_kernel<<<(512 * K_CONVP + 255) / 256, 256>>>(conv1_w, p_wts + OFF_C1, 512, K_CONV, K_CONVP);
    transpose_pad_h_kernel<<<(512 * 32 + 255) / 256, 256>>>(enc_w1, p_wts + OFF_E1, 512, FEAT, FEATP);
    transpose_pad_h_kernel<<<(512 * 512 + 255) / 256, 256>>>(enc_w2, p_wts + OFF_E2, 512, 512, 512);
    transpose_pad_h_kernel<<<(128 * 512 + 255) / 256, 256>>>(enc_w3, p_wts + OFF_E3, 128, 512, 512);
    transpose_pad_h_kernel<<<(512 * 256 + 255) / 256, 256>>>(edge_w1, p_wts + OFF_G1, 512, 256, 256);
    transpose_pad_h_kernel<<<(512 * 512 + 255) / 256, 256>>>(edge_w2, p_wts + OFF_G2, 512, 512, 512);
    transpose_pad_h_kernel<<<(512 * 512 + 255) / 256, 256>>>(edge_w3, p_wts + OFF_G3, 512, 512, 512);
    transpose_pad_h_kernel<<<(512 * NODE_INP + 255) / 256, 256>>>(node_w1, p_wts + OFF_N1, 512, NODE_IN, NODE_INP);
    transpose_pad_h_kernel<<<(512 * 512 + 255) / 256, 256>>>(node_w2, p_wts + OFF_N2, 512, 512, 512);
    transpose_pad_h_kernel<<<(128 * 512 + 255) / 256, 256>>>(node_w3, p_wts + OFF_N3, 128, 512, 512);

    // --- conv1 as GEMM (fp16 A, fp32 C for BN) ---
    im2col_kernel<<<(unsigned)(((size_t)M_CONV * K_CONVP + 255) / 256), 256>>>(obs);
    mma_gemm<256><<<dim3(2, M_CONV / 128), 256, SMEM256>>>(
        p_acolh, K_CONVP, p_wts + OFF_C1, conv1_b, nullptr, p_y, 512, K_CONVP, 0, 0, 0);

    // --- BN + conv2 + sigmoid ---
    bn_stats1_kernel<<<400, 512>>>();
    bn_stats2_kernel<<<1, 512>>>(bn1_g, bn1_b);
    conv2_sigmoid_kernel<<<M_CONV / 8, 256>>>(conv2_w, conv2_b);
    pad_x_kernel<<<(M_OBJ * (FEATP - FEAT) + 255) / 256, 256>>>();

    // --- encoder MLP: 32 -> 512 -> 512(LN) -> 128 ---
    mma_gemm<256><<<dim3(2, M_OBJ / 128), 256, SMEM256>>>(
        p_xh, FEATP, p_wts + OFF_E1, enc_b1, nullptr, p_bufh, 512, FEATP, 1, 0, 1);
    mma_gemm<256><<<dim3(2, M_OBJ / 128), 256, SMEM256>>>(
        p_bufh, 512, p_wts + OFF_E2, enc_b2, nullptr, p_bufB, 512, 512, 0, 0, 0);
    ln_relu_kernel<<<M_OBJ, 256>>>(p_bufB, p_bufh, enc_lng, enc_lnb);
    mma_gemm<128><<<dim3(1, M_OBJ / 128), 128, SMEM128>>>(
        p_bufh, 512, p_wts + OFF_E3, enc_b3, nullptr, p_state, 128, 512, 0, 0, 0);

    // --- edge MLP: gather -> 256 -> 512 -> 512(LN) -> 512(+agg fused) ---
    gather_ein_kernel<<<(unsigned)(((size_t)M_EDGE * 256 + 255) / 256), 256>>>();
    mma_gemm<256><<<dim3(2, M_EDGE / 128), 256, SMEM256>>>(
        p_einh, 256, p_wts + OFF_G1, edge_b1, nullptr, p_bufh, 512, 256, 1, 0, 1);
    mma_gemm<256><<<dim3(2, M_EDGE / 128), 256, SMEM256>>>(
        p_bufh, 512, p_wts + OFF_G2, edge_b2, nullptr, p_bufB, 512, 512, 0, 0, 0);
    ln_relu_kernel<<<M_EDGE, 256>>>(p_bufB, p_bufh, edge_lng, edge_lnb);
    mma_gemm<256><<<dim3(2, M_EDGE / 128), 256, SMEM256>>>(
        p_bufh, 512, p_wts + OFF_G3, edge_b3, nullptr, p_agg, 512, 512, 0, 1, 0);

    // --- node input assembly ---
    node_in_kernel<<<(unsigned)(((size_t)M_OBJ * NODE_INP + 255) / 256), 256>>>(action);

    // --- node MLP: 672 -> 512 -> 512(LN) -> 128, residual add state ---
    mma_gemm<256><<<dim3(2, M_OBJ / 128), 256, SMEM256>>>(
        p_ninh, NODE_INP, p_wts + OFF_N1, node_b1, nullptr, p_bufh, 512, NODE_INP, 1, 0, 1);
    mma_gemm<256><<<dim3(2, M_OBJ / 128), 256, SMEM256>>>(
        p_bufh, 512, p_wts + OFF_N2, node_b2, nullptr, p_bufB, 512, 512, 0, 0, 0);
    ln_relu_kernel<<<M_OBJ, 256>>>(p_bufB, p_bufh, node_lng, node_lnb);
    mma_gemm<128><<<dim3(1, M_OBJ / 128), 128, SMEM128>>>(
        p_bufh, 512, p_wts + OFF_N3, node_b3, p_state, out, 128, 512, 0, 0, 0);
}

// round 12
// speedup vs baseline: 3.6186x; 1.0445x over previous
#include <cuda_runtime.h>
#include <cuda_fp16.h>
#include <stdint.h>
#include <math.h>

// ---------------------------------------------------------------------------
// Problem constants
// ---------------------------------------------------------------------------
#define BB      4096
#define KOBJ    5
#define EMB     128
#define HID     512
#define ADIM    4
#define FEAT    25
#define EPS_F   1e-5f

#define M_CONV  (BB * 25)          // 102400
#define K_CONV  300
#define K_CONVP 320
#define M_OBJ   (BB * KOBJ)        // 20480
#define M_EDGE  (BB * 20)          // 81920
#define FEATP   32
#define NPROJ   1536               // [edge_w1a | edge_w1b | node_w1_state]

// ---------------------------------------------------------------------------
// Scratch (device globals)
// ---------------------------------------------------------------------------
static __device__ __half g_acolh[(size_t)M_CONV * K_CONVP];
static __device__ float  g_y[(size_t)M_CONV * HID];
static __device__ float  g_part[2 * 512 * 800];              // BN col partials (s, ss)
static __device__ float  g_scale[HID];
static __device__ float  g_shift[HID];
static __device__ __half g_xh[(size_t)M_OBJ * FEATP];
static __device__ float  g_state[(size_t)M_OBJ * EMB];
static __device__ __half g_stateh[(size_t)M_OBJ * EMB];
static __device__ float  g_proj[(size_t)M_OBJ * NPROJ];      // state @ Wcat (fp32)
static __device__ __half g_bufh[(size_t)M_EDGE * HID];
static __device__ float  g_bufB[(size_t)M_EDGE * HID];
static __device__ __half g_aggh[(size_t)M_OBJ * HID];
static __device__ __half g_wtsh[1835008];
static __device__ float  g_zerobias[NPROJ];                  // zero-init, never written

#define OFF_C1  0         // 512x320
#define OFF_E1  163840    // 512x32
#define OFF_E2  180224    // 512x512
#define OFF_E3  442368    // 128x512
#define OFF_CAT 507904    // 1536x128
#define OFF_G2  704512    // 512x512
#define OFF_G3  966656    // 512x512
#define OFF_N1G 1228800   // 512x512 (agg part of node_w1)
#define OFF_N2  1490944   // 512x512
#define OFF_N3  1753088   // 128x512

// ---------------------------------------------------------------------------
// Helpers
// ---------------------------------------------------------------------------
#define CP_ASYNC16(dst, src) \
    asm volatile("cp.async.cg.shared.global [%0], [%1], 16;" :: "r"(dst), "l"(src))
#define CP_COMMIT() asm volatile("cp.async.commit_group;" ::: "memory")
#define CP_WAIT0()  asm volatile("cp.async.wait_group 0;" ::: "memory")

#define LDSM_X4(r, addr)                                                      \
    asm volatile("ldmatrix.sync.aligned.m8n8.x4.shared.b16 {%0,%1,%2,%3}, [%4];" \
        : "=r"((r)[0]), "=r"((r)[1]), "=r"((r)[2]), "=r"((r)[3]) : "r"(addr))

// ---------------------------------------------------------------------------
// fp16 mma.sync GEMM. Modes:
//  0: fp32 out Cv (+half copy to C2 if non-null), bias(+relu)(+resid)
//  1: half out C2 only
//  2: agg: sum groups of 4 rows -> half C2, M/4 rows
//  3: fp32 out Cv + fused per-CTA BN column partials (to 'extraF')
//  4: node1: half out C2; adds bias + projR row (stride NPROJ) + action row
// ---------------------------------------------------------------------------
template<int BN>
__global__ void __launch_bounds__(BN == 256 ? 256 : 128, 1)
mma_gemm(const __half* __restrict__ A, int lda,
         const __half* __restrict__ Bt,
         const float* __restrict__ bias, const float* __restrict__ resid,
         float* __restrict__ Cv, __half* __restrict__ C2,
         int N, int K, int doRelu, int mode,
         float* __restrict__ extraF, const float* __restrict__ wact,
         const int* __restrict__ action)
{
    constexpr int T     = (BN == 256) ? 256 : 128;
    constexpr int AELEB = 128 * 40 * 2;
    constexpr int BELEB = BN * 40 * 2;
    extern __shared__ char smraw[];

    const int tid  = threadIdx.x;
    const int warp = tid >> 5, lane = tid & 31;
    const int bm = blockIdx.y * 128;
    const int bn = blockIdx.x * BN;
    const int warpM = warp & 1;
    const int warpN = warp >> 1;
    const int g = lane >> 2;
    const int t = lane & 3;

    uint32_t sbase;
    asm("{ .reg .u64 u; cvta.to.shared.u64 u, %1; cvt.u32.u64 %0, u; }"
        : "=r"(sbase) : "l"(smraw));
    const uint32_t sA = sbase;
    const uint32_t sB = sbase + 2 * AELEB;

    const __half* Abase = A  + (size_t)bm * lda;
    const __half* Bbase = Bt + (size_t)bn * K;
    const int KT = K / 32;

    float acc[4][8][4];
#pragma unroll
    for (int mi = 0; mi < 4; ++mi)
#pragma unroll
        for (int nj = 0; nj < 8; ++nj)
#pragma unroll
            for (int q = 0; q < 4; ++q) acc[mi][nj][q] = 0.f;

    auto load_tile = [&](int kt) {
        const int buf = kt & 1;
        const int k0 = kt * 32;
        uint32_t da = sA + (uint32_t)(buf * AELEB);
#pragma unroll
        for (int i = 0; i < 512 / T; ++i) {
            int id = tid + T * i;
            int r = id >> 2, c = id & 3;
            CP_ASYNC16(da + (uint32_t)(r * 40 + c * 8) * 2u,
                       Abase + (size_t)r * lda + k0 + c * 8);
        }
        uint32_t db = sB + (uint32_t)(buf * BELEB);
#pragma unroll
        for (int i = 0; i < (BN * 4) / T; ++i) {
            int id = tid + T * i;
            int r = id >> 2, c = id & 3;
            CP_ASYNC16(db + (uint32_t)(r * 40 + c * 8) * 2u,
                       Bbase + (size_t)r * K + k0 + c * 8);
        }
        CP_COMMIT();
    };

    const uint32_t aAddr0 = sA + (uint32_t)(((warpM * 64 + (lane & 15)) * 40
                                             + (lane >> 4) * 8) * 2);
    const uint32_t bAddr0 = sB + (uint32_t)(((warpN * 64 + (lane & 15)) * 40
                                             + (lane >> 4) * 8) * 2);

    load_tile(0);

    for (int kt = 0; kt < KT; ++kt) {
        CP_WAIT0();
        __syncthreads();
        if (kt + 1 < KT) load_tile(kt + 1);

        const uint32_t abuf = aAddr0 + (kt & 1) * AELEB;
        const uint32_t bbuf = bAddr0 + (kt & 1) * BELEB;

#pragma unroll
        for (int ks = 0; ks < 2; ++ks) {
            const uint32_t kofs = ks * 32;
            uint32_t a[4][4], b[4][4];
#pragma unroll
            for (int mi = 0; mi < 4; ++mi)
                LDSM_X4(a[mi], abuf + mi * 1280 + kofs);
#pragma unroll
            for (int njp = 0; njp < 4; ++njp)
                LDSM_X4(b[njp], bbuf + njp * 1280 + kofs);
#pragma unroll
            for (int mi = 0; mi < 4; ++mi)
#pragma unroll
                for (int nj = 0; nj < 8; ++nj) {
                    const uint32_t b0 = (nj & 1) ? b[nj >> 1][1] : b[nj >> 1][0];
                    const uint32_t b1 = (nj & 1) ? b[nj >> 1][3] : b[nj >> 1][2];
                    asm volatile(
                        "mma.sync.aligned.m16n8k16.row.col.f32.f16.f16.f32 "
                        "{%0,%1,%2,%3}, {%4,%5,%6,%7}, {%8,%9}, {%0,%1,%2,%3};"
                        : "+f"(acc[mi][nj][0]), "+f"(acc[mi][nj][1]),
                          "+f"(acc[mi][nj][2]), "+f"(acc[mi][nj][3])
                        : "r"(a[mi][0]), "r"(a[mi][1]), "r"(a[mi][2]), "r"(a[mi][3]),
                          "r"(b0), "r"(b1));
                }
        }
    }

    __syncthreads();   // protect smem reuse (BN staging) + uniform exit of mainloop

    if (mode == 2) {
        // sum groups of 4 consecutive rows -> half C2 (M/4 rows)
#pragma unroll
        for (int mi = 0; mi < 4; ++mi) {
            const int base = bm + warpM * 64 + mi * 16;
#pragma unroll
            for (int nj = 0; nj < 8; ++nj) {
                const int col = bn + warpN * 64 + nj * 8 + t * 2;
                const float bz0 = bias[col], bz1 = bias[col + 1];
                float v00 = acc[mi][nj][0] + bz0, v01 = acc[mi][nj][1] + bz1;
                float v10 = acc[mi][nj][2] + bz0, v11 = acc[mi][nj][3] + bz1;
#pragma unroll
                for (int o = 4; o <= 8; o <<= 1) {
                    v00 += __shfl_xor_sync(0xffffffffu, v00, o);
                    v01 += __shfl_xor_sync(0xffffffffu, v01, o);
                    v10 += __shfl_xor_sync(0xffffffffu, v10, o);
                    v11 += __shfl_xor_sync(0xffffffffu, v11, o);
                }
                if ((lane & 12) == 0) {
                    const int gblk = lane >> 4;
                    const int r0 = (base >> 2) + gblk;
                    *(__half2*)(C2 + (size_t)r0 * N + col)       = __floats2half2_rn(v00, v01);
                    *(__half2*)(C2 + (size_t)(r0 + 2) * N + col) = __floats2half2_rn(v10, v11);
                }
            }
        }
    } else if (mode == 4) {
        // node1: bias + proj row + action row, relu, half out
#pragma unroll
        for (int mi = 0; mi < 4; ++mi) {
            const int rA = bm + warpM * 64 + mi * 16 + g;
            const int rB = rA + 8;
            const int bA = rA / KOBJ, kA = rA % KOBJ;
            const int bB = rB / KOBJ, kB = rB % KOBJ;
            const int aA = action[bA] - kA * ADIM;
            const int aB = action[bB] - kB * ADIM;
            const float* prA = extraF + (size_t)rA * NPROJ;
            const float* prB = extraF + (size_t)rB * NPROJ;
            const float* waA = (aA >= 0 && aA < ADIM) ? wact + (size_t)aA * HID : nullptr;
            const float* waB = (aB >= 0 && aB < ADIM) ? wact + (size_t)aB * HID : nullptr;
#pragma unroll
            for (int nj = 0; nj < 8; ++nj) {
                const int col = bn + warpN * 64 + nj * 8 + t * 2;
                float v00 = acc[mi][nj][0] + bias[col]     + prA[col];
                float v01 = acc[mi][nj][1] + bias[col + 1] + prA[col + 1];
                float v10 = acc[mi][nj][2] + bias[col]     + prB[col];
                float v11 = acc[mi][nj][3] + bias[col + 1] + prB[col + 1];
                if (waA) { v00 += waA[col]; v01 += waA[col + 1]; }
                if (waB) { v10 += waB[col]; v11 += waB[col + 1]; }
                v00 = fmaxf(v00, 0.f); v01 = fmaxf(v01, 0.f);
                v10 = fmaxf(v10, 0.f); v11 = fmaxf(v11, 0.f);
                *(__half2*)(C2 + (size_t)rA * N + col) = __floats2half2_rn(v00, v01);
                *(__half2*)(C2 + (size_t)rB * N + col) = __floats2half2_rn(v10, v11);
            }
        }
    } else {
        float rs[8][2], rq[8][2];
        if (mode == 3) {
#pragma unroll
            for (int nj = 0; nj < 8; ++nj) {
                rs[nj][0] = rs[nj][1] = 0.f;
                rq[nj][0] = rq[nj][1] = 0.f;
            }
        }
#pragma unroll
        for (int mi = 0; mi < 4; ++mi) {
            const int r0 = bm + warpM * 64 + mi * 16 + g;
#pragma unroll
            for (int nj = 0; nj < 8; ++nj) {
                const int col = bn + warpN * 64 + nj * 8 + t * 2;
                const float bz0 = bias[col], bz1 = bias[col + 1];
                float v00 = acc[mi][nj][0] + bz0, v01 = acc[mi][nj][1] + bz1;
                float v10 = acc[mi][nj][2] + bz0, v11 = acc[mi][nj][3] + bz1;
                if (doRelu) {
                    v00 = fmaxf(v00, 0.f); v01 = fmaxf(v01, 0.f);
                    v10 = fmaxf(v10, 0.f); v11 = fmaxf(v11, 0.f);
                }
                if (resid) {
                    const float* rp0 = resid + (size_t)r0 * N + col;
                    const float* rp1 = resid + (size_t)(r0 + 8) * N + col;
                    v00 += rp0[0]; v01 += rp0[1];
                    v10 += rp1[0]; v11 += rp1[1];
                }
                if (mode == 1) {
                    *(__half2*)(C2 + (size_t)r0 * N + col)       = __floats2half2_rn(v00, v01);
                    *(__half2*)(C2 + (size_t)(r0 + 8) * N + col) = __floats2half2_rn(v10, v11);
                } else {
                    *(float2*)(Cv + (size_t)r0 * N + col)       = make_float2(v00, v01);
                    *(float2*)(Cv + (size_t)(r0 + 8) * N + col) = make_float2(v10, v11);
                    if (mode == 0 && C2) {
                        *(__half2*)(C2 + (size_t)r0 * N + col)       = __floats2half2_rn(v00, v01);
                        *(__half2*)(C2 + (size_t)(r0 + 8) * N + col) = __floats2half2_rn(v10, v11);
                    }
                    if (mode == 3) {
                        rs[nj][0] += v00 + v10;          rs[nj][1] += v01 + v11;
                        rq[nj][0] += v00 * v00 + v10 * v10;
                        rq[nj][1] += v01 * v01 + v11 * v11;
                    }
                }
            }
        }
        if (mode == 3) {
            // reduce over g (8 lanes) via xor-shfl
#pragma unroll
            for (int nj = 0; nj < 8; ++nj)
#pragma unroll
                for (int q = 0; q < 2; ++q) {
#pragma unroll
                    for (int o = 4; o <= 16; o <<= 1) {
                        rs[nj][q] += __shfl_xor_sync(0xffffffffu, rs[nj][q], o);
                        rq[nj][q] += __shfl_xor_sync(0xffffffffu, rq[nj][q], o);
                    }
                }
            float* sS = (float*)smraw;          // [256]
            float* sQ = sS + 256;               // [256]
            if (warpM == 0 && lane < 4) {
#pragma unroll
                for (int nj = 0; nj < 8; ++nj) {
                    int c = warpN * 64 + nj * 8 + lane * 2;
                    sS[c] = rs[nj][0]; sS[c + 1] = rs[nj][1];
                    sQ[c] = rq[nj][0]; sQ[c + 1] = rq[nj][1];
                }
            }
            __syncthreads();
            if (warpM == 1 && lane < 4) {
                const int yb = blockIdx.y;
#pragma unroll
                for (int nj = 0; nj < 8; ++nj) {
                    int c = warpN * 64 + nj * 8 + lane * 2;
                    extraF[(size_t)(bn + c) * 800 + yb]     = rs[nj][0] + sS[c];
                    extraF[(size_t)(bn + c + 1) * 800 + yb] = rs[nj][1] + sS[c + 1];
                    extraF[409600 + (size_t)(bn + c) * 800 + yb]     = rq[nj][0] + sQ[c];
                    extraF[409600 + (size_t)(bn + c + 1) * 800 + yb] = rq[nj][1] + sQ[c + 1];
                }
            }
        }
    }
}

// ---------------------------------------------------------------------------
// im2col (stride==kernel==10), K padded 300 -> 320, fp16 out
// ---------------------------------------------------------------------------
__global__ void im2col_kernel(const float* __restrict__ obs) {
    size_t idx = (size_t)blockIdx.x * 256 + threadIdx.x;
    if (idx >= (size_t)M_CONV * K_CONVP) return;
    int m  = (int)(idx / K_CONVP);
    int kk = (int)(idx % K_CONVP);
    float v = 0.f;
    if (kk < K_CONV) {
        int b = m / 25, p = m % 25;
        int py = p / 5, px = p % 5;
        int c = kk / 100, rr = kk % 100;
        int ky = rr / 10, kx = rr % 10;
        v = obs[((size_t)(b * 3 + c) * 50 + py * 10 + ky) * 50 + px * 10 + kx];
    }
    g_acolh[idx] = __float2half(v);
}

__global__ void padcopy_h_kernel(const float* __restrict__ w, __half* __restrict__ dst,
                                 int N, int K, int Kp) {
    int idx = blockIdx.x * 256 + threadIdx.x;
    if (idx >= N * Kp) return;
    int n = idx / Kp, k = idx % Kp;
    dst[idx] = (k < K) ? __float2half(w[n * K + k]) : __half(0.f);
}

__global__ void transpose_pad_h_kernel(const float* __restrict__ w, __half* __restrict__ dst,
                                       int N, int K, int Kp) {
    int idx = blockIdx.x * 256 + threadIdx.x;
    if (idx >= N * Kp) return;
    int n = idx / Kp, k = idx % Kp;
    dst[idx] = (k < K) ? __float2half(w[k * N + n]) : __half(0.f);
}

// Wcat[1536][128]: rows 0:512 = edge_w1 src part, 512:1024 = edge_w1 tgt part,
// 1024:1536 = node_w1 state part (all transposed to [n][k])
__global__ void wcat_kernel(const float* __restrict__ e1, const float* __restrict__ n1,
                            __half* __restrict__ dst) {
    int idx = blockIdx.x * 256 + threadIdx.x;
    if (idx >= NPROJ * 128) return;
    int n = idx / 128, k = idx % 128;
    float v;
    if (n < 512)       v = e1[(size_t)k * 512 + n];
    else if (n < 1024) v = e1[(size_t)(128 + k) * 512 + (n - 512)];
    else               v = n1[(size_t)k * 512 + (n - 1024)];
    dst[idx] = __float2half(v);
}

// ---------------------------------------------------------------------------
// BN stage 2: reduce 800 partials per column, produce scale/shift
// ---------------------------------------------------------------------------
__global__ void bn_stats2_kernel(const float* __restrict__ gamma,
                                 const float* __restrict__ beta) {
    __shared__ float sm[64];
    const int c = blockIdx.x, tid = threadIdx.x;
    float s = 0.f, q = 0.f;
    for (int i = tid; i < 800; i += 256) {
        s += g_part[(size_t)c * 800 + i];
        q += g_part[409600 + (size_t)c * 800 + i];
    }
#pragma unroll
    for (int o = 16; o > 0; o >>= 1) {
        s += __shfl_down_sync(0xffffffffu, s, o);
        q += __shfl_down_sync(0xffffffffu, q, o);
    }
    if ((tid & 31) == 0) { sm[tid >> 5] = s; sm[8 + (tid >> 5)] = q; }
    __syncthreads();
    if (tid == 0) {
        float ts = 0.f, tq = 0.f;
#pragma unroll
        for (int i = 0; i < 8; ++i) { ts += sm[i]; tq += sm[8 + i]; }
        const float inv_n = 1.f / (float)M_CONV;
        float mu  = ts * inv_n;
        float var = tq * inv_n - mu * mu;
        float sc = gamma[c] * rsqrtf(var + EPS_F);
        g_scale[c] = sc;
        g_shift[c] = beta[c] - mu * sc;
    }
}

// ---------------------------------------------------------------------------
// BN normalize + relu + conv2(1x1) + sigmoid -> g_xh
// ---------------------------------------------------------------------------
__global__ void conv2_sigmoid_kernel(const float* __restrict__ w2,
                                     const float* __restrict__ b2) {
    __shared__ float ws[5 * HID];
    __shared__ float bs[5];
    int tid = threadIdx.x;
    for (int i = tid; i < 5 * HID; i += 256) ws[i] = w2[i];
    if (tid < 5) bs[tid] = b2[tid];
    __syncthreads();

    int warp = tid >> 5, lane = tid & 31;
    size_t m = (size_t)blockIdx.x * 8 + warp;
    const float* y = g_y + m * HID;
    float a0 = 0.f, a1 = 0.f, a2 = 0.f, a3 = 0.f, a4 = 0.f;
#pragma unroll
    for (int i = 0; i < 16; ++i) {
        int c = lane + 32 * i;
        float h = fmaxf(fmaf(y[c], g_scale[c], g_shift[c]), 0.f);
        a0 = fmaf(h, ws[c],           a0);
        a1 = fmaf(h, ws[HID + c],     a1);
        a2 = fmaf(h, ws[2 * HID + c], a2);
        a3 = fmaf(h, ws[3 * HID + c], a3);
        a4 = fmaf(h, ws[4 * HID + c], a4);
    }
#pragma unroll
    for (int o = 16; o > 0; o >>= 1) {
        a0 += __shfl_down_sync(0xffffffffu, a0, o);
        a1 += __shfl_down_sync(0xffffffffu, a1, o);
        a2 += __shfl_down_sync(0xffffffffu, a2, o);
        a3 += __shfl_down_sync(0xffffffffu, a3, o);
        a4 += __shfl_down_sync(0xffffffffu, a4, o);
    }
    if (lane == 0) {
        int b = (int)(m / 25), f = (int)(m % 25);
        __half* xb = g_xh + (size_t)b * 5 * FEATP + f;
        xb[0 * FEATP] = __float2half(1.f / (1.f + expf(-(a0 + bs[0]))));
        xb[1 * FEATP] = __float2half(1.f / (1.f + expf(-(a1 + bs[1]))));
        xb[2 * FEATP] = __float2half(1.f / (1.f + expf(-(a2 + bs[2]))));
        xb[3 * FEATP] = __float2half(1.f / (1.f + expf(-(a3 + bs[3]))));
        xb[4 * FEATP] = __float2half(1.f / (1.f + expf(-(a4 + bs[4]))));
    }
}

__global__ void pad_x_kernel() {
    int idx = blockIdx.x * 256 + threadIdx.x;
    if (idx >= M_OBJ * (FEATP - FEAT)) return;
    int row = idx / (FEATP - FEAT), j = FEAT + idx % (FEATP - FEAT);
    g_xh[(size_t)row * FEATP + j] = __half(0.f);
}

// ---------------------------------------------------------------------------
// LayerNorm(512) + ReLU: fp32 in, fp16 out
// ---------------------------------------------------------------------------
__global__ void ln_relu_kernel(const float* __restrict__ Hin,
                               __half* __restrict__ Hout,
                               const float* __restrict__ g,
                               const float* __restrict__ b) {
    __shared__ float sh[8];
    const float* h = Hin + (size_t)blockIdx.x * HID;
    __half* ho = Hout + (size_t)blockIdx.x * HID;
    int tid = threadIdx.x, lane = tid & 31, w = tid >> 5;

    float x0 = h[tid], x1 = h[tid + 256];
    float s = x0 + x1;
#pragma unroll
    for (int o = 16; o > 0; o >>= 1) s += __shfl_down_sync(0xffffffffu, s, o);
    if (lane == 0) sh[w] = s;
    __syncthreads();
    if (tid == 0) {
        float tt = 0.f;
#pragma unroll
        for (int i = 0; i < 8; ++i) tt += sh[i];
        sh[0] = tt;
    }
    __syncthreads();
    float mean = sh[0] * (1.f / (float)HID);
    __syncthreads();

    float d0 = x0 - mean, d1 = x1 - mean;
    float ss = d0 * d0 + d1 * d1;
#pragma unroll
    for (int o = 16; o > 0; o >>= 1) ss += __shfl_down_sync(0xffffffffu, ss, o);
    if (lane == 0) sh[w] = ss;
    __syncthreads();
    if (tid == 0) {
        float tt = 0.f;
#pragma unroll
        for (int i = 0; i < 8; ++i) tt += sh[i];
        sh[0] = tt;
    }
    __syncthreads();
    float inv = rsqrtf(sh[0] * (1.f / (float)HID) + EPS_F);

    ho[tid]       = __float2half(fmaxf(fmaf(d0 * inv, g[tid],       b[tid]),       0.f));
    ho[tid + 256] = __float2half(fmaxf(fmaf(d1 * inv, g[tid + 256], b[tid + 256]), 0.f));
}

// ---------------------------------------------------------------------------
// edge1 combine: relu(P[b,i] + Q[b,tgt] + bias) -> half, 2 cols/thread
// P = proj cols [0,512), Q = proj cols [512,1024)
// ---------------------------------------------------------------------------
__global__ void edge1_combine_kernel(const float* __restrict__ b1) {
    size_t idx = (size_t)blockIdx.x * 256 + threadIdx.x;
    if (idx >= (size_t)M_EDGE * 256) return;
    int r = (int)(idx >> 8);
    int c = (int)(idx & 255) * 2;
    int b = r / 20, p = r % 20;
    int i = p >> 2, t = p & 3;
    int tgt = t + (t >= i ? 1 : 0);
    const float* P = g_proj + ((size_t)b * KOBJ + i)   * NPROJ + c;
    const float* Q = g_proj + ((size_t)b * KOBJ + tgt) * NPROJ + 512 + c;
    float v0 = fmaxf(P[0] + Q[0] + b1[c],     0.f);
    float v1 = fmaxf(P[1] + Q[1] + b1[c + 1], 0.f);
    *(__half2*)(g_bufh + (size_t)r * HID + c) = __floats2half2_rn(v0, v1);
}

// ---------------------------------------------------------------------------
// Launch
// ---------------------------------------------------------------------------
extern "C" void kernel_launch(void* const* d_in, const int* in_sizes, int n_in,
                              void* d_out, int out_size) {
    const float* obs     = (const float*)d_in[0];
    const int*   action  = (const int*)d_in[1];
    const float* conv1_w = (const float*)d_in[2];
    const float* conv1_b = (const float*)d_in[3];
    const float* bn1_g   = (const float*)d_in[4];
    const float* bn1_b   = (const float*)d_in[5];
    const float* conv2_w = (const float*)d_in[6];
    const float* conv2_b = (const float*)d_in[7];
    const float* enc_w1  = (const float*)d_in[8];
    const float* enc_b1  = (const float*)d_in[9];
    const float* enc_w2  = (const float*)d_in[10];
    const float* enc_b2  = (const float*)d_in[11];
    const float* enc_lng = (const float*)d_in[12];
    const float* enc_lnb = (const float*)d_in[13];
    const float* enc_w3  = (const float*)d_in[14];
    const float* enc_b3  = (const float*)d_in[15];
    const float* edge_w1 = (const float*)d_in[16];
    const float* edge_b1 = (const float*)d_in[17];
    const float* edge_w2 = (const float*)d_in[18];
    const float* edge_b2 = (const float*)d_in[19];
    const float* edge_lng= (const float*)d_in[20];
    const float* edge_lnb= (const float*)d_in[21];
    const float* edge_w3 = (const float*)d_in[22];
    const float* edge_b3 = (const float*)d_in[23];
    const float* node_w1 = (const float*)d_in[24];
    const float* node_b1 = (const float*)d_in[25];
    const float* node_w2 = (const float*)d_in[26];
    const float* node_b2 = (const float*)d_in[27];
    const float* node_lng= (const float*)d_in[28];
    const float* node_lnb= (const float*)d_in[29];
    const float* node_w3 = (const float*)d_in[30];
    const float* node_b3 = (const float*)d_in[31];
    float* out = (float*)d_out;

    float *p_y, *p_state, *p_bufB, *p_proj, *p_part, *p_zero;
    __half *p_acolh, *p_xh, *p_stateh, *p_bufh, *p_aggh, *p_wts;
    cudaGetSymbolAddress((void**)&p_acolh,  g_acolh);
    cudaGetSymbolAddress((void**)&p_y,      g_y);
    cudaGetSymbolAddress((void**)&p_xh,     g_xh);
    cudaGetSymbolAddress((void**)&p_state,  g_state);
    cudaGetSymbolAddress((void**)&p_stateh, g_stateh);
    cudaGetSymbolAddress((void**)&p_proj,   g_proj);
    cudaGetSymbolAddress((void**)&p_part,   g_part);
    cudaGetSymbolAddress((void**)&p_zero,   g_zerobias);
    cudaGetSymbolAddress((void**)&p_bufh,   g_bufh);
    cudaGetSymbolAddress((void**)&p_bufB,   g_bufB);
    cudaGetSymbolAddress((void**)&p_aggh,   g_aggh);
    cudaGetSymbolAddress((void**)&p_wts,    g_wtsh);

    const int SMEM256 = 2 * 128 * 40 * 2 + 2 * 256 * 40 * 2;   // 61440
    const int SMEM128 = 2 * 128 * 40 * 2 + 2 * 128 * 40 * 2;   // 40960
    cudaFuncSetAttribute(mma_gemm<256>, cudaFuncAttributeMaxDynamicSharedMemorySize, SMEM256);
    cudaFuncSetAttribute(mma_gemm<128>, cudaFuncAttributeMaxDynamicSharedMemorySize, SMEM128);

    // --- weight prep ---
    padcopy_h_kernel<<<(512 * K_CONVP + 255) / 256, 256>>>(conv1_w, p_wts + OFF_C1, 512, K_CONV, K_CONVP);
    transpose_pad_h_kernel<<<(512 * 32 + 255) / 256, 256>>>(enc_w1, p_wts + OFF_E1, 512, FEAT, FEATP);
    transpose_pad_h_kernel<<<(512 * 512 + 255) / 256, 256>>>(enc_w2, p_wts + OFF_E2, 512, 512, 512);
    transpose_pad_h_kernel<<<(128 * 512 + 255) / 256, 256>>>(enc_w3, p_wts + OFF_E3, 128, 512, 512);
    wcat_kernel<<<(NPROJ * 128 + 255) / 256, 256>>>(edge_w1, node_w1, p_wts + OFF_CAT);
    transpose_pad_h_kernel<<<(512 * 512 + 255) / 256, 256>>>(edge_w2, p_wts + OFF_G2, 512, 512, 512);
    transpose_pad_h_kernel<<<(512 * 512 + 255) / 256, 256>>>(edge_w3, p_wts + OFF_G3, 512, 512, 512);
    transpose_pad_h_kernel<<<(512 * 512 + 255) / 256, 256>>>(node_w1 + 132 * 512, p_wts + OFF_N1G, 512, 512, 512);
    transpose_pad_h_kernel<<<(512 * 512 + 255) / 256, 256>>>(node_w2, p_wts + OFF_N2, 512, 512, 512);
    transpose_pad_h_kernel<<<(128 * 512 + 255) / 256, 256>>>(node_w3, p_wts + OFF_N3, 128, 512, 512);

    // --- conv1 GEMM with fused BN partials (mode 3) ---
    im2col_kernel<<<(unsigned)(((size_t)M_CONV * K_CONVP + 255) / 256), 256>>>(obs);
    mma_gemm<256><<<dim3(2, M_CONV / 128), 256, SMEM256>>>(
        p_acolh, K_CONVP, p_wts + OFF_C1, conv1_b, nullptr, p_y, nullptr,
        512, K_CONVP, 0, 3, p_part, nullptr, nullptr);

    // --- BN finalize + conv2 + sigmoid ---
    bn_stats2_kernel<<<512, 256>>>(bn1_g, bn1_b);
    conv2_sigmoid_kernel<<<M_CONV / 8, 256>>>(conv2_w, conv2_b);
    pad_x_kernel<<<(M_OBJ * (FEATP - FEAT) + 255) / 256, 256>>>();

    // --- encoder MLP: 32 -> 512 -> 512(LN) -> 128 (state fp32 + fp16) ---
    mma_gemm<256><<<dim3(2, M_OBJ / 128), 256, SMEM256>>>(
        p_xh, FEATP, p_wts + OFF_E1, enc_b1, nullptr, nullptr, p_bufh,
        512, FEATP, 1, 1, nullptr, nullptr, nullptr);
    mma_gemm<256><<<dim3(2, M_OBJ / 128), 256, SMEM256>>>(
        p_bufh, 512, p_wts + OFF_E2, enc_b2, nullptr, p_bufB, nullptr,
        512, 512, 0, 0, nullptr, nullptr, nullptr);
    ln_relu_kernel<<<M_OBJ, 256>>>(p_bufB, p_bufh, enc_lng, enc_lnb);
    mma_gemm<128><<<dim3(1, M_OBJ / 128), 128, SMEM128>>>(
        p_bufh, 512, p_wts + OFF_E3, enc_b3, nullptr, p_state, p_stateh,
        128, 512, 0, 0, nullptr, nullptr, nullptr);

    // --- projection GEMM: state @ [e1a | e1b | n1s]  (K=128, N=1536) ---
    mma_gemm<256><<<dim3(NPROJ / 256, M_OBJ / 128), 256, SMEM256>>>(
        p_stateh, 128, p_wts + OFF_CAT, p_zero, nullptr, p_proj, nullptr,
        NPROJ, 128, 0, 0, nullptr, nullptr, nullptr);

    // --- edge MLP: combine -> 512 -> 512(LN) -> 512(+agg fused, half) ---
    edge1_combine_kernel<<<(unsigned)(((size_t)M_EDGE * 256 + 255) / 256), 256>>>(edge_b1);
    mma_gemm<256><<<dim3(2, M_EDGE / 128), 256, SMEM256>>>(
        p_bufh, 512, p_wts + OFF_G2, edge_b2, nullptr, p_bufB, nullptr,
        512, 512, 0, 0, nullptr, nullptr, nullptr);
    ln_relu_kernel<<<M_EDGE, 256>>>(p_bufB, p_bufh, edge_lng, edge_lnb);
    mma_gemm<256><<<dim3(2, M_EDGE / 128), 256, SMEM256>>>(
        p_bufh, 512, p_wts + OFF_G3, edge_b3, nullptr, nullptr, p_aggh,
        512, 512, 0, 2, nullptr, nullptr, nullptr);

    // --- node MLP: agg-GEMM(+proj/action epilogue) -> 512(LN) -> 128 + resid ---
    mma_gemm<256><<<dim3(2, M_OBJ / 128), 256, SMEM256>>>(
        p_aggh, 512, p_wts + OFF_N1G, node_b1, nullptr, nullptr, p_bufh,
        512, 512, 1, 4, p_proj + 1024, node_w1 + 128 * 512, action);
    mma_gemm<256><<<dim3(2, M_OBJ / 128), 256, SMEM256>>>(
        p_bufh, 512, p_wts + OFF_N2, node_b2, nullptr, p_bufB, nullptr,
        512, 512, 0, 0, nullptr, nullptr, nullptr);
    ln_relu_kernel<<<M_OBJ, 256>>>(p_bufB, p_bufh, node_lng, node_lnb);
    mma_gemm<128><<<dim3(1, M_OBJ / 128), 128, SMEM128>>>(
        p_bufh, 512, p_wts + OFF_N3, node_b3, p_state, out, nullptr,
        128, 512, 0, 0, nullptr, nullptr, nullptr);
}

// round 15
// speedup vs baseline: 3.9762x; 1.0988x over previous
#include <cuda_runtime.h>
#include <cuda_fp16.h>
#include <stdint.h>
#include <math.h>

// ---------------------------------------------------------------------------
// Problem constants
// ---------------------------------------------------------------------------
#define BB      4096
#define KOBJ    5
#define EMB     128
#define HID     512
#define ADIM    4
#define FEAT    25
#define EPS_F   1e-5f

#define M_CONV  (BB * 25)          // 102400
#define K_CONV  300
#define K_CONVP 320
#define M_OBJ   (BB * KOBJ)        // 20480
#define M_EDGE  (BB * 20)          // 81920
#define FEATP   32
#define NPROJ   1536               // [edge_w1a | edge_w1b | node_w1_state]

// ---------------------------------------------------------------------------
// Scratch (device globals)
// ---------------------------------------------------------------------------
static __device__ __half g_acolh[(size_t)M_CONV * K_CONVP];
static __device__ float  g_y[(size_t)M_CONV * HID];
static __device__ float  g_part[2 * 512 * 800];              // BN col partials
static __device__ float  g_scale[HID];
static __device__ float  g_shift[HID];
static __device__ __half g_xh[(size_t)M_OBJ * FEATP];
static __device__ float  g_state[(size_t)M_OBJ * EMB];
static __device__ __half g_stateh[(size_t)M_OBJ * EMB];
static __device__ float  g_proj[(size_t)M_OBJ * NPROJ];
static __device__ __half g_bufh[(size_t)M_EDGE * HID];
static __device__ __half g_aggh[(size_t)M_OBJ * HID];
static __device__ __half g_wtsh[1835008];
static __device__ float  g_zerobias[NPROJ];                  // zero-init

#define OFF_C1  0         // 512x320
#define OFF_E1  163840    // 512x32
#define OFF_E2  180224    // 512x512
#define OFF_E3  442368    // 128x512
#define OFF_CAT 507904    // 1536x128
#define OFF_G2  704512    // 512x512
#define OFF_G3  966656    // 512x512
#define OFF_N1G 1228800   // 512x512 (agg part of node_w1)
#define OFF_N2  1490944   // 512x512
#define OFF_N3  1753088   // 128x512

// ---------------------------------------------------------------------------
// Helpers
// ---------------------------------------------------------------------------
#define CP_ASYNC16(dst, src) \
    asm volatile("cp.async.cg.shared.global [%0], [%1], 16;" :: "r"(dst), "l"(src))
#define CP_COMMIT() asm volatile("cp.async.commit_group;" ::: "memory")
#define CP_WAIT0()  asm volatile("cp.async.wait_group 0;" ::: "memory")

#define LDSM_X4(r, addr)                                                      \
    asm volatile("ldmatrix.sync.aligned.m8n8.x4.shared.b16 {%0,%1,%2,%3}, [%4];" \
        : "=r"((r)[0]), "=r"((r)[1]), "=r"((r)[2]), "=r"((r)[3]) : "r"(addr))

#define MMA16816(acc, a, b0, b1)                                              \
    asm volatile(                                                             \
        "mma.sync.aligned.m16n8k16.row.col.f32.f16.f16.f32 "                  \
        "{%0,%1,%2,%3}, {%4,%5,%6,%7}, {%8,%9}, {%0,%1,%2,%3};"               \
        : "+f"((acc)[0]), "+f"((acc)[1]), "+f"((acc)[2]), "+f"((acc)[3])      \
        : "r"((a)[0]), "r"((a)[1]), "r"((a)[2]), "r"((a)[3]), "r"(b0), "r"(b1))

// ---------------------------------------------------------------------------
// fp16 mma.sync GEMM (BM=128). Modes:
//  0: fp32 out Cv (+half copy to C2 if non-null), bias(+relu)(+resid)
//  1: half out C2 only
//  2: agg: sum groups of 4 rows -> half C2, M/4 rows
//  3: fp32 out Cv + fused per-CTA BN column partials (to 'extraF')
//  4: node1: half out C2; adds bias + projR row (stride NPROJ) + action row
// ---------------------------------------------------------------------------
template<int BN>
__global__ void __launch_bounds__(BN == 256 ? 256 : 128, 1)
mma_gemm(const __half* __restrict__ A, int lda,
         const __half* __restrict__ Bt,
         const float* __restrict__ bias, const float* __restrict__ resid,
         float* __restrict__ Cv, __half* __restrict__ C2,
         int N, int K, int doRelu, int mode,
         float* __restrict__ extraF, const float* __restrict__ wact,
         const int* __restrict__ action)
{
    constexpr int T     = (BN == 256) ? 256 : 128;
    constexpr int AELEB = 128 * 40 * 2;
    constexpr int BELEB = BN * 40 * 2;
    extern __shared__ char smraw[];

    const int tid  = threadIdx.x;
    const int warp = tid >> 5, lane = tid & 31;
    const int bm = blockIdx.y * 128;
    const int bn = blockIdx.x * BN;
    const int warpM = warp & 1;
    const int warpN = warp >> 1;
    const int g = lane >> 2;
    const int t = lane & 3;

    uint32_t sbase;
    asm("{ .reg .u64 u; cvta.to.shared.u64 u, %1; cvt.u32.u64 %0, u; }"
        : "=r"(sbase) : "l"(smraw));
    const uint32_t sA = sbase;
    const uint32_t sB = sbase + 2 * AELEB;

    const __half* Abase = A  + (size_t)bm * lda;
    const __half* Bbase = Bt + (size_t)bn * K;
    const int KT = K / 32;

    float acc[4][8][4];
#pragma unroll
    for (int mi = 0; mi < 4; ++mi)
#pragma unroll
        for (int nj = 0; nj < 8; ++nj)
#pragma unroll
            for (int q = 0; q < 4; ++q) acc[mi][nj][q] = 0.f;

    auto load_tile = [&](int kt) {
        const int buf = kt & 1;
        const int k0 = kt * 32;
        uint32_t da = sA + (uint32_t)(buf * AELEB);
#pragma unroll
        for (int i = 0; i < 512 / T; ++i) {
            int id = tid + T * i;
            int r = id >> 2, c = id & 3;
            CP_ASYNC16(da + (uint32_t)(r * 40 + c * 8) * 2u,
                       Abase + (size_t)r * lda + k0 + c * 8);
        }
        uint32_t db = sB + (uint32_t)(buf * BELEB);
#pragma unroll
        for (int i = 0; i < (BN * 4) / T; ++i) {
            int id = tid + T * i;
            int r = id >> 2, c = id & 3;
            CP_ASYNC16(db + (uint32_t)(r * 40 + c * 8) * 2u,
                       Bbase + (size_t)r * K + k0 + c * 8);
        }
        CP_COMMIT();
    };

    const uint32_t aAddr0 = sA + (uint32_t)(((warpM * 64 + (lane & 15)) * 40
                                             + (lane >> 4) * 8) * 2);
    const uint32_t bAddr0 = sB + (uint32_t)(((warpN * 64 + (lane & 15)) * 40
                                             + (lane >> 4) * 8) * 2);

    load_tile(0);

    for (int kt = 0; kt < KT; ++kt) {
        CP_WAIT0();
        __syncthreads();
        if (kt + 1 < KT) load_tile(kt + 1);

        const uint32_t abuf = aAddr0 + (kt & 1) * AELEB;
        const uint32_t bbuf = bAddr0 + (kt & 1) * BELEB;

#pragma unroll
        for (int ks = 0; ks < 2; ++ks) {
            const uint32_t kofs = ks * 32;
            uint32_t a[4][4], b[4][4];
#pragma unroll
            for (int mi = 0; mi < 4; ++mi)
                LDSM_X4(a[mi], abuf + mi * 1280 + kofs);
#pragma unroll
            for (int njp = 0; njp < 4; ++njp)
                LDSM_X4(b[njp], bbuf + njp * 1280 + kofs);
#pragma unroll
            for (int mi = 0; mi < 4; ++mi)
#pragma unroll
                for (int nj = 0; nj < 8; ++nj) {
                    const uint32_t b0 = (nj & 1) ? b[nj >> 1][1] : b[nj >> 1][0];
                    const uint32_t b1 = (nj & 1) ? b[nj >> 1][3] : b[nj >> 1][2];
                    MMA16816(acc[mi][nj], a[mi], b0, b1);
                }
        }
    }

    __syncthreads();

    if (mode == 2) {
#pragma unroll
        for (int mi = 0; mi < 4; ++mi) {
            const int base = bm + warpM * 64 + mi * 16;
#pragma unroll
            for (int nj = 0; nj < 8; ++nj) {
                const int col = bn + warpN * 64 + nj * 8 + t * 2;
                const float bz0 = bias[col], bz1 = bias[col + 1];
                float v00 = acc[mi][nj][0] + bz0, v01 = acc[mi][nj][1] + bz1;
                float v10 = acc[mi][nj][2] + bz0, v11 = acc[mi][nj][3] + bz1;
#pragma unroll
                for (int o = 4; o <= 8; o <<= 1) {
                    v00 += __shfl_xor_sync(0xffffffffu, v00, o);
                    v01 += __shfl_xor_sync(0xffffffffu, v01, o);
                    v10 += __shfl_xor_sync(0xffffffffu, v10, o);
                    v11 += __shfl_xor_sync(0xffffffffu, v11, o);
                }
                if ((lane & 12) == 0) {
                    const int gblk = lane >> 4;
                    const int r0 = (base >> 2) + gblk;
                    *(__half2*)(C2 + (size_t)r0 * N + col)       = __floats2half2_rn(v00, v01);
                    *(__half2*)(C2 + (size_t)(r0 + 2) * N + col) = __floats2half2_rn(v10, v11);
                }
            }
        }
    } else if (mode == 4) {
#pragma unroll
        for (int mi = 0; mi < 4; ++mi) {
            const int rA = bm + warpM * 64 + mi * 16 + g;
            const int rB = rA + 8;
            const int bA = rA / KOBJ, kA = rA % KOBJ;
            const int bB = rB / KOBJ, kB = rB % KOBJ;
            const int aA = action[bA] - kA * ADIM;
            const int aB = action[bB] - kB * ADIM;
            const float* prA = extraF + (size_t)rA * NPROJ;
            const float* prB = extraF + (size_t)rB * NPROJ;
            const float* waA = (aA >= 0 && aA < ADIM) ? wact + (size_t)aA * HID : nullptr;
            const float* waB = (aB >= 0 && aB < ADIM) ? wact + (size_t)aB * HID : nullptr;
#pragma unroll
            for (int nj = 0; nj < 8; ++nj) {
                const int col = bn + warpN * 64 + nj * 8 + t * 2;
                float v00 = acc[mi][nj][0] + bias[col]     + prA[col];
                float v01 = acc[mi][nj][1] + bias[col + 1] + prA[col + 1];
                float v10 = acc[mi][nj][2] + bias[col]     + prB[col];
                float v11 = acc[mi][nj][3] + bias[col + 1] + prB[col + 1];
                if (waA) { v00 += waA[col]; v01 += waA[col + 1]; }
                if (waB) { v10 += waB[col]; v11 += waB[col + 1]; }
                v00 = fmaxf(v00, 0.f); v01 = fmaxf(v01, 0.f);
                v10 = fmaxf(v10, 0.f); v11 = fmaxf(v11, 0.f);
                *(__half2*)(C2 + (size_t)rA * N + col) = __floats2half2_rn(v00, v01);
                *(__half2*)(C2 + (size_t)rB * N + col) = __floats2half2_rn(v10, v11);
            }
        }
    } else {
        float rs[8][2], rq[8][2];
        if (mode == 3) {
#pragma unroll
            for (int nj = 0; nj < 8; ++nj) {
                rs[nj][0] = rs[nj][1] = 0.f;
                rq[nj][0] = rq[nj][1] = 0.f;
            }
        }
#pragma unroll
        for (int mi = 0; mi < 4; ++mi) {
            const int r0 = bm + warpM * 64 + mi * 16 + g;
#pragma unroll
            for (int nj = 0; nj < 8; ++nj) {
                const int col = bn + warpN * 64 + nj * 8 + t * 2;
                const float bz0 = bias[col], bz1 = bias[col + 1];
                float v00 = acc[mi][nj][0] + bz0, v01 = acc[mi][nj][1] + bz1;
                float v10 = acc[mi][nj][2] + bz0, v11 = acc[mi][nj][3] + bz1;
                if (doRelu) {
                    v00 = fmaxf(v00, 0.f); v01 = fmaxf(v01, 0.f);
                    v10 = fmaxf(v10, 0.f); v11 = fmaxf(v11, 0.f);
                }
                if (resid) {
                    const float* rp0 = resid + (size_t)r0 * N + col;
                    const float* rp1 = resid + (size_t)(r0 + 8) * N + col;
                    v00 += rp0[0]; v01 += rp0[1];
                    v10 += rp1[0]; v11 += rp1[1];
                }
                if (mode == 1) {
                    *(__half2*)(C2 + (size_t)r0 * N + col)       = __floats2half2_rn(v00, v01);
                    *(__half2*)(C2 + (size_t)(r0 + 8) * N + col) = __floats2half2_rn(v10, v11);
                } else {
                    *(float2*)(Cv + (size_t)r0 * N + col)       = make_float2(v00, v01);
                    *(float2*)(Cv + (size_t)(r0 + 8) * N + col) = make_float2(v10, v11);
                    if (mode == 0 && C2) {
                        *(__half2*)(C2 + (size_t)r0 * N + col)       = __floats2half2_rn(v00, v01);
                        *(__half2*)(C2 + (size_t)(r0 + 8) * N + col) = __floats2half2_rn(v10, v11);
                    }
                    if (mode == 3) {
                        rs[nj][0] += v00 + v10;          rs[nj][1] += v01 + v11;
                        rq[nj][0] += v00 * v00 + v10 * v10;
                        rq[nj][1] += v01 * v01 + v11 * v11;
                    }
                }
            }
        }
        if (mode == 3) {
#pragma unroll
            for (int nj = 0; nj < 8; ++nj)
#pragma unroll
                for (int q = 0; q < 2; ++q) {
#pragma unroll
                    for (int o = 4; o <= 16; o <<= 1) {
                        rs[nj][q] += __shfl_xor_sync(0xffffffffu, rs[nj][q], o);
                        rq[nj][q] += __shfl_xor_sync(0xffffffffu, rq[nj][q], o);
                    }
                }
            float* sS = (float*)smraw;
            float* sQ = sS + 256;
            if (warpM == 0 && lane < 4) {
#pragma unroll
                for (int nj = 0; nj < 8; ++nj) {
                    int c = warpN * 64 + nj * 8 + lane * 2;
                    sS[c] = rs[nj][0]; sS[c + 1] = rs[nj][1];
                    sQ[c] = rq[nj][0]; sQ[c + 1] = rq[nj][1];
                }
            }
            __syncthreads();
            if (warpM == 1 && lane < 4) {
                const int yb = blockIdx.y;
#pragma unroll
                for (int nj = 0; nj < 8; ++nj) {
                    int c = warpN * 64 + nj * 8 + lane * 2;
                    extraF[(size_t)(bn + c) * 800 + yb]     = rs[nj][0] + sS[c];
                    extraF[(size_t)(bn + c + 1) * 800 + yb] = rs[nj][1] + sS[c + 1];
                    extraF[409600 + (size_t)(bn + c) * 800 + yb]     = rq[nj][0] + sQ[c];
                    extraF[409600 + (size_t)(bn + c + 1) * 800 + yb] = rq[nj][1] + sQ[c + 1];
                }
            }
        }
    }
}

// ---------------------------------------------------------------------------
// Fused GEMM + LayerNorm + ReLU, N=512 (full row per CTA).
// BM=64, 512 threads (16 warps), warp tile 64x32. A and C in-place safe
// (each CTA reads exactly its own 64-row block, writes after mainloop).
// C = half( relu( LN(A@Bt^T + bias) * lng + lnb ) )
// ---------------------------------------------------------------------------
__global__ void __launch_bounds__(512, 1)
mma_gemm_ln(const __half* __restrict__ A,
            const __half* __restrict__ Bt,
            const float* __restrict__ bias,
            const float* __restrict__ lng, const float* __restrict__ lnb,
            __half* __restrict__ C2, int K)
{
    constexpr int AELEB = 64 * 40 * 2;      // 5120 B per A buffer
    constexpr int BELEB = 512 * 40 * 2;     // 40960 B per B buffer
    extern __shared__ char smraw[];

    const int tid = threadIdx.x;
    const int warp = tid >> 5, lane = tid & 31;
    const int bm = blockIdx.x * 64;
    const int g = lane >> 2, t = lane & 3;

    uint32_t sbase;
    asm("{ .reg .u64 u; cvta.to.shared.u64 u, %1; cvt.u32.u64 %0, u; }"
        : "=r"(sbase) : "l"(smraw));
    const uint32_t sA = sbase;
    const uint32_t sB = sbase + 2 * AELEB;

    const __half* Abase = A + (size_t)bm * K;
    const int KT = K / 32;

    float acc[4][4][4];
#pragma unroll
    for (int mi = 0; mi < 4; ++mi)
#pragma unroll
        for (int nj = 0; nj < 4; ++nj)
#pragma unroll
            for (int q = 0; q < 4; ++q) acc[mi][nj][q] = 0.f;

    auto load_tile = [&](int kt) {
        const int buf = kt & 1;
        const int k0 = kt * 32;
        if (tid < 256) {
            int r = tid >> 2, c = tid & 3;
            CP_ASYNC16(sA + (uint32_t)(buf * AELEB) + (uint32_t)(r * 40 + c * 8) * 2u,
                       Abase + (size_t)r * K + k0 + c * 8);
        }
        uint32_t db = sB + (uint32_t)(buf * BELEB);
#pragma unroll
        for (int i = 0; i < 4; ++i) {
            int id = tid + 512 * i;
            int r = id >> 2, c = id & 3;
            CP_ASYNC16(db + (uint32_t)(r * 40 + c * 8) * 2u,
                       Bt + (size_t)r * K + k0 + c * 8);
        }
        CP_COMMIT();
    };

    const uint32_t aAddr0 = sA + (uint32_t)(((lane & 15) * 40 + (lane >> 4) * 8) * 2);
    const uint32_t bAddr0 = sB + (uint32_t)(((warp * 32 + (lane & 15)) * 40
                                             + (lane >> 4) * 8) * 2);

    load_tile(0);

    for (int kt = 0; kt < KT; ++kt) {
        CP_WAIT0();
        __syncthreads();
        if (kt + 1 < KT) load_tile(kt + 1);

        const uint32_t abuf = aAddr0 + (kt & 1) * AELEB;
        const uint32_t bbuf = bAddr0 + (kt & 1) * BELEB;

#pragma unroll
        for (int ks = 0; ks < 2; ++ks) {
            const uint32_t kofs = ks * 32;
            uint32_t a[4][4], b[2][4];
#pragma unroll
            for (int mi = 0; mi < 4; ++mi)
                LDSM_X4(a[mi], abuf + mi * 1280 + kofs);
#pragma unroll
            for (int p = 0; p < 2; ++p)
                LDSM_X4(b[p], bbuf + p * 1280 + kofs);
#pragma unroll
            for (int mi = 0; mi < 4; ++mi)
#pragma unroll
                for (int nj = 0; nj < 4; ++nj) {
                    const uint32_t b0 = (nj & 1) ? b[nj >> 1][1] : b[nj >> 1][0];
                    const uint32_t b1 = (nj & 1) ? b[nj >> 1][3] : b[nj >> 1][2];
                    MMA16816(acc[mi][nj], a[mi], b0, b1);
                }
        }
    }

    __syncthreads();   // everyone done with smem tiles before stats reuse

    float* sS    = (float*)smraw;        // [64][17]
    float* sQ    = sS + 64 * 17;         // [64][17]
    float* rstat = sQ + 64 * 17;         // [64][2]

    // per-lane partial sums (bias added in place)
    float sums[4][2], sqs[4][2];
#pragma unroll
    for (int mi = 0; mi < 4; ++mi) {
        float sa = 0.f, qa = 0.f, sb = 0.f, qb = 0.f;
#pragma unroll
        for (int nj = 0; nj < 4; ++nj) {
            const int c = warp * 32 + nj * 8 + t * 2;
            const float b0 = bias[c], b1 = bias[c + 1];
            acc[mi][nj][0] += b0; acc[mi][nj][1] += b1;
            acc[mi][nj][2] += b0; acc[mi][nj][3] += b1;
            sa += acc[mi][nj][0] + acc[mi][nj][1];
            qa += acc[mi][nj][0] * acc[mi][nj][0] + acc[mi][nj][1] * acc[mi][nj][1];
            sb += acc[mi][nj][2] + acc[mi][nj][3];
            qb += acc[mi][nj][2] * acc[mi][nj][2] + acc[mi][nj][3] * acc[mi][nj][3];
        }
#pragma unroll
        for (int o = 1; o <= 2; o <<= 1) {
            sa += __shfl_xor_sync(0xffffffffu, sa, o);
            qa += __shfl_xor_sync(0xffffffffu, qa, o);
            sb += __shfl_xor_sync(0xffffffffu, sb, o);
            qb += __shfl_xor_sync(0xffffffffu, qb, o);
        }
        sums[mi][0] = sa; sums[mi][1] = sb;
        sqs[mi][0]  = qa; sqs[mi][1]  = qb;
    }
    if (t == 0) {
#pragma unroll
        for (int mi = 0; mi < 4; ++mi) {
            sS[(mi * 16 + g) * 17 + warp]     = sums[mi][0];
            sS[(mi * 16 + 8 + g) * 17 + warp] = sums[mi][1];
            sQ[(mi * 16 + g) * 17 + warp]     = sqs[mi][0];
            sQ[(mi * 16 + 8 + g) * 17 + warp] = sqs[mi][1];
        }
    }
    __syncthreads();
    if (tid < 64) {
        float s = 0.f, q = 0.f;
#pragma unroll
        for (int w = 0; w < 16; ++w) { s += sS[tid * 17 + w]; q += sQ[tid * 17 + w]; }
        float mean = s * (1.f / 512.f);
        float var  = q * (1.f / 512.f) - mean * mean;
        rstat[tid * 2]     = mean;
        rstat[tid * 2 + 1] = rsqrtf(var + EPS_F);
    }
    __syncthreads();

#pragma unroll
    for (int mi = 0; mi < 4; ++mi) {
        const int rA = mi * 16 + g, rB = rA + 8;
        const float mA = rstat[rA * 2], iA = rstat[rA * 2 + 1];
        const float mB = rstat[rB * 2], iB = rstat[rB * 2 + 1];
#pragma unroll
        for (int nj = 0; nj < 4; ++nj) {
            const int c = warp * 32 + nj * 8 + t * 2;
            const float ga = lng[c], gb = lng[c + 1];
            const float ba = lnb[c], bb = lnb[c + 1];
            float v00 = fmaxf(fmaf((acc[mi][nj][0] - mA) * iA, ga, ba), 0.f);
            float v01 = fmaxf(fmaf((acc[mi][nj][1] - mA) * iA, gb, bb), 0.f);
            float v10 = fmaxf(fmaf((acc[mi][nj][2] - mB) * iB, ga, ba), 0.f);
            float v11 = fmaxf(fmaf((acc[mi][nj][3] - mB) * iB, gb, bb), 0.f);
            *(__half2*)(C2 + (size_t)(bm + rA) * 512 + c) = __floats2half2_rn(v00, v01);
            *(__half2*)(C2 + (size_t)(bm + rB) * 512 + c) = __floats2half2_rn(v10, v11);
        }
    }
}

// ---------------------------------------------------------------------------
// Merged weight prep: all 10 segments in one launch
// ---------------------------------------------------------------------------
__global__ void prep_weights_kernel(
    const float* __restrict__ conv1_w, const float* __restrict__ enc_w1,
    const float* __restrict__ enc_w2,  const float* __restrict__ enc_w3,
    const float* __restrict__ edge_w1, const float* __restrict__ node_w1,
    const float* __restrict__ edge_w2, const float* __restrict__ edge_w3,
    const float* __restrict__ node_w2, const float* __restrict__ node_w3)
{
    int idx = blockIdx.x * 256 + threadIdx.x;
    if (idx >= 1835008) return;
    float v;
    if (idx < OFF_E1) {                       // conv1: padcopy [512][300]->[512][320]
        int n = idx / 320, k = idx % 320;
        v = (k < 300) ? conv1_w[n * 300 + k] : 0.f;
    } else if (idx < OFF_E2) {                // enc_w1: [25][512] -> [512][32]
        int j = idx - OFF_E1; int n = j >> 5, k = j & 31;
        v = (k < 25) ? enc_w1[k * 512 + n] : 0.f;
    } else if (idx < OFF_E3) {                // enc_w2 transpose
        int j = idx - OFF_E2; int n = j >> 9, k = j & 511;
        v = enc_w2[k * 512 + n];
    } else if (idx < OFF_CAT) {               // enc_w3: [512][128] -> [128][512]
        int j = idx - OFF_E3; int n = j >> 9, k = j & 511;
        v = enc_w3[k * 128 + n];
    } else if (idx < OFF_G2) {                // Wcat [1536][128]
        int j = idx - OFF_CAT; int n = j >> 7, k = j & 127;
        if (n < 512)       v = edge_w1[k * 512 + n];
        else if (n < 1024) v = edge_w1[(128 + k) * 512 + (n - 512)];
        else               v = node_w1[k * 512 + (n - 1024)];
    } else if (idx < OFF_G3) {                // edge_w2
        int j = idx - OFF_G2; int n = j >> 9, k = j & 511;
        v = edge_w2[k * 512 + n];
    } else if (idx < OFF_N1G) {               // edge_w3
        int j = idx - OFF_G3; int n = j >> 9, k = j & 511;
        v = edge_w3[k * 512 + n];
    } else if (idx < OFF_N2) {                // node_w1 agg part (rows 132..)
        int j = idx - OFF_N1G; int n = j >> 9, k = j & 511;
        v = node_w1[(132 + k) * 512 + n];
    } else if (idx < OFF_N3) {                // node_w2
        int j = idx - OFF_N2; int n = j >> 9, k = j & 511;
        v = node_w2[k * 512 + n];
    } else {                                  // node_w3: [512][128] -> [128][512]
        int j = idx - OFF_N3; int n = j >> 9, k = j & 511;
        v = node_w3[k * 128 + n];
    }
    g_wtsh[idx] = __float2half(v);
}

// ---------------------------------------------------------------------------
// im2col (stride==kernel==10), K padded 300 -> 320, fp16 out
// ---------------------------------------------------------------------------
__global__ void im2col_kernel(const float* __restrict__ obs) {
    size_t idx = (size_t)blockIdx.x * 256 + threadIdx.x;
    if (idx >= (size_t)M_CONV * K_CONVP) return;
    int m  = (int)(idx / K_CONVP);
    int kk = (int)(idx % K_CONVP);
    float v = 0.f;
    if (kk < K_CONV) {
        int b = m / 25, p = m % 25;
        int py = p / 5, px = p % 5;
        int c = kk / 100, rr = kk % 100;
        int ky = rr / 10, kx = rr % 10;
        v = obs[((size_t)(b * 3 + c) * 50 + py * 10 + ky) * 50 + px * 10 + kx];
    }
    g_acolh[idx] = __float2half(v);
}

// ---------------------------------------------------------------------------
// BN stage 2: reduce 800 partials per column, produce scale/shift
// ---------------------------------------------------------------------------
__global__ void bn_stats2_kernel(const float* __restrict__ gamma,
                                 const float* __restrict__ beta) {
    __shared__ float sm[64];
    const int c = blockIdx.x, tid = threadIdx.x;
    float s = 0.f, q = 0.f;
    for (int i = tid; i < 800; i += 256) {
        s += g_part[(size_t)c * 800 + i];
        q += g_part[409600 + (size_t)c * 800 + i];
    }
#pragma unroll
    for (int o = 16; o > 0; o >>= 1) {
        s += __shfl_down_sync(0xffffffffu, s, o);
        q += __shfl_down_sync(0xffffffffu, q, o);
    }
    if ((tid & 31) == 0) { sm[tid >> 5] = s; sm[8 + (tid >> 5)] = q; }
    __syncthreads();
    if (tid == 0) {
        float ts = 0.f, tq = 0.f;
#pragma unroll
        for (int i = 0; i < 8; ++i) { ts += sm[i]; tq += sm[8 + i]; }
        const float inv_n = 1.f / (float)M_CONV;
        float mu  = ts * inv_n;
        float var = tq * inv_n - mu * mu;
        float sc = gamma[c] * rsqrtf(var + EPS_F);
        g_scale[c] = sc;
        g_shift[c] = beta[c] - mu * sc;
    }
}

// ---------------------------------------------------------------------------
// BN normalize + relu + conv2(1x1) + sigmoid -> g_xh
// ---------------------------------------------------------------------------
__global__ void conv2_sigmoid_kernel(const float* __restrict__ w2,
                                     const float* __restrict__ b2) {
    __shared__ float ws[5 * HID];
    __shared__ float bs[5];
    int tid = threadIdx.x;
    for (int i = tid; i < 5 * HID; i += 256) ws[i] = w2[i];
    if (tid < 5) bs[tid] = b2[tid];
    __syncthreads();

    int warp = tid >> 5, lane = tid & 31;
    size_t m = (size_t)blockIdx.x * 8 + warp;
    const float* y = g_y + m * HID;
    float a0 = 0.f, a1 = 0.f, a2 = 0.f, a3 = 0.f, a4 = 0.f;
#pragma unroll
    for (int i = 0; i < 16; ++i) {
        int c = lane + 32 * i;
        float h = fmaxf(fmaf(y[c], g_scale[c], g_shift[c]), 0.f);
        a0 = fmaf(h, ws[c],           a0);
        a1 = fmaf(h, ws[HID + c],     a1);
        a2 = fmaf(h, ws[2 * HID + c], a2);
        a3 = fmaf(h, ws[3 * HID + c], a3);
        a4 = fmaf(h, ws[4 * HID + c], a4);
    }
#pragma unroll
    for (int o = 16; o > 0; o >>= 1) {
        a0 += __shfl_down_sync(0xffffffffu, a0, o);
        a1 += __shfl_down_sync(0xffffffffu, a1, o);
        a2 += __shfl_down_sync(0xffffffffu, a2, o);
        a3 += __shfl_down_sync(0xffffffffu, a3, o);
        a4 += __shfl_down_sync(0xffffffffu, a4, o);
    }
    if (lane == 0) {
        int b = (int)(m / 25), f = (int)(m % 25);
        __half* xb = g_xh + (size_t)b * 5 * FEATP + f;
        xb[0 * FEATP] = __float2half(1.f / (1.f + expf(-(a0 + bs[0]))));
        xb[1 * FEATP] = __float2half(1.f / (1.f + expf(-(a1 + bs[1]))));
        xb[2 * FEATP] = __float2half(1.f / (1.f + expf(-(a2 + bs[2]))));
        xb[3 * FEATP] = __float2half(1.f / (1.f + expf(-(a3 + bs[3]))));
        xb[4 * FEATP] = __float2half(1.f / (1.f + expf(-(a4 + bs[4]))));
    }
}

__global__ void pad_x_kernel() {
    int idx = blockIdx.x * 256 + threadIdx.x;
    if (idx >= M_OBJ * (FEATP - FEAT)) return;
    int row = idx / (FEATP - FEAT), j = FEAT + idx % (FEATP - FEAT);
    g_xh[(size_t)row * FEATP + j] = __half(0.f);
}

// ---------------------------------------------------------------------------
// edge1 combine: relu(P[b,i] + Q[b,tgt] + bias) -> half
// ---------------------------------------------------------------------------
__global__ void edge1_combine_kernel(const float* __restrict__ b1) {
    size_t idx = (size_t)blockIdx.x * 256 + threadIdx.x;
    if (idx >= (size_t)M_EDGE * 256) return;
    int r = (int)(idx >> 8);
    int c = (int)(idx & 255) * 2;
    int b = r / 20, p = r % 20;
    int i = p >> 2, t = p & 3;
    int tgt = t + (t >= i ? 1 : 0);
    const float* P = g_proj + ((size_t)b * KOBJ + i)   * NPROJ + c;
    const float* Q = g_proj + ((size_t)b * KOBJ + tgt) * NPROJ + 512 + c;
    float v0 = fmaxf(P[0] + Q[0] + b1[c],     0.f);
    float v1 = fmaxf(P[1] + Q[1] + b1[c + 1], 0.f);
    *(__half2*)(g_bufh + (size_t)r * HID + c) = __floats2half2_rn(v0, v1);
}

// ---------------------------------------------------------------------------
// Launch
// ---------------------------------------------------------------------------
extern "C" void kernel_launch(void* const* d_in, const int* in_sizes, int n_in,
                              void* d_out, int out_size) {
    const float* obs     = (const float*)d_in[0];
    const int*   action  = (const int*)d_in[1];
    const float* conv1_w = (const float*)d_in[2];
    const float* conv1_b = (const float*)d_in[3];
    const float* bn1_g   = (const float*)d_in[4];
    const float* bn1_b   = (const float*)d_in[5];
    const float* conv2_w = (const float*)d_in[6];
    const float* conv2_b = (const float*)d_in[7];
    const float* enc_w1  = (const float*)d_in[8];
    const float* enc_b1  = (const float*)d_in[9];
    const float* enc_w2  = (const float*)d_in[10];
    const float* enc_b2  = (const float*)d_in[11];
    const float* enc_lng = (const float*)d_in[12];
    const float* enc_lnb = (const float*)d_in[13];
    const float* enc_w3  = (const float*)d_in[14];
    const float* enc_b3  = (const float*)d_in[15];
    const float* edge_w1 = (const float*)d_in[16];
    const float* edge_b1 = (const float*)d_in[17];
    const float* edge_w2 = (const float*)d_in[18];
    const float* edge_b2 = (const float*)d_in[19];
    const float* edge_lng= (const float*)d_in[20];
    const float* edge_lnb= (const float*)d_in[21];
    const float* edge_w3 = (const float*)d_in[22];
    const float* edge_b3 = (const float*)d_in[23];
    const float* node_w1 = (const float*)d_in[24];
    const float* node_b1 = (const float*)d_in[25];
    const float* node_w2 = (const float*)d_in[26];
    const float* node_b2 = (const float*)d_in[27];
    const float* node_lng= (const float*)d_in[28];
    const float* node_lnb= (const float*)d_in[29];
    const float* node_w3 = (const float*)d_in[30];
    const float* node_b3 = (const float*)d_in[31];
    float* out = (float*)d_out;

    float *p_y, *p_state, *p_proj, *p_part, *p_zero;
    __half *p_acolh, *p_xh, *p_stateh, *p_bufh, *p_aggh, *p_wts;
    cudaGetSymbolAddress((void**)&p_acolh,  g_acolh);
    cudaGetSymbolAddress((void**)&p_y,      g_y);
    cudaGetSymbolAddress((void**)&p_xh,     g_xh);
    cudaGetSymbolAddress((void**)&p_state,  g_state);
    cudaGetSymbolAddress((void**)&p_stateh, g_stateh);
    cudaGetSymbolAddress((void**)&p_proj,   g_proj);
    cudaGetSymbolAddress((void**)&p_part,   g_part);
    cudaGetSymbolAddress((void**)&p_zero,   g_zerobias);
    cudaGetSymbolAddress((void**)&p_bufh,   g_bufh);
    cudaGetSymbolAddress((void**)&p_aggh,   g_aggh);
    cudaGetSymbolAddress((void**)&p_wts,    g_wtsh);

    const int SMEM256 = 2 * 128 * 40 * 2 + 2 * 256 * 40 * 2;   // 61440
    const int SMEM128 = 2 * 128 * 40 * 2 + 2 * 128 * 40 * 2;   // 40960
    const int SMEMLN  = 2 * 64 * 40 * 2 + 2 * 512 * 40 * 2;    // 92160
    cudaFuncSetAttribute(mma_gemm<256>, cudaFuncAttributeMaxDynamicSharedMemorySize, SMEM256);
    cudaFuncSetAttribute(mma_gemm<128>, cudaFuncAttributeMaxDynamicSharedMemorySize, SMEM128);
    cudaFuncSetAttribute(mma_gemm_ln,   cudaFuncAttributeMaxDynamicSharedMemorySize, SMEMLN);

    // --- weight prep (single launch) ---
    prep_weights_kernel<<<(1835008 + 255) / 256, 256>>>(
        conv1_w, enc_w1, enc_w2, enc_w3, edge_w1, node_w1,
        edge_w2, edge_w3, node_w2, node_w3);

    // --- conv1 GEMM with fused BN partials (mode 3) ---
    im2col_kernel<<<(unsigned)(((size_t)M_CONV * K_CONVP + 255) / 256), 256>>>(obs);
    mma_gemm<256><<<dim3(2, M_CONV / 128), 256, SMEM256>>>(
        p_acolh, K_CONVP, p_wts + OFF_C1, conv1_b, nullptr, p_y, nullptr,
        512, K_CONVP, 0, 3, p_part, nullptr, nullptr);

    // --- BN finalize + conv2 + sigmoid ---
    bn_stats2_kernel<<<512, 256>>>(bn1_g, bn1_b);
    conv2_sigmoid_kernel<<<M_CONV / 8, 256>>>(conv2_w, conv2_b);
    pad_x_kernel<<<(M_OBJ * (FEATP - FEAT) + 255) / 256, 256>>>();

    // --- encoder MLP: 32 -> 512 -> 512(LN fused) -> 128 ---
    mma_gemm<256><<<dim3(2, M_OBJ / 128), 256, SMEM256>>>(
        p_xh, FEATP, p_wts + OFF_E1, enc_b1, nullptr, nullptr, p_bufh,
        512, FEATP, 1, 1, nullptr, nullptr, nullptr);
    mma_gemm_ln<<<M_OBJ / 64, 512, SMEMLN>>>(
        p_bufh, p_wts + OFF_E2, enc_b2, enc_lng, enc_lnb, p_bufh, 512);
    mma_gemm<128><<<dim3(1, M_OBJ / 128), 128, SMEM128>>>(
        p_bufh, 512, p_wts + OFF_E3, enc_b3, nullptr, p_state, p_stateh,
        128, 512, 0, 0, nullptr, nullptr, nullptr);

    // --- projection GEMM: state @ [e1a | e1b | n1s]  (K=128, N=1536) ---
    mma_gemm<256><<<dim3(NPROJ / 256, M_OBJ / 128), 256, SMEM256>>>(
        p_stateh, 128, p_wts + OFF_CAT, p_zero, nullptr, p_proj, nullptr,
        NPROJ, 128, 0, 0, nullptr, nullptr, nullptr);

    // --- edge MLP: combine -> 512(LN fused) -> 512(+agg fused) ---
    edge1_combine_kernel<<<(unsigned)(((size_t)M_EDGE * 256 + 255) / 256), 256>>>(edge_b1);
    mma_gemm_ln<<<M_EDGE / 64, 512, SMEMLN>>>(
        p_bufh, p_wts + OFF_G2, edge_b2, edge_lng, edge_lnb, p_bufh, 512);
    mma_gemm<256><<<dim3(2, M_EDGE / 128), 256, SMEM256>>>(
        p_bufh, 512, p_wts + OFF_G3, edge_b3, nullptr, nullptr, p_aggh,
        512, 512, 0, 2, nullptr, nullptr, nullptr);

    // --- node MLP: agg-GEMM(+proj/action epilogue) -> 512(LN fused) -> 128 + resid ---
    mma_gemm<256><<<dim3(2, M_OBJ / 128), 256, SMEM256>>>(
        p_aggh, 512, p_wts + OFF_N1G, node_b1, nullptr, nullptr, p_bufh,
        512, 512, 1, 4, p_proj + 1024, node_w1 + 128 * 512, action);
    mma_gemm_ln<<<M_OBJ / 64, 512, SMEMLN>>>(
        p_bufh, p_wts + OFF_N2, node_b2, node_lng, node_lnb, p_bufh, 512);
    mma_gemm<128><<<dim3(1, M_OBJ / 128), 128, SMEM128>>>(
        p_bufh, 512, p_wts + OFF_N3, node_b3, p_state, out, nullptr,
        128, 512, 0, 0, nullptr, nullptr, nullptr);
}

// round 16
// speedup vs baseline: 4.1034x; 1.0320x over previous
#include <cuda_runtime.h>
#include <cuda_fp16.h>
#include <stdint.h>
#include <math.h>

// ---------------------------------------------------------------------------
// Problem constants
// ---------------------------------------------------------------------------
#define BB      4096
#define KOBJ    5
#define EMB     128
#define HID     512
#define ADIM    4
#define FEAT    25
#define EPS_F   1e-5f

#define M_CONV  (BB * 25)          // 102400
#define K_CONV  300
#define K_CONVP 320
#define M_OBJ   (BB * KOBJ)        // 20480
#define M_EDGE  (BB * 20)          // 81920
#define FEATP   32
#define NPROJ   1536               // [edge_w1a | edge_w1b | node_w1_state]

#define WTOT    1835008
#define PADX    (M_OBJ * (FEATP - FEAT))     // 143360
#define PREPTOT (WTOT + PADX)

// ---------------------------------------------------------------------------
// Scratch (device globals)
// ---------------------------------------------------------------------------
static __device__ __half g_acolh[(size_t)M_CONV * K_CONVP];
static __device__ __half g_yh[(size_t)M_CONV * HID];         // conv1 out (fp16)
static __device__ float  g_part[2 * 512 * 800];              // BN col partials
static __device__ float  g_scale[HID];
static __device__ float  g_shift[HID];
static __device__ __half g_xh[(size_t)M_OBJ * FEATP];
static __device__ float  g_state[(size_t)M_OBJ * EMB];
static __device__ __half g_stateh[(size_t)M_OBJ * EMB];
static __device__ __half g_projh[(size_t)M_OBJ * NPROJ];     // state @ Wcat (fp16)
static __device__ __half g_bufh[(size_t)M_EDGE * HID];
static __device__ __half g_aggh[(size_t)M_OBJ * HID];
static __device__ __half g_wtsh[WTOT];
static __device__ float  g_zerobias[NPROJ];                  // zero-init

#define OFF_C1  0         // 512x320
#define OFF_E1  163840    // 512x32
#define OFF_E2  180224    // 512x512
#define OFF_E3  442368    // 128x512
#define OFF_CAT 507904    // 1536x128
#define OFF_G2  704512    // 512x512
#define OFF_G3  966656    // 512x512
#define OFF_N1G 1228800   // 512x512 (agg part of node_w1)
#define OFF_N2  1490944   // 512x512
#define OFF_N3  1753088   // 128x512

// ---------------------------------------------------------------------------
// Helpers
// ---------------------------------------------------------------------------
#define CP_ASYNC16(dst, src) \
    asm volatile("cp.async.cg.shared.global [%0], [%1], 16;" :: "r"(dst), "l"(src))
#define CP_COMMIT() asm volatile("cp.async.commit_group;" ::: "memory")
#define CP_WAIT0()  asm volatile("cp.async.wait_group 0;" ::: "memory")

#define LDSM_X4(r, addr)                                                      \
    asm volatile("ldmatrix.sync.aligned.m8n8.x4.shared.b16 {%0,%1,%2,%3}, [%4];" \
        : "=r"((r)[0]), "=r"((r)[1]), "=r"((r)[2]), "=r"((r)[3]) : "r"(addr))

#define MMA16816(acc, a, b0, b1)                                              \
    asm volatile(                                                             \
        "mma.sync.aligned.m16n8k16.row.col.f32.f16.f16.f32 "                  \
        "{%0,%1,%2,%3}, {%4,%5,%6,%7}, {%8,%9}, {%0,%1,%2,%3};"               \
        : "+f"((acc)[0]), "+f"((acc)[1]), "+f"((acc)[2]), "+f"((acc)[3])      \
        : "r"((a)[0]), "r"((a)[1]), "r"((a)[2]), "r"((a)[3]), "r"(b0), "r"(b1))

// ---------------------------------------------------------------------------
// fp16 mma.sync GEMM (BM=128). Modes:
//  0: fp32 out Cv (+half copy to C2 if non-null), bias(+relu)(+resid)
//  1: half out C2 only
//  2: agg: sum groups of 4 rows -> half C2, M/4 rows
//  3: half out C2 + fused per-CTA BN column partials (fp32 accs -> extraP)
//  4: node1: half out C2; adds bias + half proj row (extraP, stride NPROJ)
//     + fp32 action row
// ---------------------------------------------------------------------------
template<int BN>
__global__ void __launch_bounds__(BN == 256 ? 256 : 128, 1)
mma_gemm(const __half* __restrict__ A, int lda,
         const __half* __restrict__ Bt,
         const float* __restrict__ bias, const float* __restrict__ resid,
         float* __restrict__ Cv, __half* __restrict__ C2,
         int N, int K, int doRelu, int mode,
         void* __restrict__ extraP, const float* __restrict__ wact,
         const int* __restrict__ action)
{
    constexpr int T     = (BN == 256) ? 256 : 128;
    constexpr int AELEB = 128 * 40 * 2;
    constexpr int BELEB = BN * 40 * 2;
    extern __shared__ char smraw[];

    const int tid  = threadIdx.x;
    const int warp = tid >> 5, lane = tid & 31;
    const int bm = blockIdx.y * 128;
    const int bn = blockIdx.x * BN;
    const int warpM = warp & 1;
    const int warpN = warp >> 1;
    const int g = lane >> 2;
    const int t = lane & 3;

    uint32_t sbase;
    asm("{ .reg .u64 u; cvta.to.shared.u64 u, %1; cvt.u32.u64 %0, u; }"
        : "=r"(sbase) : "l"(smraw));
    const uint32_t sA = sbase;
    const uint32_t sB = sbase + 2 * AELEB;

    const __half* Abase = A  + (size_t)bm * lda;
    const __half* Bbase = Bt + (size_t)bn * K;
    const int KT = K / 32;

    float acc[4][8][4];
#pragma unroll
    for (int mi = 0; mi < 4; ++mi)
#pragma unroll
        for (int nj = 0; nj < 8; ++nj)
#pragma unroll
            for (int q = 0; q < 4; ++q) acc[mi][nj][q] = 0.f;

    auto load_tile = [&](int kt) {
        const int buf = kt & 1;
        const int k0 = kt * 32;
        uint32_t da = sA + (uint32_t)(buf * AELEB);
#pragma unroll
        for (int i = 0; i < 512 / T; ++i) {
            int id = tid + T * i;
            int r = id >> 2, c = id & 3;
            CP_ASYNC16(da + (uint32_t)(r * 40 + c * 8) * 2u,
                       Abase + (size_t)r * lda + k0 + c * 8);
        }
        uint32_t db = sB + (uint32_t)(buf * BELEB);
#pragma unroll
        for (int i = 0; i < (BN * 4) / T; ++i) {
            int id = tid + T * i;
            int r = id >> 2, c = id & 3;
            CP_ASYNC16(db + (uint32_t)(r * 40 + c * 8) * 2u,
                       Bbase + (size_t)r * K + k0 + c * 8);
        }
        CP_COMMIT();
    };

    const uint32_t aAddr0 = sA + (uint32_t)(((warpM * 64 + (lane & 15)) * 40
                                             + (lane >> 4) * 8) * 2);
    const uint32_t bAddr0 = sB + (uint32_t)(((warpN * 64 + (lane & 15)) * 40
                                             + (lane >> 4) * 8) * 2);

    load_tile(0);

    for (int kt = 0; kt < KT; ++kt) {
        CP_WAIT0();
        __syncthreads();
        if (kt + 1 < KT) load_tile(kt + 1);

        const uint32_t abuf = aAddr0 + (kt & 1) * AELEB;
        const uint32_t bbuf = bAddr0 + (kt & 1) * BELEB;

#pragma unroll
        for (int ks = 0; ks < 2; ++ks) {
            const uint32_t kofs = ks * 32;
            uint32_t a[4][4], b[4][4];
#pragma unroll
            for (int mi = 0; mi < 4; ++mi)
                LDSM_X4(a[mi], abuf + mi * 1280 + kofs);
#pragma unroll
            for (int njp = 0; njp < 4; ++njp)
                LDSM_X4(b[njp], bbuf + njp * 1280 + kofs);
#pragma unroll
            for (int mi = 0; mi < 4; ++mi)
#pragma unroll
                for (int nj = 0; nj < 8; ++nj) {
                    const uint32_t b0 = (nj & 1) ? b[nj >> 1][1] : b[nj >> 1][0];
                    const uint32_t b1 = (nj & 1) ? b[nj >> 1][3] : b[nj >> 1][2];
                    MMA16816(acc[mi][nj], a[mi], b0, b1);
                }
        }
    }

    __syncthreads();

    if (mode == 2) {
#pragma unroll
        for (int mi = 0; mi < 4; ++mi) {
            const int base = bm + warpM * 64 + mi * 16;
#pragma unroll
            for (int nj = 0; nj < 8; ++nj) {
                const int col = bn + warpN * 64 + nj * 8 + t * 2;
                const float bz0 = bias[col], bz1 = bias[col + 1];
                float v00 = acc[mi][nj][0] + bz0, v01 = acc[mi][nj][1] + bz1;
                float v10 = acc[mi][nj][2] + bz0, v11 = acc[mi][nj][3] + bz1;
#pragma unroll
                for (int o = 4; o <= 8; o <<= 1) {
                    v00 += __shfl_xor_sync(0xffffffffu, v00, o);
                    v01 += __shfl_xor_sync(0xffffffffu, v01, o);
                    v10 += __shfl_xor_sync(0xffffffffu, v10, o);
                    v11 += __shfl_xor_sync(0xffffffffu, v11, o);
                }
                if ((lane & 12) == 0) {
                    const int gblk = lane >> 4;
                    const int r0 = (base >> 2) + gblk;
                    *(__half2*)(C2 + (size_t)r0 * N + col)       = __floats2half2_rn(v00, v01);
                    *(__half2*)(C2 + (size_t)(r0 + 2) * N + col) = __floats2half2_rn(v10, v11);
                }
            }
        }
    } else if (mode == 4) {
        const __half* projH = (const __half*)extraP;
#pragma unroll
        for (int mi = 0; mi < 4; ++mi) {
            const int rA = bm + warpM * 64 + mi * 16 + g;
            const int rB = rA + 8;
            const int bA = rA / KOBJ, kA = rA % KOBJ;
            const int bB = rB / KOBJ, kB = rB % KOBJ;
            const int aA = action[bA] - kA * ADIM;
            const int aB = action[bB] - kB * ADIM;
            const __half* prA = projH + (size_t)rA * NPROJ;
            const __half* prB = projH + (size_t)rB * NPROJ;
            const float* waA = (aA >= 0 && aA < ADIM) ? wact + (size_t)aA * HID : nullptr;
            const float* waB = (aB >= 0 && aB < ADIM) ? wact + (size_t)aB * HID : nullptr;
#pragma unroll
            for (int nj = 0; nj < 8; ++nj) {
                const int col = bn + warpN * 64 + nj * 8 + t * 2;
                float2 pA = __half22float2(*(const __half2*)(prA + col));
                float2 pB = __half22float2(*(const __half2*)(prB + col));
                float v00 = acc[mi][nj][0] + bias[col]     + pA.x;
                float v01 = acc[mi][nj][1] + bias[col + 1] + pA.y;
                float v10 = acc[mi][nj][2] + bias[col]     + pB.x;
                float v11 = acc[mi][nj][3] + bias[col + 1] + pB.y;
                if (waA) { v00 += waA[col]; v01 += waA[col + 1]; }
                if (waB) { v10 += waB[col]; v11 += waB[col + 1]; }
                v00 = fmaxf(v00, 0.f); v01 = fmaxf(v01, 0.f);
                v10 = fmaxf(v10, 0.f); v11 = fmaxf(v11, 0.f);
                *(__half2*)(C2 + (size_t)rA * N + col) = __floats2half2_rn(v00, v01);
                *(__half2*)(C2 + (size_t)rB * N + col) = __floats2half2_rn(v10, v11);
            }
        }
    } else {
        float rs[8][2], rq[8][2];
        if (mode == 3) {
#pragma unroll
            for (int nj = 0; nj < 8; ++nj) {
                rs[nj][0] = rs[nj][1] = 0.f;
                rq[nj][0] = rq[nj][1] = 0.f;
            }
        }
#pragma unroll
        for (int mi = 0; mi < 4; ++mi) {
            const int r0 = bm + warpM * 64 + mi * 16 + g;
#pragma unroll
            for (int nj = 0; nj < 8; ++nj) {
                const int col = bn + warpN * 64 + nj * 8 + t * 2;
                const float bz0 = bias[col], bz1 = bias[col + 1];
                float v00 = acc[mi][nj][0] + bz0, v01 = acc[mi][nj][1] + bz1;
                float v10 = acc[mi][nj][2] + bz0, v11 = acc[mi][nj][3] + bz1;
                if (doRelu) {
                    v00 = fmaxf(v00, 0.f); v01 = fmaxf(v01, 0.f);
                    v10 = fmaxf(v10, 0.f); v11 = fmaxf(v11, 0.f);
                }
                if (resid) {
                    const float* rp0 = resid + (size_t)r0 * N + col;
                    const float* rp1 = resid + (size_t)(r0 + 8) * N + col;
                    v00 += rp0[0]; v01 += rp0[1];
                    v10 += rp1[0]; v11 += rp1[1];
                }
                if (mode == 0) {
                    *(float2*)(Cv + (size_t)r0 * N + col)       = make_float2(v00, v01);
                    *(float2*)(Cv + (size_t)(r0 + 8) * N + col) = make_float2(v10, v11);
                    if (C2) {
                        *(__half2*)(C2 + (size_t)r0 * N + col)       = __floats2half2_rn(v00, v01);
                        *(__half2*)(C2 + (size_t)(r0 + 8) * N + col) = __floats2half2_rn(v10, v11);
                    }
                } else {   // mode 1 or 3: half out
                    *(__half2*)(C2 + (size_t)r0 * N + col)       = __floats2half2_rn(v00, v01);
                    *(__half2*)(C2 + (size_t)(r0 + 8) * N + col) = __floats2half2_rn(v10, v11);
                    if (mode == 3) {
                        rs[nj][0] += v00 + v10;          rs[nj][1] += v01 + v11;
                        rq[nj][0] += v00 * v00 + v10 * v10;
                        rq[nj][1] += v01 * v01 + v11 * v11;
                    }
                }
            }
        }
        if (mode == 3) {
            float* extraF = (float*)extraP;
#pragma unroll
            for (int nj = 0; nj < 8; ++nj)
#pragma unroll
                for (int q = 0; q < 2; ++q) {
#pragma unroll
                    for (int o = 4; o <= 16; o <<= 1) {
                        rs[nj][q] += __shfl_xor_sync(0xffffffffu, rs[nj][q], o);
                        rq[nj][q] += __shfl_xor_sync(0xffffffffu, rq[nj][q], o);
                    }
                }
            float* sS = (float*)smraw;
            float* sQ = sS + 256;
            if (warpM == 0 && lane < 4) {
#pragma unroll
                for (int nj = 0; nj < 8; ++nj) {
                    int c = warpN * 64 + nj * 8 + lane * 2;
                    sS[c] = rs[nj][0]; sS[c + 1] = rs[nj][1];
                    sQ[c] = rq[nj][0]; sQ[c + 1] = rq[nj][1];
                }
            }
            __syncthreads();
            if (warpM == 1 && lane < 4) {
                const int yb = blockIdx.y;
#pragma unroll
                for (int nj = 0; nj < 8; ++nj) {
                    int c = warpN * 64 + nj * 8 + lane * 2;
                    extraF[(size_t)(bn + c) * 800 + yb]     = rs[nj][0] + sS[c];
                    extraF[(size_t)(bn + c + 1) * 800 + yb] = rs[nj][1] + sS[c + 1];
                    extraF[409600 + (size_t)(bn + c) * 800 + yb]     = rq[nj][0] + sQ[c];
                    extraF[409600 + (size_t)(bn + c + 1) * 800 + yb] = rq[nj][1] + sQ[c + 1];
                }
            }
        }
    }
}

// ---------------------------------------------------------------------------
// Fused GEMM + LayerNorm + ReLU, N=512 (full row per CTA). BM=64, 512 thr.
// ---------------------------------------------------------------------------
__global__ void __launch_bounds__(512, 1)
mma_gemm_ln(const __half* __restrict__ A,
            const __half* __restrict__ Bt,
            const float* __restrict__ bias,
            const float* __restrict__ lng, const float* __restrict__ lnb,
            __half* __restrict__ C2, int K)
{
    constexpr int AELEB = 64 * 40 * 2;
    constexpr int BELEB = 512 * 40 * 2;
    extern __shared__ char smraw[];

    const int tid = threadIdx.x;
    const int warp = tid >> 5, lane = tid & 31;
    const int bm = blockIdx.x * 64;
    const int g = lane >> 2, t = lane & 3;

    uint32_t sbase;
    asm("{ .reg .u64 u; cvta.to.shared.u64 u, %1; cvt.u32.u64 %0, u; }"
        : "=r"(sbase) : "l"(smraw));
    const uint32_t sA = sbase;
    const uint32_t sB = sbase + 2 * AELEB;

    const __half* Abase = A + (size_t)bm * K;
    const int KT = K / 32;

    float acc[4][4][4];
#pragma unroll
    for (int mi = 0; mi < 4; ++mi)
#pragma unroll
        for (int nj = 0; nj < 4; ++nj)
#pragma unroll
            for (int q = 0; q < 4; ++q) acc[mi][nj][q] = 0.f;

    auto load_tile = [&](int kt) {
        const int buf = kt & 1;
        const int k0 = kt * 32;
        if (tid < 256) {
            int r = tid >> 2, c = tid & 3;
            CP_ASYNC16(sA + (uint32_t)(buf * AELEB) + (uint32_t)(r * 40 + c * 8) * 2u,
                       Abase + (size_t)r * K + k0 + c * 8);
        }
        uint32_t db = sB + (uint32_t)(buf * BELEB);
#pragma unroll
        for (int i = 0; i < 4; ++i) {
            int id = tid + 512 * i;
            int r = id >> 2, c = id & 3;
            CP_ASYNC16(db + (uint32_t)(r * 40 + c * 8) * 2u,
                       Bt + (size_t)r * K + k0 + c * 8);
        }
        CP_COMMIT();
    };

    const uint32_t aAddr0 = sA + (uint32_t)(((lane & 15) * 40 + (lane >> 4) * 8) * 2);
    const uint32_t bAddr0 = sB + (uint32_t)(((warp * 32 + (lane & 15)) * 40
                                             + (lane >> 4) * 8) * 2);

    load_tile(0);

    for (int kt = 0; kt < KT; ++kt) {
        CP_WAIT0();
        __syncthreads();
        if (kt + 1 < KT) load_tile(kt + 1);

        const uint32_t abuf = aAddr0 + (kt & 1) * AELEB;
        const uint32_t bbuf = bAddr0 + (kt & 1) * BELEB;

#pragma unroll
        for (int ks = 0; ks < 2; ++ks) {
            const uint32_t kofs = ks * 32;
            uint32_t a[4][4], b[2][4];
#pragma unroll
            for (int mi = 0; mi < 4; ++mi)
                LDSM_X4(a[mi], abuf + mi * 1280 + kofs);
#pragma unroll
            for (int p = 0; p < 2; ++p)
                LDSM_X4(b[p], bbuf + p * 1280 + kofs);
#pragma unroll
            for (int mi = 0; mi < 4; ++mi)
#pragma unroll
                for (int nj = 0; nj < 4; ++nj) {
                    const uint32_t b0 = (nj & 1) ? b[nj >> 1][1] : b[nj >> 1][0];
                    const uint32_t b1 = (nj & 1) ? b[nj >> 1][3] : b[nj >> 1][2];
                    MMA16816(acc[mi][nj], a[mi], b0, b1);
                }
        }
    }

    __syncthreads();

    float* sS    = (float*)smraw;        // [64][17]
    float* sQ    = sS + 64 * 17;         // [64][17]
    float* rstat = sQ + 64 * 17;         // [64][2]

    float sums[4][2], sqs[4][2];
#pragma unroll
    for (int mi = 0; mi < 4; ++mi) {
        float sa = 0.f, qa = 0.f, sb = 0.f, qb = 0.f;
#pragma unroll
        for (int nj = 0; nj < 4; ++nj) {
            const int c = warp * 32 + nj * 8 + t * 2;
            const float b0 = bias[c], b1 = bias[c + 1];
            acc[mi][nj][0] += b0; acc[mi][nj][1] += b1;
            acc[mi][nj][2] += b0; acc[mi][nj][3] += b1;
            sa += acc[mi][nj][0] + acc[mi][nj][1];
            qa += acc[mi][nj][0] * acc[mi][nj][0] + acc[mi][nj][1] * acc[mi][nj][1];
            sb += acc[mi][nj][2] + acc[mi][nj][3];
            qb += acc[mi][nj][2] * acc[mi][nj][2] + acc[mi][nj][3] * acc[mi][nj][3];
        }
#pragma unroll
        for (int o = 1; o <= 2; o <<= 1) {
            sa += __shfl_xor_sync(0xffffffffu, sa, o);
            qa += __shfl_xor_sync(0xffffffffu, qa, o);
            sb += __shfl_xor_sync(0xffffffffu, sb, o);
            qb += __shfl_xor_sync(0xffffffffu, qb, o);
        }
        sums[mi][0] = sa; sums[mi][1] = sb;
        sqs[mi][0]  = qa; sqs[mi][1]  = qb;
    }
    if (t == 0) {
#pragma unroll
        for (int mi = 0; mi < 4; ++mi) {
            sS[(mi * 16 + g) * 17 + warp]     = sums[mi][0];
            sS[(mi * 16 + 8 + g) * 17 + warp] = sums[mi][1];
            sQ[(mi * 16 + g) * 17 + warp]     = sqs[mi][0];
            sQ[(mi * 16 + 8 + g) * 17 + warp] = sqs[mi][1];
        }
    }
    __syncthreads();
    if (tid < 64) {
        float s = 0.f, q = 0.f;
#pragma unroll
        for (int w = 0; w < 16; ++w) { s += sS[tid * 17 + w]; q += sQ[tid * 17 + w]; }
        float mean = s * (1.f / 512.f);
        float var  = q * (1.f / 512.f) - mean * mean;
        rstat[tid * 2]     = mean;
        rstat[tid * 2 + 1] = rsqrtf(var + EPS_F);
    }
    __syncthreads();

#pragma unroll
    for (int mi = 0; mi < 4; ++mi) {
        const int rA = mi * 16 + g, rB = rA + 8;
        const float mA = rstat[rA * 2], iA = rstat[rA * 2 + 1];
        const float mB = rstat[rB * 2], iB = rstat[rB * 2 + 1];
#pragma unroll
        for (int nj = 0; nj < 4; ++nj) {
            const int c = warp * 32 + nj * 8 + t * 2;
            const float ga = lng[c], gb = lng[c + 1];
            const float ba = lnb[c], bb = lnb[c + 1];
            float v00 = fmaxf(fmaf((acc[mi][nj][0] - mA) * iA, ga, ba), 0.f);
            float v01 = fmaxf(fmaf((acc[mi][nj][1] - mA) * iA, gb, bb), 0.f);
            float v10 = fmaxf(fmaf((acc[mi][nj][2] - mB) * iB, ga, ba), 0.f);
            float v11 = fmaxf(fmaf((acc[mi][nj][3] - mB) * iB, gb, bb), 0.f);
            *(__half2*)(C2 + (size_t)(bm + rA) * 512 + c) = __floats2half2_rn(v00, v01);
            *(__half2*)(C2 + (size_t)(bm + rB) * 512 + c) = __floats2half2_rn(v10, v11);
        }
    }
}

// ---------------------------------------------------------------------------
// Merged weight prep (10 segments) + g_xh pad-column zeroing
// ---------------------------------------------------------------------------
__global__ void prep_weights_kernel(
    const float* __restrict__ conv1_w, const float* __restrict__ enc_w1,
    const float* __restrict__ enc_w2,  const float* __restrict__ enc_w3,
    const float* __restrict__ edge_w1, const float* __restrict__ node_w1,
    const float* __restrict__ edge_w2, const float* __restrict__ edge_w3,
    const float* __restrict__ node_w2, const float* __restrict__ node_w3)
{
    int idx = blockIdx.x * 256 + threadIdx.x;
    if (idx >= PREPTOT) return;
    if (idx >= WTOT) {                        // g_xh pad columns (25..31)
        int j = idx - WTOT;
        int row = j / (FEATP - FEAT), col = FEAT + j % (FEATP - FEAT);
        g_xh[(size_t)row * FEATP + col] = __half(0.f);
        return;
    }
    float v;
    if (idx < OFF_E1) {
        int n = idx / 320, k = idx % 320;
        v = (k < 300) ? conv1_w[n * 300 + k] : 0.f;
    } else if (idx < OFF_E2) {
        int j = idx - OFF_E1; int n = j >> 5, k = j & 31;
        v = (k < 25) ? enc_w1[k * 512 + n] : 0.f;
    } else if (idx < OFF_E3) {
        int j = idx - OFF_E2; int n = j >> 9, k = j & 511;
        v = enc_w2[k * 512 + n];
    } else if (idx < OFF_CAT) {
        int j = idx - OFF_E3; int n = j >> 9, k = j & 511;
        v = enc_w3[k * 128 + n];
    } else if (idx < OFF_G2) {
        int j = idx - OFF_CAT; int n = j >> 7, k = j & 127;
        if (n < 512)       v = edge_w1[k * 512 + n];
        else if (n < 1024) v = edge_w1[(128 + k) * 512 + (n - 512)];
        else               v = node_w1[k * 512 + (n - 1024)];
    } else if (idx < OFF_G3) {
        int j = idx - OFF_G2; int n = j >> 9, k = j & 511;
        v = edge_w2[k * 512 + n];
    } else if (idx < OFF_N1G) {
        int j = idx - OFF_G3; int n = j >> 9, k = j & 511;
        v = edge_w3[k * 512 + n];
    } else if (idx < OFF_N2) {
        int j = idx - OFF_N1G; int n = j >> 9, k = j & 511;
        v = node_w1[(132 + k) * 512 + n];
    } else if (idx < OFF_N3) {
        int j = idx - OFF_N2; int n = j >> 9, k = j & 511;
        v = node_w2[k * 512 + n];
    } else {
        int j = idx - OFF_N3; int n = j >> 9, k = j & 511;
        v = node_w3[k * 128 + n];
    }
    g_wtsh[idx] = __float2half(v);
}

// ---------------------------------------------------------------------------
// im2col (stride==kernel==10), K padded 300 -> 320, fp16 out
// ---------------------------------------------------------------------------
__global__ void im2col_kernel(const float* __restrict__ obs) {
    size_t idx = (size_t)blockIdx.x * 256 + threadIdx.x;
    if (idx >= (size_t)M_CONV * K_CONVP) return;
    int m  = (int)(idx / K_CONVP);
    int kk = (int)(idx % K_CONVP);
    float v = 0.f;
    if (kk < K_CONV) {
        int b = m / 25, p = m % 25;
        int py = p / 5, px = p % 5;
        int c = kk / 100, rr = kk % 100;
        int ky = rr / 10, kx = rr % 10;
        v = obs[((size_t)(b * 3 + c) * 50 + py * 10 + ky) * 50 + px * 10 + kx];
    }
    g_acolh[idx] = __float2half(v);
}

// ---------------------------------------------------------------------------
// BN stage 2: reduce 800 partials per column, produce scale/shift
// ---------------------------------------------------------------------------
__global__ void bn_stats2_kernel(const float* __restrict__ gamma,
                                 const float* __restrict__ beta) {
    __shared__ float sm[64];
    const int c = blockIdx.x, tid = threadIdx.x;
    float s = 0.f, q = 0.f;
    for (int i = tid; i < 800; i += 256) {
        s += g_part[(size_t)c * 800 + i];
        q += g_part[409600 + (size_t)c * 800 + i];
    }
#pragma unroll
    for (int o = 16; o > 0; o >>= 1) {
        s += __shfl_down_sync(0xffffffffu, s, o);
        q += __shfl_down_sync(0xffffffffu, q, o);
    }
    if ((tid & 31) == 0) { sm[tid >> 5] = s; sm[8 + (tid >> 5)] = q; }
    __syncthreads();
    if (tid == 0) {
        float ts = 0.f, tq = 0.f;
#pragma unroll
        for (int i = 0; i < 8; ++i) { ts += sm[i]; tq += sm[8 + i]; }
        const float inv_n = 1.f / (float)M_CONV;
        float mu  = ts * inv_n;
        float var = tq * inv_n - mu * mu;
        float sc = gamma[c] * rsqrtf(var + EPS_F);
        g_scale[c] = sc;
        g_shift[c] = beta[c] - mu * sc;
    }
}

// ---------------------------------------------------------------------------
// BN normalize + relu + conv2(1x1) + sigmoid -> g_xh  (reads half y)
// ---------------------------------------------------------------------------
__global__ void conv2_sigmoid_kernel(const float* __restrict__ w2,
                                     const float* __restrict__ b2) {
    __shared__ float ws[5 * HID];
    __shared__ float bs[5];
    int tid = threadIdx.x;
    for (int i = tid; i < 5 * HID; i += 256) ws[i] = w2[i];
    if (tid < 5) bs[tid] = b2[tid];
    __syncthreads();

    int warp = tid >> 5, lane = tid & 31;
    size_t m = (size_t)blockIdx.x * 8 + warp;
    const __half* y = g_yh + m * HID;
    float a0 = 0.f, a1 = 0.f, a2 = 0.f, a3 = 0.f, a4 = 0.f;
#pragma unroll
    for (int i = 0; i < 16; ++i) {
        int c = lane + 32 * i;
        float h = fmaxf(fmaf(__half2float(y[c]), g_scale[c], g_shift[c]), 0.f);
        a0 = fmaf(h, ws[c],           a0);
        a1 = fmaf(h, ws[HID + c],     a1);
        a2 = fmaf(h, ws[2 * HID + c], a2);
        a3 = fmaf(h, ws[3 * HID + c], a3);
        a4 = fmaf(h, ws[4 * HID + c], a4);
    }
#pragma unroll
    for (int o = 16; o > 0; o >>= 1) {
        a0 += __shfl_down_sync(0xffffffffu, a0, o);
        a1 += __shfl_down_sync(0xffffffffu, a1, o);
        a2 += __shfl_down_sync(0xffffffffu, a2, o);
        a3 += __shfl_down_sync(0xffffffffu, a3, o);
        a4 += __shfl_down_sync(0xffffffffu, a4, o);
    }
    if (lane == 0) {
        int b = (int)(m / 25), f = (int)(m % 25);
        __half* xb = g_xh + (size_t)b * 5 * FEATP + f;
        xb[0 * FEATP] = __float2half(1.f / (1.f + expf(-(a0 + bs[0]))));
        xb[1 * FEATP] = __float2half(1.f / (1.f + expf(-(a1 + bs[1]))));
        xb[2 * FEATP] = __float2half(1.f / (1.f + expf(-(a2 + bs[2]))));
        xb[3 * FEATP] = __float2half(1.f / (1.f + expf(-(a3 + bs[3]))));
        xb[4 * FEATP] = __float2half(1.f / (1.f + expf(-(a4 + bs[4]))));
    }
}

// ---------------------------------------------------------------------------
// edge1 combine: relu(P[b,i] + Q[b,tgt] + bias) -> half (reads half proj)
// ---------------------------------------------------------------------------
__global__ void edge1_combine_kernel(const float* __restrict__ b1) {
    size_t idx = (size_t)blockIdx.x * 256 + threadIdx.x;
    if (idx >= (size_t)M_EDGE * 256) return;
    int r = (int)(idx >> 8);
    int c = (int)(idx & 255) * 2;
    int b = r / 20, p = r % 20;
    int i = p >> 2, t = p & 3;
    int tgt = t + (t >= i ? 1 : 0);
    float2 P = __half22float2(*(const __half2*)(g_projh + ((size_t)b * KOBJ + i)   * NPROJ + c));
    float2 Q = __half22float2(*(const __half2*)(g_projh + ((size_t)b * KOBJ + tgt) * NPROJ + 512 + c));
    float v0 = fmaxf(P.x + Q.x + b1[c],     0.f);
    float v1 = fmaxf(P.y + Q.y + b1[c + 1], 0.f);
    *(__half2*)(g_bufh + (size_t)r * HID + c) = __floats2half2_rn(v0, v1);
}

// ---------------------------------------------------------------------------
// Launch
// ---------------------------------------------------------------------------
extern "C" void kernel_launch(void* const* d_in, const int* in_sizes, int n_in,
                              void* d_out, int out_size) {
    const float* obs     = (const float*)d_in[0];
    const int*   action  = (const int*)d_in[1];
    const float* conv1_w = (const float*)d_in[2];
    const float* conv1_b = (const float*)d_in[3];
    const float* bn1_g   = (const float*)d_in[4];
    const float* bn1_b   = (const float*)d_in[5];
    const float* conv2_w = (const float*)d_in[6];
    const float* conv2_b = (const float*)d_in[7];
    const float* enc_w1  = (const float*)d_in[8];
    const float* enc_b1  = (const float*)d_in[9];
    const float* enc_w2  = (const float*)d_in[10];
    const float* enc_b2  = (const float*)d_in[11];
    const float* enc_lng = (const float*)d_in[12];
    const float* enc_lnb = (const float*)d_in[13];
    const float* enc_w3  = (const float*)d_in[14];
    const float* enc_b3  = (const float*)d_in[15];
    const float* edge_w1 = (const float*)d_in[16];
    const float* edge_b1 = (const float*)d_in[17];
    const float* edge_w2 = (const float*)d_in[18];
    const float* edge_b2 = (const float*)d_in[19];
    const float* edge_lng= (const float*)d_in[20];
    const float* edge_lnb= (const float*)d_in[21];
    const float* edge_w3 = (const float*)d_in[22];
    const float* edge_b3 = (const float*)d_in[23];
    const float* node_w1 = (const float*)d_in[24];
    const float* node_b1 = (const float*)d_in[25];
    const float* node_w2 = (const float*)d_in[26];
    const float* node_b2 = (const float*)d_in[27];
    const float* node_lng= (const float*)d_in[28];
    const float* node_lnb= (const float*)d_in[29];
    const float* node_w3 = (const float*)d_in[30];
    const float* node_b3 = (const float*)d_in[31];
    float* out = (float*)d_out;

    float *p_state, *p_part, *p_zero;
    __half *p_acolh, *p_yh, *p_xh, *p_stateh, *p_projh, *p_bufh, *p_aggh, *p_wts;
    cudaGetSymbolAddress((void**)&p_acolh,  g_acolh);
    cudaGetSymbolAddress((void**)&p_yh,     g_yh);
    cudaGetSymbolAddress((void**)&p_xh,     g_xh);
    cudaGetSymbolAddress((void**)&p_state,  g_state);
    cudaGetSymbolAddress((void**)&p_stateh, g_stateh);
    cudaGetSymbolAddress((void**)&p_projh,  g_projh);
    cudaGetSymbolAddress((void**)&p_part,   g_part);
    cudaGetSymbolAddress((void**)&p_zero,   g_zerobias);
    cudaGetSymbolAddress((void**)&p_bufh,   g_bufh);
    cudaGetSymbolAddress((void**)&p_aggh,   g_aggh);
    cudaGetSymbolAddress((void**)&p_wts,    g_wtsh);

    const int SMEM256 = 2 * 128 * 40 * 2 + 2 * 256 * 40 * 2;   // 61440
    const int SMEM128 = 2 * 128 * 40 * 2 + 2 * 128 * 40 * 2;   // 40960
    const int SMEMLN  = 2 * 64 * 40 * 2 + 2 * 512 * 40 * 2;    // 92160
    cudaFuncSetAttribute(mma_gemm<256>, cudaFuncAttributeMaxDynamicSharedMemorySize, SMEM256);
    cudaFuncSetAttribute(mma_gemm<128>, cudaFuncAttributeMaxDynamicSharedMemorySize, SMEM128);
    cudaFuncSetAttribute(mma_gemm_ln,   cudaFuncAttributeMaxDynamicSharedMemorySize, SMEMLN);

    // --- weight prep + x-pad zeroing (single launch) ---
    prep_weights_kernel<<<(PREPTOT + 255) / 256, 256>>>(
        conv1_w, enc_w1, enc_w2, enc_w3, edge_w1, node_w1,
        edge_w2, edge_w3, node_w2, node_w3);

    // --- conv1 GEMM: half out + fused BN partials (mode 3) ---
    im2col_kernel<<<(unsigned)(((size_t)M_CONV * K_CONVP + 255) / 256), 256>>>(obs);
    mma_gemm<256><<<dim3(2, M_CONV / 128), 256, SMEM256>>>(
        p_acolh, K_CONVP, p_wts + OFF_C1, conv1_b, nullptr, nullptr, p_yh,
        512, K_CONVP, 0, 3, p_part, nullptr, nullptr);

    // --- BN finalize + conv2 + sigmoid ---
    bn_stats2_kernel<<<512, 256>>>(bn1_g, bn1_b);
    conv2_sigmoid_kernel<<<M_CONV / 8, 256>>>(conv2_w, conv2_b);

    // --- encoder MLP: 32 -> 512 -> 512(LN fused) -> 128 ---
    mma_gemm<256><<<dim3(2, M_OBJ / 128), 256, SMEM256>>>(
        p_xh, FEATP, p_wts + OFF_E1, enc_b1, nullptr, nullptr, p_bufh,
        512, FEATP, 1, 1, nullptr, nullptr, nullptr);
    mma_gemm_ln<<<M_OBJ / 64, 512, SMEMLN>>>(
        p_bufh, p_wts + OFF_E2, enc_b2, enc_lng, enc_lnb, p_bufh, 512);
    mma_gemm<128><<<dim3(1, M_OBJ / 128), 128, SMEM128>>>(
        p_bufh, 512, p_wts + OFF_E3, enc_b3, nullptr, p_state, p_stateh,
        128, 512, 0, 0, nullptr, nullptr, nullptr);

    // --- projection GEMM: state @ [e1a | e1b | n1s] -> half (K=128, N=1536) ---
    mma_gemm<256><<<dim3(NPROJ / 256, M_OBJ / 128), 256, SMEM256>>>(
        p_stateh, 128, p_wts + OFF_CAT, p_zero, nullptr, nullptr, p_projh,
        NPROJ, 128, 0, 1, nullptr, nullptr, nullptr);

    // --- edge MLP: combine -> 512(LN fused) -> 512(+agg fused) ---
    edge1_combine_kernel<<<(unsigned)(((size_t)M_EDGE * 256 + 255) / 256), 256>>>(edge_b1);
    mma_gemm_ln<<<M_EDGE / 64, 512, SMEMLN>>>(
        p_bufh, p_wts + OFF_G2, edge_b2, edge_lng, edge_lnb, p_bufh, 512);
    mma_gemm<256><<<dim3(2, M_EDGE / 128), 256, SMEM256>>>(
        p_bufh, 512, p_wts + OFF_G3, edge_b3, nullptr, nullptr, p_aggh,
        512, 512, 0, 2, nullptr, nullptr, nullptr);

    // --- node MLP: agg-GEMM(+proj/action) -> 512(LN fused) -> 128 + resid ---
    mma_gemm<256><<<dim3(2, M_OBJ / 128), 256, SMEM256>>>(
        p_aggh, 512, p_wts + OFF_N1G, node_b1, nullptr, nullptr, p_bufh,
        512, 512, 1, 4, p_projh + 1024, node_w1 + 128 * 512, action);
    mma_gemm_ln<<<M_OBJ / 64, 512, SMEMLN>>>(
        p_bufh, p_wts + OFF_N2, node_b2, node_lng, node_lnb, p_bufh, 512);
    mma_gemm<128><<<dim3(1, M_OBJ / 128), 128, SMEM128>>>(
        p_bufh, 512, p_wts + OFF_N3, node_b3, p_state, out, nullptr,
        128, 512, 0, 0, nullptr, nullptr, nullptr);
}

// round 17
// speedup vs baseline: 4.2398x; 1.0332x over previous
#include <cuda_runtime.h>
#include <cuda_fp16.h>
#include <stdint.h>
#include <math.h>

// ---------------------------------------------------------------------------
// Problem constants
// ---------------------------------------------------------------------------
#define BB      4096
#define KOBJ    5
#define EMB     128
#define HID     512
#define ADIM    4
#define FEAT    25
#define EPS_F   1e-5f

#define M_CONV  (BB * 25)          // 102400
#define K_CONV  300
#define K_CONVP 320
#define M_OBJ   (BB * KOBJ)        // 20480
#define M_EDGE  (BB * 20)          // 81920
#define FEATP   32
#define NPROJ   1536               // [edge_w1a | edge_w1b | node_w1_state]

#define WTOT    1835008
#define PADX    (M_OBJ * (FEATP - FEAT))     // 143360
#define PREPTOT (WTOT + PADX)

// ---------------------------------------------------------------------------
// Scratch (device globals)
// ---------------------------------------------------------------------------
static __device__ __half g_acolh[(size_t)M_CONV * K_CONVP];
static __device__ __half g_yh[(size_t)M_CONV * HID];         // conv1 out (fp16)
static __device__ float  g_part[2 * 512 * 800];              // BN col partials
static __device__ float  g_scale[HID];
static __device__ float  g_shift[HID];
static __device__ __half g_xh[(size_t)M_OBJ * FEATP];
static __device__ float  g_state[(size_t)M_OBJ * EMB];
static __device__ __half g_stateh[(size_t)M_OBJ * EMB];
static __device__ __half g_projh[(size_t)M_OBJ * NPROJ];     // state @ Wcat (fp16)
static __device__ __half g_bufh[(size_t)M_EDGE * HID];
static __device__ __half g_aggh[(size_t)M_OBJ * HID];
static __device__ __half g_wtsh[WTOT];
static __device__ float  g_zerobias[NPROJ];                  // zero-init

#define OFF_C1  0         // 512x320
#define OFF_E1  163840    // 512x32
#define OFF_E2  180224    // 512x512
#define OFF_E3  442368    // 128x512
#define OFF_CAT 507904    // 1536x128
#define OFF_G2  704512    // 512x512
#define OFF_G3  966656    // 512x512
#define OFF_N1G 1228800   // 512x512 (agg part of node_w1)
#define OFF_N2  1490944   // 512x512
#define OFF_N3  1753088   // 128x512

// ---------------------------------------------------------------------------
// Helpers
// ---------------------------------------------------------------------------
#define CP_ASYNC16(dst, src) \
    asm volatile("cp.async.cg.shared.global [%0], [%1], 16;" :: "r"(dst), "l"(src))
#define CP_COMMIT() asm volatile("cp.async.commit_group;" ::: "memory")
#define CP_WAIT0()  asm volatile("cp.async.wait_group 0;" ::: "memory")

#define LDSM_X4(r, addr)                                                      \
    asm volatile("ldmatrix.sync.aligned.m8n8.x4.shared.b16 {%0,%1,%2,%3}, [%4];" \
        : "=r"((r)[0]), "=r"((r)[1]), "=r"((r)[2]), "=r"((r)[3]) : "r"(addr))

#define MMA16816(acc, a, b0, b1)                                              \
    asm volatile(                                                             \
        "mma.sync.aligned.m16n8k16.row.col.f32.f16.f16.f32 "                  \
        "{%0,%1,%2,%3}, {%4,%5,%6,%7}, {%8,%9}, {%0,%1,%2,%3};"               \
        : "+f"((acc)[0]), "+f"((acc)[1]), "+f"((acc)[2]), "+f"((acc)[3])      \
        : "r"((a)[0]), "r"((a)[1]), "r"((a)[2]), "r"((a)[3]), "r"(b0), "r"(b1))

// ---------------------------------------------------------------------------
// fp16 mma.sync GEMM (BM=128). Modes:
//  0: fp32 out Cv (+half copy to C2 if non-null), bias(+relu)(+resid)
//  1: half out C2 only
//  2: agg: sum groups of 4 rows -> half C2, M/4 rows
//  3: half out C2 + fused per-CTA BN column partials (fp32 accs -> extraP)
//  4: node1: half out C2; adds bias + half proj row (extraP, stride NPROJ)
//     + fp32 action row
// ---------------------------------------------------------------------------
template<int BN>
__global__ void __launch_bounds__(BN == 256 ? 256 : 128, 1)
mma_gemm(const __half* __restrict__ A, int lda,
         const __half* __restrict__ Bt,
         const float* __restrict__ bias, const float* __restrict__ resid,
         float* __restrict__ Cv, __half* __restrict__ C2,
         int N, int K, int doRelu, int mode,
         void* __restrict__ extraP, const float* __restrict__ wact,
         const int* __restrict__ action)
{
    constexpr int T     = (BN == 256) ? 256 : 128;
    constexpr int AELEB = 128 * 40 * 2;
    constexpr int BELEB = BN * 40 * 2;
    extern __shared__ char smraw[];

    const int tid  = threadIdx.x;
    const int warp = tid >> 5, lane = tid & 31;
    const int bm = blockIdx.y * 128;
    const int bn = blockIdx.x * BN;
    const int warpM = warp & 1;
    const int warpN = warp >> 1;
    const int g = lane >> 2;
    const int t = lane & 3;

    uint32_t sbase;
    asm("{ .reg .u64 u; cvta.to.shared.u64 u, %1; cvt.u32.u64 %0, u; }"
        : "=r"(sbase) : "l"(smraw));
    const uint32_t sA = sbase;
    const uint32_t sB = sbase + 2 * AELEB;

    const __half* Abase = A  + (size_t)bm * lda;
    const __half* Bbase = Bt + (size_t)bn * K;
    const int KT = K / 32;

    float acc[4][8][4];
#pragma unroll
    for (int mi = 0; mi < 4; ++mi)
#pragma unroll
        for (int nj = 0; nj < 8; ++nj)
#pragma unroll
            for (int q = 0; q < 4; ++q) acc[mi][nj][q] = 0.f;

    auto load_tile = [&](int kt) {
        const int buf = kt & 1;
        const int k0 = kt * 32;
        uint32_t da = sA + (uint32_t)(buf * AELEB);
#pragma unroll
        for (int i = 0; i < 512 / T; ++i) {
            int id = tid + T * i;
            int r = id >> 2, c = id & 3;
            CP_ASYNC16(da + (uint32_t)(r * 40 + c * 8) * 2u,
                       Abase + (size_t)r * lda + k0 + c * 8);
        }
        uint32_t db = sB + (uint32_t)(buf * BELEB);
#pragma unroll
        for (int i = 0; i < (BN * 4) / T; ++i) {
            int id = tid + T * i;
            int r = id >> 2, c = id & 3;
            CP_ASYNC16(db + (uint32_t)(r * 40 + c * 8) * 2u,
                       Bbase + (size_t)r * K + k0 + c * 8);
        }
        CP_COMMIT();
    };

    const uint32_t aAddr0 = sA + (uint32_t)(((warpM * 64 + (lane & 15)) * 40
                                             + (lane >> 4) * 8) * 2);
    const uint32_t bAddr0 = sB + (uint32_t)(((warpN * 64 + (lane & 15)) * 40
                                             + (lane >> 4) * 8) * 2);

    load_tile(0);

    for (int kt = 0; kt < KT; ++kt) {
        CP_WAIT0();
        __syncthreads();
        if (kt + 1 < KT) load_tile(kt + 1);

        const uint32_t abuf = aAddr0 + (kt & 1) * AELEB;
        const uint32_t bbuf = bAddr0 + (kt & 1) * BELEB;

#pragma unroll
        for (int ks = 0; ks < 2; ++ks) {
            const uint32_t kofs = ks * 32;
            uint32_t a[4][4], b[4][4];
#pragma unroll
            for (int mi = 0; mi < 4; ++mi)
                LDSM_X4(a[mi], abuf + mi * 1280 + kofs);
#pragma unroll
            for (int njp = 0; njp < 4; ++njp)
                LDSM_X4(b[njp], bbuf + njp * 1280 + kofs);
#pragma unroll
            for (int mi = 0; mi < 4; ++mi)
#pragma unroll
                for (int nj = 0; nj < 8; ++nj) {
                    const uint32_t b0 = (nj & 1) ? b[nj >> 1][1] : b[nj >> 1][0];
                    const uint32_t b1 = (nj & 1) ? b[nj >> 1][3] : b[nj >> 1][2];
                    MMA16816(acc[mi][nj], a[mi], b0, b1);
                }
        }
    }

    __syncthreads();

    if (mode == 2) {
#pragma unroll
        for (int mi = 0; mi < 4; ++mi) {
            const int base = bm + warpM * 64 + mi * 16;
#pragma unroll
            for (int nj = 0; nj < 8; ++nj) {
                const int col = bn + warpN * 64 + nj * 8 + t * 2;
                const float bz0 = bias[col], bz1 = bias[col + 1];
                float v00 = acc[mi][nj][0] + bz0, v01 = acc[mi][nj][1] + bz1;
                float v10 = acc[mi][nj][2] + bz0, v11 = acc[mi][nj][3] + bz1;
#pragma unroll
                for (int o = 4; o <= 8; o <<= 1) {
                    v00 += __shfl_xor_sync(0xffffffffu, v00, o);
                    v01 += __shfl_xor_sync(0xffffffffu, v01, o);
                    v10 += __shfl_xor_sync(0xffffffffu, v10, o);
                    v11 += __shfl_xor_sync(0xffffffffu, v11, o);
                }
                if ((lane & 12) == 0) {
                    const int gblk = lane >> 4;
                    const int r0 = (base >> 2) + gblk;
                    *(__half2*)(C2 + (size_t)r0 * N + col)       = __floats2half2_rn(v00, v01);
                    *(__half2*)(C2 + (size_t)(r0 + 2) * N + col) = __floats2half2_rn(v10, v11);
                }
            }
        }
    } else if (mode == 4) {
        const __half* projH = (const __half*)extraP;
#pragma unroll
        for (int mi = 0; mi < 4; ++mi) {
            const int rA = bm + warpM * 64 + mi * 16 + g;
            const int rB = rA + 8;
            const int bA = rA / KOBJ, kA = rA % KOBJ;
            const int bB = rB / KOBJ, kB = rB % KOBJ;
            const int aA = action[bA] - kA * ADIM;
            const int aB = action[bB] - kB * ADIM;
            const __half* prA = projH + (size_t)rA * NPROJ;
            const __half* prB = projH + (size_t)rB * NPROJ;
            const float* waA = (aA >= 0 && aA < ADIM) ? wact + (size_t)aA * HID : nullptr;
            const float* waB = (aB >= 0 && aB < ADIM) ? wact + (size_t)aB * HID : nullptr;
#pragma unroll
            for (int nj = 0; nj < 8; ++nj) {
                const int col = bn + warpN * 64 + nj * 8 + t * 2;
                float2 pA = __half22float2(*(const __half2*)(prA + col));
                float2 pB = __half22float2(*(const __half2*)(prB + col));
                float v00 = acc[mi][nj][0] + bias[col]     + pA.x;
                float v01 = acc[mi][nj][1] + bias[col + 1] + pA.y;
                float v10 = acc[mi][nj][2] + bias[col]     + pB.x;
                float v11 = acc[mi][nj][3] + bias[col + 1] + pB.y;
                if (waA) { v00 += waA[col]; v01 += waA[col + 1]; }
                if (waB) { v10 += waB[col]; v11 += waB[col + 1]; }
                v00 = fmaxf(v00, 0.f); v01 = fmaxf(v01, 0.f);
                v10 = fmaxf(v10, 0.f); v11 = fmaxf(v11, 0.f);
                *(__half2*)(C2 + (size_t)rA * N + col) = __floats2half2_rn(v00, v01);
                *(__half2*)(C2 + (size_t)rB * N + col) = __floats2half2_rn(v10, v11);
            }
        }
    } else {
        float rs[8][2], rq[8][2];
        if (mode == 3) {
#pragma unroll
            for (int nj = 0; nj < 8; ++nj) {
                rs[nj][0] = rs[nj][1] = 0.f;
                rq[nj][0] = rq[nj][1] = 0.f;
            }
        }
#pragma unroll
        for (int mi = 0; mi < 4; ++mi) {
            const int r0 = bm + warpM * 64 + mi * 16 + g;
#pragma unroll
            for (int nj = 0; nj < 8; ++nj) {
                const int col = bn + warpN * 64 + nj * 8 + t * 2;
                const float bz0 = bias[col], bz1 = bias[col + 1];
                float v00 = acc[mi][nj][0] + bz0, v01 = acc[mi][nj][1] + bz1;
                float v10 = acc[mi][nj][2] + bz0, v11 = acc[mi][nj][3] + bz1;
                if (doRelu) {
                    v00 = fmaxf(v00, 0.f); v01 = fmaxf(v01, 0.f);
                    v10 = fmaxf(v10, 0.f); v11 = fmaxf(v11, 0.f);
                }
                if (resid) {
                    const float* rp0 = resid + (size_t)r0 * N + col;
                    const float* rp1 = resid + (size_t)(r0 + 8) * N + col;
                    v00 += rp0[0]; v01 += rp0[1];
                    v10 += rp1[0]; v11 += rp1[1];
                }
                if (mode == 0) {
                    *(float2*)(Cv + (size_t)r0 * N + col)       = make_float2(v00, v01);
                    *(float2*)(Cv + (size_t)(r0 + 8) * N + col) = make_float2(v10, v11);
                    if (C2) {
                        *(__half2*)(C2 + (size_t)r0 * N + col)       = __floats2half2_rn(v00, v01);
                        *(__half2*)(C2 + (size_t)(r0 + 8) * N + col) = __floats2half2_rn(v10, v11);
                    }
                } else {   // mode 1 or 3: half out
                    *(__half2*)(C2 + (size_t)r0 * N + col)       = __floats2half2_rn(v00, v01);
                    *(__half2*)(C2 + (size_t)(r0 + 8) * N + col) = __floats2half2_rn(v10, v11);
                    if (mode == 3) {
                        rs[nj][0] += v00 + v10;          rs[nj][1] += v01 + v11;
                        rq[nj][0] += v00 * v00 + v10 * v10;
                        rq[nj][1] += v01 * v01 + v11 * v11;
                    }
                }
            }
        }
        if (mode == 3) {
            float* extraF = (float*)extraP;
#pragma unroll
            for (int nj = 0; nj < 8; ++nj)
#pragma unroll
                for (int q = 0; q < 2; ++q) {
#pragma unroll
                    for (int o = 4; o <= 16; o <<= 1) {
                        rs[nj][q] += __shfl_xor_sync(0xffffffffu, rs[nj][q], o);
                        rq[nj][q] += __shfl_xor_sync(0xffffffffu, rq[nj][q], o);
                    }
                }
            float* sS = (float*)smraw;
            float* sQ = sS + 256;
            if (warpM == 0 && lane < 4) {
#pragma unroll
                for (int nj = 0; nj < 8; ++nj) {
                    int c = warpN * 64 + nj * 8 + lane * 2;
                    sS[c] = rs[nj][0]; sS[c + 1] = rs[nj][1];
                    sQ[c] = rq[nj][0]; sQ[c + 1] = rq[nj][1];
                }
            }
            __syncthreads();
            if (warpM == 1 && lane < 4) {
                const int yb = blockIdx.y;
#pragma unroll
                for (int nj = 0; nj < 8; ++nj) {
                    int c = warpN * 64 + nj * 8 + lane * 2;
                    extraF[(size_t)(bn + c) * 800 + yb]     = rs[nj][0] + sS[c];
                    extraF[(size_t)(bn + c + 1) * 800 + yb] = rs[nj][1] + sS[c + 1];
                    extraF[409600 + (size_t)(bn + c) * 800 + yb]     = rq[nj][0] + sQ[c];
                    extraF[409600 + (size_t)(bn + c + 1) * 800 + yb] = rq[nj][1] + sQ[c + 1];
                }
            }
        }
    }
}

// ---------------------------------------------------------------------------
// Fused GEMM + LayerNorm + ReLU, N=512 (full row per CTA). BM=64, 512 thr.
// Used for enc2 / node2 (A = half activations in gmem).
// ---------------------------------------------------------------------------
__global__ void __launch_bounds__(512, 1)
mma_gemm_ln(const __half* __restrict__ A,
            const __half* __restrict__ Bt,
            const float* __restrict__ bias,
            const float* __restrict__ lng, const float* __restrict__ lnb,
            __half* __restrict__ C2, int K)
{
    constexpr int AELEB = 64 * 40 * 2;
    constexpr int BELEB = 512 * 40 * 2;
    extern __shared__ char smraw[];

    const int tid = threadIdx.x;
    const int warp = tid >> 5, lane = tid & 31;
    const int bm = blockIdx.x * 64;
    const int g = lane >> 2, t = lane & 3;

    uint32_t sbase;
    asm("{ .reg .u64 u; cvta.to.shared.u64 u, %1; cvt.u32.u64 %0, u; }"
        : "=r"(sbase) : "l"(smraw));
    const uint32_t sA = sbase;
    const uint32_t sB = sbase + 2 * AELEB;

    const __half* Abase = A + (size_t)bm * K;
    const int KT = K / 32;

    float acc[4][4][4];
#pragma unroll
    for (int mi = 0; mi < 4; ++mi)
#pragma unroll
        for (int nj = 0; nj < 4; ++nj)
#pragma unroll
            for (int q = 0; q < 4; ++q) acc[mi][nj][q] = 0.f;

    auto load_tile = [&](int kt) {
        const int buf = kt & 1;
        const int k0 = kt * 32;
        if (tid < 256) {
            int r = tid >> 2, c = tid & 3;
            CP_ASYNC16(sA + (uint32_t)(buf * AELEB) + (uint32_t)(r * 40 + c * 8) * 2u,
                       Abase + (size_t)r * K + k0 + c * 8);
        }
        uint32_t db = sB + (uint32_t)(buf * BELEB);
#pragma unroll
        for (int i = 0; i < 4; ++i) {
            int id = tid + 512 * i;
            int r = id >> 2, c = id & 3;
            CP_ASYNC16(db + (uint32_t)(r * 40 + c * 8) * 2u,
                       Bt + (size_t)r * K + k0 + c * 8);
        }
        CP_COMMIT();
    };

    const uint32_t aAddr0 = sA + (uint32_t)(((lane & 15) * 40 + (lane >> 4) * 8) * 2);
    const uint32_t bAddr0 = sB + (uint32_t)(((warp * 32 + (lane & 15)) * 40
                                             + (lane >> 4) * 8) * 2);

    load_tile(0);

    for (int kt = 0; kt < KT; ++kt) {
        CP_WAIT0();
        __syncthreads();
        if (kt + 1 < KT) load_tile(kt + 1);

        const uint32_t abuf = aAddr0 + (kt & 1) * AELEB;
        const uint32_t bbuf = bAddr0 + (kt & 1) * BELEB;

#pragma unroll
        for (int ks = 0; ks < 2; ++ks) {
            const uint32_t kofs = ks * 32;
            uint32_t a[4][4], b[2][4];
#pragma unroll
            for (int mi = 0; mi < 4; ++mi)
                LDSM_X4(a[mi], abuf + mi * 1280 + kofs);
#pragma unroll
            for (int p = 0; p < 2; ++p)
                LDSM_X4(b[p], bbuf + p * 1280 + kofs);
#pragma unroll
            for (int mi = 0; mi < 4; ++mi)
#pragma unroll
                for (int nj = 0; nj < 4; ++nj) {
                    const uint32_t b0 = (nj & 1) ? b[nj >> 1][1] : b[nj >> 1][0];
                    const uint32_t b1 = (nj & 1) ? b[nj >> 1][3] : b[nj >> 1][2];
                    MMA16816(acc[mi][nj], a[mi], b0, b1);
                }
        }
    }

    __syncthreads();

    float* sS    = (float*)smraw;        // [64][17]
    float* sQ    = sS + 64 * 17;         // [64][17]
    float* rstat = sQ + 64 * 17;         // [64][2]

    float sums[4][2], sqs[4][2];
#pragma unroll
    for (int mi = 0; mi < 4; ++mi) {
        float sa = 0.f, qa = 0.f, sb = 0.f, qb = 0.f;
#pragma unroll
        for (int nj = 0; nj < 4; ++nj) {
            const int c = warp * 32 + nj * 8 + t * 2;
            const float b0 = bias[c], b1 = bias[c + 1];
            acc[mi][nj][0] += b0; acc[mi][nj][1] += b1;
            acc[mi][nj][2] += b0; acc[mi][nj][3] += b1;
            sa += acc[mi][nj][0] + acc[mi][nj][1];
            qa += acc[mi][nj][0] * acc[mi][nj][0] + acc[mi][nj][1] * acc[mi][nj][1];
            sb += acc[mi][nj][2] + acc[mi][nj][3];
            qb += acc[mi][nj][2] * acc[mi][nj][2] + acc[mi][nj][3] * acc[mi][nj][3];
        }
#pragma unroll
        for (int o = 1; o <= 2; o <<= 1) {
            sa += __shfl_xor_sync(0xffffffffu, sa, o);
            qa += __shfl_xor_sync(0xffffffffu, qa, o);
            sb += __shfl_xor_sync(0xffffffffu, sb, o);
            qb += __shfl_xor_sync(0xffffffffu, qb, o);
        }
        sums[mi][0] = sa; sums[mi][1] = sb;
        sqs[mi][0]  = qa; sqs[mi][1]  = qb;
    }
    if (t == 0) {
#pragma unroll
        for (int mi = 0; mi < 4; ++mi) {
            sS[(mi * 16 + g) * 17 + warp]     = sums[mi][0];
            sS[(mi * 16 + 8 + g) * 17 + warp] = sums[mi][1];
            sQ[(mi * 16 + g) * 17 + warp]     = sqs[mi][0];
            sQ[(mi * 16 + 8 + g) * 17 + warp] = sqs[mi][1];
        }
    }
    __syncthreads();
    if (tid < 64) {
        float s = 0.f, q = 0.f;
#pragma unroll
        for (int w = 0; w < 16; ++w) { s += sS[tid * 17 + w]; q += sQ[tid * 17 + w]; }
        float mean = s * (1.f / 512.f);
        float var  = q * (1.f / 512.f) - mean * mean;
        rstat[tid * 2]     = mean;
        rstat[tid * 2 + 1] = rsqrtf(var + EPS_F);
    }
    __syncthreads();

#pragma unroll
    for (int mi = 0; mi < 4; ++mi) {
        const int rA = mi * 16 + g, rB = rA + 8;
        const float mA = rstat[rA * 2], iA = rstat[rA * 2 + 1];
        const float mB = rstat[rB * 2], iB = rstat[rB * 2 + 1];
#pragma unroll
        for (int nj = 0; nj < 4; ++nj) {
            const int c = warp * 32 + nj * 8 + t * 2;
            const float ga = lng[c], gb = lng[c + 1];
            const float ba = lnb[c], bb = lnb[c + 1];
            float v00 = fmaxf(fmaf((acc[mi][nj][0] - mA) * iA, ga, ba), 0.f);
            float v01 = fmaxf(fmaf((acc[mi][nj][1] - mA) * iA, gb, bb), 0.f);
            float v10 = fmaxf(fmaf((acc[mi][nj][2] - mB) * iB, ga, ba), 0.f);
            float v11 = fmaxf(fmaf((acc[mi][nj][3] - mB) * iB, gb, bb), 0.f);
            *(__half2*)(C2 + (size_t)(bm + rA) * 512 + c) = __floats2half2_rn(v00, v01);
            *(__half2*)(C2 + (size_t)(bm + rB) * 512 + c) = __floats2half2_rn(v10, v11);
        }
    }
}

// ---------------------------------------------------------------------------
// Fused EDGE kernel: combine (P[src]+Q[tgt]+b1, relu) built in the A-loader
// (register-pipelined LDGs), then GEMM @ edge_w2 + LayerNorm + ReLU.
// BM=64, N=512, K=512, 512 threads. Replaces edge1_combine + mma_gemm_ln.
// ---------------------------------------------------------------------------
__global__ void __launch_bounds__(512, 1)
mma_gemm_comb_ln(const __half* __restrict__ projh,
                 const float* __restrict__ b1,
                 const __half* __restrict__ Bt,
                 const float* __restrict__ bias,
                 const float* __restrict__ lng, const float* __restrict__ lnb,
                 __half* __restrict__ C2)
{
    constexpr int K = 512, KT = 16;
    constexpr int AELEB = 64 * 40 * 2;      // 5120
    constexpr int BELEB = 512 * 40 * 2;     // 40960
    extern __shared__ char smraw[];
    float* sBias = (float*)(smraw + 2 * AELEB + 2 * BELEB);   // [512]

    const int tid = threadIdx.x;
    const int warp = tid >> 5, lane = tid & 31;
    const int bm = blockIdx.x * 64;
    const int g = lane >> 2, t = lane & 3;

    uint32_t sbase;
    asm("{ .reg .u64 u; cvta.to.shared.u64 u, %1; cvt.u32.u64 %0, u; }"
        : "=r"(sbase) : "l"(smraw));
    const uint32_t sB = sbase + 2 * AELEB;

    // --- combine-row precompute (fixed per thread) ---
    const int ar  = tid >> 3;             // A row 0..63
    const int ac4 = (tid & 7) * 4;        // col offset within 32-chunk
    const int R = bm + ar;
    const int bb_ = R / 20, p_ = R % 20;
    const int i_ = p_ >> 2, tt_ = p_ & 3;
    const int tgt_ = tt_ + (tt_ >= i_ ? 1 : 0);
    const __half* Pp = projh + ((size_t)bb_ * KOBJ + i_)   * NPROJ;
    const __half* Qp = projh + ((size_t)bb_ * KOBJ + tgt_) * NPROJ + 512;
    char* aSts = smraw + (ar * 40 + ac4) * 2;

    // bias -> smem
    if (tid < 512) sBias[tid] = b1[tid];

    const int KT_ = KT;
    auto ldgA = [&](int kt) -> uint4 {
        const int k0 = kt * 32 + ac4;
        uint2 P = *(const uint2*)(Pp + k0);
        uint2 Q = *(const uint2*)(Qp + k0);
        return make_uint4(P.x, P.y, Q.x, Q.y);
    };
    auto stsA = [&](uint4 ra, int kt) {
        float2 f0 = __half22float2(*(__half2*)&ra.x);
        float2 f1 = __half22float2(*(__half2*)&ra.y);
        float2 q0 = __half22float2(*(__half2*)&ra.z);
        float2 q1 = __half22float2(*(__half2*)&ra.w);
        float4 bz = *(const float4*)(sBias + kt * 32 + ac4);
        float v0 = fmaxf(f0.x + q0.x + bz.x, 0.f);
        float v1 = fmaxf(f0.y + q0.y + bz.y, 0.f);
        float v2 = fmaxf(f1.x + q1.x + bz.z, 0.f);
        float v3 = fmaxf(f1.y + q1.y + bz.w, 0.f);
        __half2 h0 = __floats2half2_rn(v0, v1);
        __half2 h1 = __floats2half2_rn(v2, v3);
        *(uint2*)(aSts + (kt & 1) * AELEB) =
            make_uint2(*(uint32_t*)&h0, *(uint32_t*)&h1);
    };
    auto cpB = [&](int kt) {
        const int k0 = kt * 32;
        uint32_t db = sB + (uint32_t)((kt & 1) * BELEB);
#pragma unroll
        for (int i = 0; i < 4; ++i) {
            int id = tid + 512 * i;
            int r = id >> 2, c = id & 3;
            CP_ASYNC16(db + (uint32_t)(r * 40 + c * 8) * 2u,
                       Bt + (size_t)r * K + k0 + c * 8);
        }
        CP_COMMIT();
    };

    float acc[4][4][4];
#pragma unroll
    for (int mi = 0; mi < 4; ++mi)
#pragma unroll
        for (int nj = 0; nj < 4; ++nj)
#pragma unroll
            for (int q = 0; q < 4; ++q) acc[mi][nj][q] = 0.f;

    const uint32_t aAddr0 = sbase + (uint32_t)(((lane & 15) * 40 + (lane >> 4) * 8) * 2);
    const uint32_t bAddr0 = sB + (uint32_t)(((warp * 32 + (lane & 15)) * 40
                                             + (lane >> 4) * 8) * 2);

    uint4 ra = ldgA(0);
    cpB(0);
    __syncthreads();          // sBias visible before first stsA

    for (int kt = 0; kt < KT_; ++kt) {
        CP_WAIT0();           // B(kt) arrived
        stsA(ra, kt);         // A(kt) from regs (no gmem latency here)
        __syncthreads();
        if (kt + 1 < KT_) { ra = ldgA(kt + 1); cpB(kt + 1); }

        const uint32_t abuf = aAddr0 + (kt & 1) * AELEB;
        const uint32_t bbuf = bAddr0 + (kt & 1) * BELEB;
#pragma unroll
        for (int ks = 0; ks < 2; ++ks) {
            const uint32_t kofs = ks * 32;
            uint32_t a[4][4], b[2][4];
#pragma unroll
            for (int mi = 0; mi < 4; ++mi)
                LDSM_X4(a[mi], abuf + mi * 1280 + kofs);
#pragma unroll
            for (int p = 0; p < 2; ++p)
                LDSM_X4(b[p], bbuf + p * 1280 + kofs);
#pragma unroll
            for (int mi = 0; mi < 4; ++mi)
#pragma unroll
                for (int nj = 0; nj < 4; ++nj) {
                    const uint32_t b0 = (nj & 1) ? b[nj >> 1][1] : b[nj >> 1][0];
                    const uint32_t b1v = (nj & 1) ? b[nj >> 1][3] : b[nj >> 1][2];
                    MMA16816(acc[mi][nj], a[mi], b0, b1v);
                }
        }
    }

    __syncthreads();

    // --- LayerNorm epilogue (identical to mma_gemm_ln) ---
    float* sS    = (float*)smraw;
    float* sQ    = sS + 64 * 17;
    float* rstat = sQ + 64 * 17;

    float sums[4][2], sqs[4][2];
#pragma unroll
    for (int mi = 0; mi < 4; ++mi) {
        float sa = 0.f, qa = 0.f, sb = 0.f, qb = 0.f;
#pragma unroll
        for (int nj = 0; nj < 4; ++nj) {
            const int c = warp * 32 + nj * 8 + t * 2;
            const float b0 = bias[c], b1v = bias[c + 1];
            acc[mi][nj][0] += b0; acc[mi][nj][1] += b1v;
            acc[mi][nj][2] += b0; acc[mi][nj][3] += b1v;
            sa += acc[mi][nj][0] + acc[mi][nj][1];
            qa += acc[mi][nj][0] * acc[mi][nj][0] + acc[mi][nj][1] * acc[mi][nj][1];
            sb += acc[mi][nj][2] + acc[mi][nj][3];
            qb += acc[mi][nj][2] * acc[mi][nj][2] + acc[mi][nj][3] * acc[mi][nj][3];
        }
#pragma unroll
        for (int o = 1; o <= 2; o <<= 1) {
            sa += __shfl_xor_sync(0xffffffffu, sa, o);
            qa += __shfl_xor_sync(0xffffffffu, qa, o);
            sb += __shfl_xor_sync(0xffffffffu, sb, o);
            qb += __shfl_xor_sync(0xffffffffu, qb, o);
        }
        sums[mi][0] = sa; sums[mi][1] = sb;
        sqs[mi][0]  = qa; sqs[mi][1]  = qb;
    }
    if (t == 0) {
#pragma unroll
        for (int mi = 0; mi < 4; ++mi) {
            sS[(mi * 16 + g) * 17 + warp]     = sums[mi][0];
            sS[(mi * 16 + 8 + g) * 17 + warp] = sums[mi][1];
            sQ[(mi * 16 + g) * 17 + warp]     = sqs[mi][0];
            sQ[(mi * 16 + 8 + g) * 17 + warp] = sqs[mi][1];
        }
    }
    __syncthreads();
    if (tid < 64) {
        float s = 0.f, q = 0.f;
#pragma unroll
        for (int w = 0; w < 16; ++w) { s += sS[tid * 17 + w]; q += sQ[tid * 17 + w]; }
        float mean = s * (1.f / 512.f);
        float var  = q * (1.f / 512.f) - mean * mean;
        rstat[tid * 2]     = mean;
        rstat[tid * 2 + 1] = rsqrtf(var + EPS_F);
    }
    __syncthreads();

#pragma unroll
    for (int mi = 0; mi < 4; ++mi) {
        const int rA = mi * 16 + g, rB = rA + 8;
        const float mA = rstat[rA * 2], iA = rstat[rA * 2 + 1];
        const float mB = rstat[rB * 2], iB = rstat[rB * 2 + 1];
#pragma unroll
        for (int nj = 0; nj < 4; ++nj) {
            const int c = warp * 32 + nj * 8 + t * 2;
            const float ga = lng[c], gb = lng[c + 1];
            const float ba = lnb[c], bb = lnb[c + 1];
            float v00 = fmaxf(fmaf((acc[mi][nj][0] - mA) * iA, ga, ba), 0.f);
            float v01 = fmaxf(fmaf((acc[mi][nj][1] - mA) * iA, gb, bb), 0.f);
            float v10 = fmaxf(fmaf((acc[mi][nj][2] - mB) * iB, ga, ba), 0.f);
            float v11 = fmaxf(fmaf((acc[mi][nj][3] - mB) * iB, gb, bb), 0.f);
            *(__half2*)(C2 + (size_t)(bm + rA) * 512 + c) = __floats2half2_rn(v00, v01);
            *(__half2*)(C2 + (size_t)(bm + rB) * 512 + c) = __floats2half2_rn(v10, v11);
        }
    }
}

// ---------------------------------------------------------------------------
// Merged weight prep (10 segments) + g_xh pad-column zeroing
// ---------------------------------------------------------------------------
__global__ void prep_weights_kernel(
    const float* __restrict__ conv1_w, const float* __restrict__ enc_w1,
    const float* __restrict__ enc_w2,  const float* __restrict__ enc_w3,
    const float* __restrict__ edge_w1, const float* __restrict__ node_w1,
    const float* __restrict__ edge_w2, const float* __restrict__ edge_w3,
    const float* __restrict__ node_w2, const float* __restrict__ node_w3)
{
    int idx = blockIdx.x * 256 + threadIdx.x;
    if (idx >= PREPTOT) return;
    if (idx >= WTOT) {
        int j = idx - WTOT;
        int row = j / (FEATP - FEAT), col = FEAT + j % (FEATP - FEAT);
        g_xh[(size_t)row * FEATP + col] = __half(0.f);
        return;
    }
    float v;
    if (idx < OFF_E1) {
        int n = idx / 320, k = idx % 320;
        v = (k < 300) ? conv1_w[n * 300 + k] : 0.f;
    } else if (idx < OFF_E2) {
        int j = idx - OFF_E1; int n = j >> 5, k = j & 31;
        v = (k < 25) ? enc_w1[k * 512 + n] : 0.f;
    } else if (idx < OFF_E3) {
        int j = idx - OFF_E2; int n = j >> 9, k = j & 511;
        v = enc_w2[k * 512 + n];
    } else if (idx < OFF_CAT) {
        int j = idx - OFF_E3; int n = j >> 9, k = j & 511;
        v = enc_w3[k * 128 + n];
    } else if (idx < OFF_G2) {
        int j = idx - OFF_CAT; int n = j >> 7, k = j & 127;
        if (n < 512)       v = edge_w1[k * 512 + n];
        else if (n < 1024) v = edge_w1[(128 + k) * 512 + (n - 512)];
        else               v = node_w1[k * 512 + (n - 1024)];
    } else if (idx < OFF_G3) {
        int j = idx - OFF_G2; int n = j >> 9, k = j & 511;
        v = edge_w2[k * 512 + n];
    } else if (idx < OFF_N1G) {
        int j = idx - OFF_G3; int n = j >> 9, k = j & 511;
        v = edge_w3[k * 512 + n];
    } else if (idx < OFF_N2) {
        int j = idx - OFF_N1G; int n = j >> 9, k = j & 511;
        v = node_w1[(132 + k) * 512 + n];
    } else if (idx < OFF_N3) {
        int j = idx - OFF_N2; int n = j >> 9, k = j & 511;
        v = node_w2[k * 512 + n];
    } else {
        int j = idx - OFF_N3; int n = j >> 9, k = j & 511;
        v = node_w3[k * 128 + n];
    }
    g_wtsh[idx] = __float2half(v);
}

// ---------------------------------------------------------------------------
// im2col (stride==kernel==10), K padded 300 -> 320, fp16 out
// ---------------------------------------------------------------------------
__global__ void im2col_kernel(const float* __restrict__ obs) {
    size_t idx = (size_t)blockIdx.x * 256 + threadIdx.x;
    if (idx >= (size_t)M_CONV * K_CONVP) return;
    int m  = (int)(idx / K_CONVP);
    int kk = (int)(idx % K_CONVP);
    float v = 0.f;
    if (kk < K_CONV) {
        int b = m / 25, p = m % 25;
        int py = p / 5, px = p % 5;
        int c = kk / 100, rr = kk % 100;
        int ky = rr / 10, kx = rr % 10;
        v = obs[((size_t)(b * 3 + c) * 50 + py * 10 + ky) * 50 + px * 10 + kx];
    }
    g_acolh[idx] = __float2half(v);
}

// ---------------------------------------------------------------------------
// BN stage 2: reduce 800 partials per column, produce scale/shift
// ---------------------------------------------------------------------------
__global__ void bn_stats2_kernel(const float* __restrict__ gamma,
                                 const float* __restrict__ beta) {
    __shared__ float sm[64];
    const int c = blockIdx.x, tid = threadIdx.x;
    float s = 0.f, q = 0.f;
    for (int i = tid; i < 800; i += 256) {
        s += g_part[(size_t)c * 800 + i];
        q += g_part[409600 + (size_t)c * 800 + i];
    }
#pragma unroll
    for (int o = 16; o > 0; o >>= 1) {
        s += __shfl_down_sync(0xffffffffu, s, o);
        q += __shfl_down_sync(0xffffffffu, q, o);
    }
    if ((tid & 31) == 0) { sm[tid >> 5] = s; sm[8 + (tid >> 5)] = q; }
    __syncthreads();
    if (tid == 0) {
        float ts = 0.f, tq = 0.f;
#pragma unroll
        for (int i = 0; i < 8; ++i) { ts += sm[i]; tq += sm[8 + i]; }
        const float inv_n = 1.f / (float)M_CONV;
        float mu  = ts * inv_n;
        float var = tq * inv_n - mu * mu;
        float sc = gamma[c] * rsqrtf(var + EPS_F);
        g_scale[c] = sc;
        g_shift[c] = beta[c] - mu * sc;
    }
}

// ---------------------------------------------------------------------------
// BN normalize + relu + conv2(1x1) + sigmoid -> g_xh  (reads half y)
// ---------------------------------------------------------------------------
__global__ void conv2_sigmoid_kernel(const float* __restrict__ w2,
                                     const float* __restrict__ b2) {
    __shared__ float ws[5 * HID];
    __shared__ float bs[5];
    int tid = threadIdx.x;
    for (int i = tid; i < 5 * HID; i += 256) ws[i] = w2[i];
    if (tid < 5) bs[tid] = b2[tid];
    __syncthreads();

    int warp = tid >> 5, lane = tid & 31;
    size_t m = (size_t)blockIdx.x * 8 + warp;
    const __half* y = g_yh + m * HID;
    float a0 = 0.f, a1 = 0.f, a2 = 0.f, a3 = 0.f, a4 = 0.f;
#pragma unroll
    for (int i = 0; i < 16; ++i) {
        int c = lane + 32 * i;
        float h = fmaxf(fmaf(__half2float(y[c]), g_scale[c], g_shift[c]), 0.f);
        a0 = fmaf(h, ws[c],           a0);
        a1 = fmaf(h, ws[HID + c],     a1);
        a2 = fmaf(h, ws[2 * HID + c], a2);
        a3 = fmaf(h, ws[3 * HID + c], a3);
        a4 = fmaf(h, ws[4 * HID + c], a4);
    }
#pragma unroll
    for (int o = 16; o > 0; o >>= 1) {
        a0 += __shfl_down_sync(0xffffffffu, a0, o);
        a1 += __shfl_down_sync(0xffffffffu, a1, o);
        a2 += __shfl_down_sync(0xffffffffu, a2, o);
        a3 += __shfl_down_sync(0xffffffffu, a3, o);
        a4 += __shfl_down_sync(0xffffffffu, a4, o);
    }
    if (lane == 0) {
        int b = (int)(m / 25), f = (int)(m % 25);
        __half* xb = g_xh + (size_t)b * 5 * FEATP + f;
        xb[0 * FEATP] = __float2half(1.f / (1.f + expf(-(a0 + bs[0]))));
        xb[1 * FEATP] = __float2half(1.f / (1.f + expf(-(a1 + bs[1]))));
        xb[2 * FEATP] = __float2half(1.f / (1.f + expf(-(a2 + bs[2]))));
        xb[3 * FEATP] = __float2half(1.f / (1.f + expf(-(a3 + bs[3]))));
        xb[4 * FEATP] = __float2half(1.f / (1.f + expf(-(a4 + bs[4]))));
    }
}

// ---------------------------------------------------------------------------
// Launch
// ---------------------------------------------------------------------------
extern "C" void kernel_launch(void* const* d_in, const int* in_sizes, int n_in,
                              void* d_out, int out_size) {
    const float* obs     = (const float*)d_in[0];
    const int*   action  = (const int*)d_in[1];
    const float* conv1_w = (const float*)d_in[2];
    const float* conv1_b = (const float*)d_in[3];
    const float* bn1_g   = (const float*)d_in[4];
    const float* bn1_b   = (const float*)d_in[5];
    const float* conv2_w = (const float*)d_in[6];
    const float* conv2_b = (const float*)d_in[7];
    const float* enc_w1  = (const float*)d_in[8];
    const float* enc_b1  = (const float*)d_in[9];
    const float* enc_w2  = (const float*)d_in[10];
    const float* enc_b2  = (const float*)d_in[11];
    const float* enc_lng = (const float*)d_in[12];
    const float* enc_lnb = (const float*)d_in[13];
    const float* enc_w3  = (const float*)d_in[14];
    const float* enc_b3  = (const float*)d_in[15];
    const float* edge_w1 = (const float*)d_in[16];
    const float* edge_b1 = (const float*)d_in[17];
    const float* edge_w2 = (const float*)d_in[18];
    const float* edge_b2 = (const float*)d_in[19];
    const float* edge_lng= (const float*)d_in[20];
    const float* edge_lnb= (const float*)d_in[21];
    const float* edge_w3 = (const float*)d_in[22];
    const float* edge_b3 = (const float*)d_in[23];
    const float* node_w1 = (const float*)d_in[24];
    const float* node_b1 = (const float*)d_in[25];
    const float* node_w2 = (const float*)d_in[26];
    const float* node_b2 = (const float*)d_in[27];
    const float* node_lng= (const float*)d_in[28];
    const float* node_lnb= (const float*)d_in[29];
    const float* node_w3 = (const float*)d_in[30];
    const float* node_b3 = (const float*)d_in[31];
    float* out = (float*)d_out;

    float *p_state, *p_part, *p_zero;
    __half *p_acolh, *p_yh, *p_xh, *p_stateh, *p_projh, *p_bufh, *p_aggh, *p_wts;
    cudaGetSymbolAddress((void**)&p_acolh,  g_acolh);
    cudaGetSymbolAddress((void**)&p_yh,     g_yh);
    cudaGetSymbolAddress((void**)&p_xh,     g_xh);
    cudaGetSymbolAddress((void**)&p_state,  g_state);
    cudaGetSymbolAddress((void**)&p_stateh, g_stateh);
    cudaGetSymbolAddress((void**)&p_projh,  g_projh);
    cudaGetSymbolAddress((void**)&p_part,   g_part);
    cudaGetSymbolAddress((void**)&p_zero,   g_zerobias);
    cudaGetSymbolAddress((void**)&p_bufh,   g_bufh);
    cudaGetSymbolAddress((void**)&p_aggh,   g_aggh);
    cudaGetSymbolAddress((void**)&p_wts,    g_wtsh);

    const int SMEM256 = 2 * 128 * 40 * 2 + 2 * 256 * 40 * 2;   // 61440
    const int SMEM128 = 2 * 128 * 40 * 2 + 2 * 128 * 40 * 2;   // 40960
    const int SMEMLN  = 2 * 64 * 40 * 2 + 2 * 512 * 40 * 2;    // 92160
    const int SMEMCLN = SMEMLN + 2048;                         // + sBias
    cudaFuncSetAttribute(mma_gemm<256>, cudaFuncAttributeMaxDynamicSharedMemorySize, SMEM256);
    cudaFuncSetAttribute(mma_gemm<128>, cudaFuncAttributeMaxDynamicSharedMemorySize, SMEM128);
    cudaFuncSetAttribute(mma_gemm_ln,   cudaFuncAttributeMaxDynamicSharedMemorySize, SMEMLN);
    cudaFuncSetAttribute(mma_gemm_comb_ln, cudaFuncAttributeMaxDynamicSharedMemorySize, SMEMCLN);

    // --- weight prep + x-pad zeroing (single launch) ---
    prep_weights_kernel<<<(PREPTOT + 255) / 256, 256>>>(
        conv1_w, enc_w1, enc_w2, enc_w3, edge_w1, node_w1,
        edge_w2, edge_w3, node_w2, node_w3);

    // --- conv1 GEMM: half out + fused BN partials (mode 3) ---
    im2col_kernel<<<(unsigned)(((size_t)M_CONV * K_CONVP + 255) / 256), 256>>>(obs);
    mma_gemm<256><<<dim3(2, M_CONV / 128), 256, SMEM256>>>(
        p_acolh, K_CONVP, p_wts + OFF_C1, conv1_b, nullptr, nullptr, p_yh,
        512, K_CONVP, 0, 3, p_part, nullptr, nullptr);

    // --- BN finalize + conv2 + sigmoid ---
    bn_stats2_kernel<<<512, 256>>>(bn1_g, bn1_b);
    conv2_sigmoid_kernel<<<M_CONV / 8, 256>>>(conv2_w, conv2_b);

    // --- encoder MLP: 32 -> 512 -> 512(LN fused) -> 128 ---
    mma_gemm<256><<<dim3(2, M_OBJ / 128), 256, SMEM256>>>(
        p_xh, FEATP, p_wts + OFF_E1, enc_b1, nullptr, nullptr, p_bufh,
        512, FEATP, 1, 1, nullptr, nullptr, nullptr);
    mma_gemm_ln<<<M_OBJ / 64, 512, SMEMLN>>>(
        p_bufh, p_wts + OFF_E2, enc_b2, enc_lng, enc_lnb, p_bufh, 512);
    mma_gemm<128><<<dim3(1, M_OBJ / 128), 128, SMEM128>>>(
        p_bufh, 512, p_wts + OFF_E3, enc_b3, nullptr, p_state, p_stateh,
        128, 512, 0, 0, nullptr, nullptr, nullptr);

    // --- projection GEMM: state @ [e1a | e1b | n1s] -> half (K=128, N=1536) ---
    mma_gemm<256><<<dim3(NPROJ / 256, M_OBJ / 128), 256, SMEM256>>>(
        p_stateh, 128, p_wts + OFF_CAT, p_zero, nullptr, nullptr, p_projh,
        NPROJ, 128, 0, 1, nullptr, nullptr, nullptr);

    // --- edge MLP: fused combine+GEMM+LN -> 512(+agg fused) ---
    mma_gemm_comb_ln<<<M_EDGE / 64, 512, SMEMCLN>>>(
        p_projh, edge_b1, p_wts + OFF_G2, edge_b2, edge_lng, edge_lnb, p_bufh);
    mma_gemm<256><<<dim3(2, M_EDGE / 128), 256, SMEM256>>>(
        p_bufh, 512, p_wts + OFF_G3, edge_b3, nullptr, nullptr, p_aggh,
        512, 512, 0, 2, nullptr, nullptr, nullptr);

    // --- node MLP: agg-GEMM(+proj/action) -> 512(LN fused) -> 128 + resid ---
    mma_gemm<256><<<dim3(2, M_OBJ / 128), 256, SMEM256>>>(
        p_aggh, 512, p_wts + OFF_N1G, node_b1, nullptr, nullptr, p_bufh,
        512, 512, 1, 4, p_projh + 1024, node_w1 + 128 * 512, action);
    mma_gemm_ln<<<M_OBJ / 64, 512, SMEMLN>>>(
        p_bufh, p_wts + OFF_N2, node_b2, node_lng, node_lnb, p_bufh, 512);
    mma_gemm<128><<<dim3(1, M_OBJ / 128), 128, SMEM128>>>(
        p_bufh, 512, p_wts + OFF_N3, node_b3, p_state, out, nullptr,
        128, 512, 0, 0, nullptr, nullptr, nullptr);
}